// round 1
// baseline (speedup 1.0000x reference)
#include <cuda_runtime.h>
#include <math_constants.h>

#define NPTS 8192
#define CCH  256
#define KNB  16

// ---------------- scratch (device globals; no allocation APIs) ----------------
__device__ float4 g_pts[NPTS];          // x, y, z, |p|^2
__device__ int    g_idx[NPTS * KNB];    // knn indices
__device__ float  g_theta[NPTS * CCH];  // feats @ theta_w + theta_b
__device__ float  g_phi[NPTS * CCH];    // feats @ phi_w + phi_b
__device__ float  g_gv[NPTS * CCH];     // feats @ g_w + g_b
__device__ float  g_y[NPTS * CCH];      // attention output before final linear

// ---------------- prep: pack coords + squared norm ----------------
__global__ void prep_kernel(const float* __restrict__ coords) {
    int i = blockIdx.x * blockDim.x + threadIdx.x;
    if (i < NPTS) {
        float x = coords[3 * i + 0];
        float y = coords[3 * i + 1];
        float z = coords[3 * i + 2];
        g_pts[i] = make_float4(x, y, z, x * x + y * y + z * z);
    }
}

// ---------------- KNN: warp per query, 8 queries per block ----------------
__device__ __forceinline__ bool knn_less(float d1, int i1, float d2, int i2) {
    return (d1 < d2) || (d1 == d2 && i1 < i2);
}

__global__ __launch_bounds__(256) void knn_kernel() {
    // per-warp dump area, layout [slot][lane] -> conflict-free column access
    __shared__ float s_d[8][16][32];
    __shared__ int   s_i[8][16][32];

    int warp = threadIdx.x >> 5;
    int lane = threadIdx.x & 31;
    int q = blockIdx.x * 8 + warp;

    float4 qp = g_pts[q];

    float best_d[16];
    int   best_i[16];
#pragma unroll
    for (int s = 0; s < 16; ++s) { best_d[s] = CUDART_INF_F; best_i[s] = 0x7fffffff; }

    for (int j = lane; j < NPTS; j += 32) {
        float4 p = g_pts[j];
        float dot = qp.x * p.x + qp.y * p.y + qp.z * p.z;
        float d2 = (qp.w + p.w) - 2.0f * dot;   // matches reference formula
        if (knn_less(d2, j, best_d[15], best_i[15])) {
            best_d[15] = d2; best_i[15] = j;
#pragma unroll
            for (int s = 15; s > 0; --s) {
                if (knn_less(best_d[s], best_i[s], best_d[s - 1], best_i[s - 1])) {
                    float td = best_d[s]; best_d[s] = best_d[s - 1]; best_d[s - 1] = td;
                    int   ti = best_i[s]; best_i[s] = best_i[s - 1]; best_i[s - 1] = ti;
                }
            }
        }
    }

#pragma unroll
    for (int s = 0; s < 16; ++s) {
        s_d[warp][s][lane] = best_d[s];
        s_i[warp][s][lane] = best_i[s];
    }
    __syncwarp();

    // 32-way sorted-list merge: 16 rounds of warp argmin over list heads
    int ptr = 0;
    for (int r = 0; r < 16; ++r) {
        float d  = (ptr < 16) ? s_d[warp][ptr][lane] : CUDART_INF_F;
        int   ii = (ptr < 16) ? s_i[warp][ptr][lane] : 0x7fffffff;
        float curd = d; int curi = ii;
#pragma unroll
        for (int off = 16; off > 0; off >>= 1) {
            float od = __shfl_xor_sync(0xffffffffu, d, off);
            int   oi = __shfl_xor_sync(0xffffffffu, ii, off);
            if (knn_less(od, oi, d, ii)) { d = od; ii = oi; }
        }
        if (curd == d && curi == ii) ptr++;   // unique (d, idx) per lane: j strided by lane
        if (lane == 0) g_idx[q * KNB + r] = ii;
    }
}

// ---------------- generic linear: out = A @ W + b (+ resid) ----------------
// A [M=8192 rows via grid, 256], W [256,256] row-major, tile 64(M) x 256(N), BK=16
__global__ __launch_bounds__(256) void linear_kernel(
    const float* __restrict__ A, const float* __restrict__ W,
    const float* __restrict__ bias, const float* __restrict__ resid,
    float* __restrict__ out)
{
    __shared__ float s_A[64][17];
    __shared__ float s_W[16][256];

    int t  = threadIdx.x;
    int tx = t & 31;     // column group: cols tx*8 .. tx*8+7
    int ty = t >> 5;     // row group:    rows ty*8 .. ty*8+7
    int row0 = blockIdx.x * 64;

    float acc[8][8];
#pragma unroll
    for (int i = 0; i < 8; ++i)
#pragma unroll
        for (int j = 0; j < 8; ++j) acc[i][j] = 0.0f;

    int am = t >> 2;            // 0..63
    int ak = (t & 3) * 4;       // 0,4,8,12

    for (int ks = 0; ks < 16; ++ks) {
        float4 a4 = *(const float4*)&A[(row0 + am) * CCH + ks * 16 + ak];
        s_A[am][ak + 0] = a4.x; s_A[am][ak + 1] = a4.y;
        s_A[am][ak + 2] = a4.z; s_A[am][ak + 3] = a4.w;
#pragma unroll
        for (int r = 0; r < 4; ++r) {
            int kk = (t >> 6) + r * 4;
            int c  = (t & 63) * 4;
            *(float4*)&s_W[kk][c] = *(const float4*)&W[(ks * 16 + kk) * CCH + c];
        }
        __syncthreads();
#pragma unroll
        for (int kk = 0; kk < 16; ++kk) {
            float a[8], w[8];
#pragma unroll
            for (int i = 0; i < 8; ++i) a[i] = s_A[ty * 8 + i][kk];
            float4 w0 = *(const float4*)&s_W[kk][tx * 8];
            float4 w1 = *(const float4*)&s_W[kk][tx * 8 + 4];
            w[0] = w0.x; w[1] = w0.y; w[2] = w0.z; w[3] = w0.w;
            w[4] = w1.x; w[5] = w1.y; w[6] = w1.z; w[7] = w1.w;
#pragma unroll
            for (int i = 0; i < 8; ++i)
#pragma unroll
                for (int j = 0; j < 8; ++j)
                    acc[i][j] = fmaf(a[i], w[j], acc[i][j]);
        }
        __syncthreads();
    }

    float4 b0 = *(const float4*)&bias[tx * 8];
    float4 b1 = *(const float4*)&bias[tx * 8 + 4];
#pragma unroll
    for (int i = 0; i < 8; ++i) {
        int row = row0 + ty * 8 + i;
        float4 r0, r1;
        r0.x = acc[i][0] + b0.x; r0.y = acc[i][1] + b0.y;
        r0.z = acc[i][2] + b0.z; r0.w = acc[i][3] + b0.w;
        r1.x = acc[i][4] + b1.x; r1.y = acc[i][5] + b1.y;
        r1.z = acc[i][6] + b1.z; r1.w = acc[i][7] + b1.w;
        if (resid != nullptr) {
            float4 f0 = *(const float4*)&resid[row * CCH + tx * 8];
            float4 f1 = *(const float4*)&resid[row * CCH + tx * 8 + 4];
            r0.x += f0.x; r0.y += f0.y; r0.z += f0.z; r0.w += f0.w;
            r1.x += f1.x; r1.y += f1.y; r1.z += f1.z; r1.w += f1.w;
        }
        *(float4*)&out[row * CCH + tx * 8]     = r0;
        *(float4*)&out[row * CCH + tx * 8 + 4] = r1;
    }
}

// ---------------- fused attention: 2 points per block, column-pair per thread ----------------
// per point i: hidden = relu(delta @ w1 + b1) [16,256] in smem,
// pe = hidden @ w2 + b2 (register accum, 2 channels/thread),
// delta_features -> softmax over K (pure registers) -> y = sum sim * g
__global__ __launch_bounds__(256) void attn_kernel(
    const float* __restrict__ coords,
    const float* __restrict__ pe1_w1, const float* __restrict__ pe1_b1,
    const float* __restrict__ pe1_w2, const float* __restrict__ pe1_b2)
{
    __shared__ float s_w1[3 * 256];
    __shared__ float s_b1[256];
    __shared__ float s_hid[2][16][256];
    __shared__ int   s_idx[2][16];
    __shared__ float s_delta[2][16][3];

    int t    = threadIdx.x;
    int half = t >> 7;       // which of the 2 points
    int lt   = t & 127;
    int i    = blockIdx.x * 2 + half;
    int c0   = lt * 2;       // this thread's channel pair: c0, c0+1

    // cooperative loads of pe1 first-layer params
    s_b1[t & 255] = pe1_b1[t & 255];
    for (int r = t; r < 768; r += 256) s_w1[r] = pe1_w1[r];
    if (lt < 16) s_idx[half][lt] = g_idx[i * KNB + lt];
    __syncthreads();

    if (lt < 48) {
        int k = lt / 3, d = lt % 3;
        s_delta[half][k][d] = coords[s_idx[half][k] * 3 + d] - coords[i * 3 + d];
    }
    __syncthreads();

    // hidden[k][c] = relu(delta[k] . w1[:,c] + b1[c]) for this thread's two channels
#pragma unroll
    for (int k = 0; k < 16; ++k) {
        float dx = s_delta[half][k][0];
        float dy = s_delta[half][k][1];
        float dz = s_delta[half][k][2];
        float h0 = fmaf(dz, s_w1[512 + c0],     fmaf(dy, s_w1[256 + c0],     fmaf(dx, s_w1[c0],     s_b1[c0])));
        float h1 = fmaf(dz, s_w1[512 + c0 + 1], fmaf(dy, s_w1[256 + c0 + 1], fmaf(dx, s_w1[c0 + 1], s_b1[c0 + 1])));
        h0 = fmaxf(h0, 0.0f);
        h1 = fmaxf(h1, 0.0f);
        *(float2*)&s_hid[half][k][c0] = make_float2(h0, h1);
    }
    __syncthreads();

    // pe[k][c] = hidden[k][:] @ w2[:, c] + b2[c]  (the 8.6-GMAC hot loop)
    float pe0[16], pe1v[16];
    float b20 = pe1_b2[c0], b21 = pe1_b2[c0 + 1];
#pragma unroll
    for (int k = 0; k < 16; ++k) { pe0[k] = b20; pe1v[k] = b21; }

    for (int j = 0; j < 256; j += 2) {
        float2 wA = *(const float2*)&pe1_w2[j * CCH + c0];
        float2 wB = *(const float2*)&pe1_w2[(j + 1) * CCH + c0];
#pragma unroll
        for (int k = 0; k < 16; ++k) {
            float2 h = *(const float2*)&s_hid[half][k][j];   // broadcast LDS.64
            pe0[k]  = fmaf(h.x, wA.x, pe0[k]);
            pe1v[k] = fmaf(h.x, wA.y, pe1v[k]);
            pe0[k]  = fmaf(h.y, wB.x, pe0[k]);
            pe1v[k] = fmaf(h.y, wB.y, pe1v[k]);
        }
    }

    // delta_features = (pe*(theta - phi) + pe) / sqrt(C);  softmax over K per channel
    float th0 = g_theta[i * CCH + c0];
    float th1 = g_theta[i * CCH + c0 + 1];
#pragma unroll
    for (int k = 0; k < 16; ++k) {
        int nid = s_idx[half][k];
        float2 ph = *(const float2*)&g_phi[nid * CCH + c0];
        pe0[k]  = (pe0[k]  * (th0 - ph.x) + pe0[k])  * 0.0625f;
        pe1v[k] = (pe1v[k] * (th1 - ph.y) + pe1v[k]) * 0.0625f;
    }

    float m0 = pe0[0], m1 = pe1v[0];
#pragma unroll
    for (int k = 1; k < 16; ++k) { m0 = fmaxf(m0, pe0[k]); m1 = fmaxf(m1, pe1v[k]); }
    float sum0 = 0.0f, sum1 = 0.0f;
#pragma unroll
    for (int k = 0; k < 16; ++k) {
        pe0[k]  = expf(pe0[k]  - m0); sum0 += pe0[k];
        pe1v[k] = expf(pe1v[k] - m1); sum1 += pe1v[k];
    }
    float inv0 = 1.0f / sum0, inv1 = 1.0f / sum1;

    float y0 = 0.0f, y1 = 0.0f;
#pragma unroll
    for (int k = 0; k < 16; ++k) {
        int nid = s_idx[half][k];
        float2 gk = *(const float2*)&g_gv[nid * CCH + c0];
        y0 = fmaf(pe0[k]  * inv0, gk.x, y0);
        y1 = fmaf(pe1v[k] * inv1, gk.y, y1);
    }
    *(float2*)&g_y[i * CCH + c0] = make_float2(y0, y1);
}

// ---------------- launch ----------------
extern "C" void kernel_launch(void* const* d_in, const int* in_sizes, int n_in,
                              void* d_out, int out_size) {
    const float* coords  = (const float*)d_in[0];
    const float* feats   = (const float*)d_in[1];
    const float* theta_w = (const float*)d_in[2];
    const float* theta_b = (const float*)d_in[3];
    const float* phi_w   = (const float*)d_in[4];
    const float* phi_b   = (const float*)d_in[5];
    const float* g_w     = (const float*)d_in[6];
    const float* g_b     = (const float*)d_in[7];
    const float* pe1_w1  = (const float*)d_in[8];
    const float* pe1_b1  = (const float*)d_in[9];
    const float* pe1_w2  = (const float*)d_in[10];
    const float* pe1_b2  = (const float*)d_in[11];
    const float* W_w     = (const float*)d_in[12];
    const float* W_b     = (const float*)d_in[13];
    float* out = (float*)d_out;

    float *p_theta, *p_phi, *p_g, *p_y;
    cudaGetSymbolAddress((void**)&p_theta, g_theta);
    cudaGetSymbolAddress((void**)&p_phi,   g_phi);
    cudaGetSymbolAddress((void**)&p_g,     g_gv);
    cudaGetSymbolAddress((void**)&p_y,     g_y);

    prep_kernel<<<(NPTS + 255) / 256, 256>>>(coords);
    knn_kernel<<<NPTS / 8, 256>>>();

    linear_kernel<<<NPTS / 64, 256>>>(feats, theta_w, theta_b, nullptr, p_theta);
    linear_kernel<<<NPTS / 64, 256>>>(feats, phi_w,   phi_b,   nullptr, p_phi);
    linear_kernel<<<NPTS / 64, 256>>>(feats, g_w,     g_b,     nullptr, p_g);

    attn_kernel<<<NPTS / 2, 256>>>(coords, pe1_w1, pe1_b1, pe1_w2, pe1_b2);

    linear_kernel<<<NPTS / 64, 256>>>(p_y, W_w, W_b, feats, out);
}

// round 2
// speedup vs baseline: 1.7512x; 1.7512x over previous
#include <cuda_runtime.h>
#include <math_constants.h>

#define NPTS 8192
#define CCH  256
#define KNB  16

typedef unsigned long long ull;

// ---------------- packed f32x2 helpers ----------------
__device__ __forceinline__ ull pk2(float x, float y) {
    ull r; asm("mov.b64 %0, {%1, %2};" : "=l"(r) : "f"(x), "f"(y)); return r;
}
__device__ __forceinline__ ull fma2(ull a, ull b, ull c) {
    ull d; asm("fma.rn.f32x2 %0, %1, %2, %3;" : "=l"(d) : "l"(a), "l"(b), "l"(c)); return d;
}
__device__ __forceinline__ float2 upk(ull v) {
    float2 f; asm("mov.b64 {%0, %1}, %2;" : "=f"(f.x), "=f"(f.y) : "l"(v)); return f;
}

// ---------------- scratch (device globals; no allocation APIs) ----------------
__device__ float4 g_pts[NPTS];          // x, y, z, |p|^2
__device__ int    g_idx[NPTS * KNB];    // knn indices
__device__ float  g_theta[NPTS * CCH];  // feats @ theta_w + theta_b
__device__ float  g_phi[NPTS * CCH];    // feats @ phi_w + phi_b
__device__ float  g_gv[NPTS * CCH];     // feats @ g_w + g_b
__device__ float  g_y[NPTS * CCH];      // attention output before final linear

// ---------------- prep: pack coords + squared norm ----------------
__global__ void prep_kernel(const float* __restrict__ coords) {
    int i = blockIdx.x * blockDim.x + threadIdx.x;
    if (i < NPTS) {
        float x = coords[3 * i + 0];
        float y = coords[3 * i + 1];
        float z = coords[3 * i + 2];
        g_pts[i] = make_float4(x, y, z, x * x + y * y + z * z);
    }
}

// ---------------- KNN: warp per query, 8 queries per block ----------------
__device__ __forceinline__ bool knn_less(float d1, int i1, float d2, int i2) {
    return (d1 < d2) || (d1 == d2 && i1 < i2);
}

__global__ __launch_bounds__(256) void knn_kernel() {
    __shared__ float s_d[8][16][32];
    __shared__ int   s_i[8][16][32];

    int warp = threadIdx.x >> 5;
    int lane = threadIdx.x & 31;
    int q = blockIdx.x * 8 + warp;

    float4 qp = g_pts[q];

    float best_d[16];
    int   best_i[16];
#pragma unroll
    for (int s = 0; s < 16; ++s) { best_d[s] = CUDART_INF_F; best_i[s] = 0x7fffffff; }

    for (int j = lane; j < NPTS; j += 32) {
        float4 p = g_pts[j];
        float dot = qp.x * p.x + qp.y * p.y + qp.z * p.z;
        float d2 = (qp.w + p.w) - 2.0f * dot;
        if (knn_less(d2, j, best_d[15], best_i[15])) {
            best_d[15] = d2; best_i[15] = j;
#pragma unroll
            for (int s = 15; s > 0; --s) {
                if (knn_less(best_d[s], best_i[s], best_d[s - 1], best_i[s - 1])) {
                    float td = best_d[s]; best_d[s] = best_d[s - 1]; best_d[s - 1] = td;
                    int   ti = best_i[s]; best_i[s] = best_i[s - 1]; best_i[s - 1] = ti;
                }
            }
        }
    }

#pragma unroll
    for (int s = 0; s < 16; ++s) {
        s_d[warp][s][lane] = best_d[s];
        s_i[warp][s][lane] = best_i[s];
    }
    __syncwarp();

    int ptr = 0;
    for (int r = 0; r < 16; ++r) {
        float d  = (ptr < 16) ? s_d[warp][ptr][lane] : CUDART_INF_F;
        int   ii = (ptr < 16) ? s_i[warp][ptr][lane] : 0x7fffffff;
        float curd = d; int curi = ii;
#pragma unroll
        for (int off = 16; off > 0; off >>= 1) {
            float od = __shfl_xor_sync(0xffffffffu, d, off);
            int   oi = __shfl_xor_sync(0xffffffffu, ii, off);
            if (knn_less(od, oi, d, ii)) { d = od; ii = oi; }
        }
        if (curd == d && curi == ii) ptr++;
        if (lane == 0) g_idx[q * KNB + r] = ii;
    }
}

// ---------------- linear: out = A @ W + b (+ resid), packed f32x2 ----------------
// tile 64(M) x 256(N), BK=16. gridDim.y selects among up to 3 problems.
__global__ __launch_bounds__(256) void linear_kernel(
    const float* __restrict__ A,
    const float* __restrict__ W0, const float* __restrict__ W1, const float* __restrict__ W2,
    const float* __restrict__ b0_, const float* __restrict__ b1_, const float* __restrict__ b2_,
    float* __restrict__ o0, float* __restrict__ o1, float* __restrict__ o2,
    const float* __restrict__ resid)
{
    const float* W    = (blockIdx.y == 0) ? W0 : (blockIdx.y == 1) ? W1 : W2;
    const float* bias = (blockIdx.y == 0) ? b0_ : (blockIdx.y == 1) ? b1_ : b2_;
    float*       out  = (blockIdx.y == 0) ? o0 : (blockIdx.y == 1) ? o1 : o2;

    __shared__ float s_A[64][17];
    __shared__ float s_W[16][256];

    int t  = threadIdx.x;
    int tx = t & 31;     // column group: cols tx*8 .. tx*8+7
    int ty = t >> 5;     // row group:    rows ty*8 .. ty*8+7
    int row0 = blockIdx.x * 64;

    ull acc[8][4];       // [row][col-pair], each packs cols (2p, 2p+1)
#pragma unroll
    for (int i = 0; i < 8; ++i)
#pragma unroll
        for (int p = 0; p < 4; ++p) acc[i][p] = 0ull;

    int am = t >> 2;
    int ak = (t & 3) * 4;

    for (int ks = 0; ks < 16; ++ks) {
        float4 a4 = *(const float4*)&A[(row0 + am) * CCH + ks * 16 + ak];
        s_A[am][ak + 0] = a4.x; s_A[am][ak + 1] = a4.y;
        s_A[am][ak + 2] = a4.z; s_A[am][ak + 3] = a4.w;
#pragma unroll
        for (int r = 0; r < 4; ++r) {
            int kk = (t >> 6) + r * 4;
            int c  = (t & 63) * 4;
            *(float4*)&s_W[kk][c] = *(const float4*)&W[(ks * 16 + kk) * CCH + c];
        }
        __syncthreads();
#pragma unroll
        for (int kk = 0; kk < 16; ++kk) {
            ull av[8];
#pragma unroll
            for (int i = 0; i < 8; ++i) {
                float a = s_A[ty * 8 + i][kk];
                av[i] = pk2(a, a);
            }
            const ull* wrow = (const ull*)&s_W[kk][tx * 8];  // 4 packed col-pairs
            ull wp0 = wrow[0], wp1 = wrow[1], wp2 = wrow[2], wp3 = wrow[3];
#pragma unroll
            for (int i = 0; i < 8; ++i) {
                acc[i][0] = fma2(av[i], wp0, acc[i][0]);
                acc[i][1] = fma2(av[i], wp1, acc[i][1]);
                acc[i][2] = fma2(av[i], wp2, acc[i][2]);
                acc[i][3] = fma2(av[i], wp3, acc[i][3]);
            }
        }
        __syncthreads();
    }

    float4 b0 = *(const float4*)&bias[tx * 8];
    float4 b1 = *(const float4*)&bias[tx * 8 + 4];
#pragma unroll
    for (int i = 0; i < 8; ++i) {
        int row = row0 + ty * 8 + i;
        float2 c01 = upk(acc[i][0]);
        float2 c23 = upk(acc[i][1]);
        float2 c45 = upk(acc[i][2]);
        float2 c67 = upk(acc[i][3]);
        float4 r0, r1;
        r0.x = c01.x + b0.x; r0.y = c01.y + b0.y;
        r0.z = c23.x + b0.z; r0.w = c23.y + b0.w;
        r1.x = c45.x + b1.x; r1.y = c45.y + b1.y;
        r1.z = c67.x + b1.z; r1.w = c67.y + b1.w;
        if (resid != nullptr) {
            float4 f0 = *(const float4*)&resid[row * CCH + tx * 8];
            float4 f1 = *(const float4*)&resid[row * CCH + tx * 8 + 4];
            r0.x += f0.x; r0.y += f0.y; r0.z += f0.z; r0.w += f0.w;
            r1.x += f1.x; r1.y += f1.y; r1.z += f1.z; r1.w += f1.w;
        }
        *(float4*)&out[row * CCH + tx * 8]     = r0;
        *(float4*)&out[row * CCH + tx * 8 + 4] = r1;
    }
}

// ---------------- fused attention with packed f32x2 pe-GEMM ----------------
// 2 points/block, 128 threads/point, 2 channels/thread.
// s_hid layout: [point][hidden-channel j][k padded to 20] so neighbor pairs
// (k,k+1) load as aligned 64-bit packed operands for fma.rn.f32x2.
__global__ __launch_bounds__(256) void attn_kernel(
    const float* __restrict__ coords,
    const float* __restrict__ pe1_w1, const float* __restrict__ pe1_b1,
    const float* __restrict__ pe1_w2, const float* __restrict__ pe1_b2)
{
    __shared__ float s_w1[3 * 256];
    __shared__ float s_b1[256];
    __shared__ float s_hid[2][256][20];   // 40 KB
    __shared__ int   s_idx[2][16];
    __shared__ float s_delta[2][16][3];

    int t    = threadIdx.x;
    int half = t >> 7;
    int lt   = t & 127;
    int i    = blockIdx.x * 2 + half;
    int c0   = lt * 2;

    s_b1[t] = pe1_b1[t];
    { int r = t; if (r < 768) s_w1[r] = pe1_w1[r]; r += 256; if (r < 768) s_w1[r] = pe1_w1[r]; r += 256; if (r < 768) s_w1[r] = pe1_w1[r]; }
    if (lt < 16) s_idx[half][lt] = g_idx[i * KNB + lt];
    __syncthreads();

    if (lt < 48) {
        int k = lt / 3, d = lt % 3;
        s_delta[half][k][d] = coords[s_idx[half][k] * 3 + d] - coords[i * 3 + d];
    }
    __syncthreads();

    // hidden: h[c][k] = relu(delta_k . w1[:,c] + b1[c]) — this thread: rows c0, c0+1
    {
        float h0[16], h1[16];
        float w1x0 = s_w1[c0],       w1x1 = s_w1[c0 + 1];
        float w1y0 = s_w1[256 + c0], w1y1 = s_w1[256 + c0 + 1];
        float w1z0 = s_w1[512 + c0], w1z1 = s_w1[512 + c0 + 1];
        float bb0 = s_b1[c0], bb1 = s_b1[c0 + 1];
#pragma unroll
        for (int k = 0; k < 16; ++k) {
            float dx = s_delta[half][k][0];
            float dy = s_delta[half][k][1];
            float dz = s_delta[half][k][2];
            h0[k] = fmaxf(fmaf(dz, w1z0, fmaf(dy, w1y0, fmaf(dx, w1x0, bb0))), 0.0f);
            h1[k] = fmaxf(fmaf(dz, w1z1, fmaf(dy, w1y1, fmaf(dx, w1x1, bb1))), 0.0f);
        }
        float* r0 = &s_hid[half][c0][0];
        float* r1 = &s_hid[half][c0 + 1][0];
#pragma unroll
        for (int q = 0; q < 4; ++q) {
            *(float4*)&r0[q * 4] = make_float4(h0[q * 4], h0[q * 4 + 1], h0[q * 4 + 2], h0[q * 4 + 3]);
            *(float4*)&r1[q * 4] = make_float4(h1[q * 4], h1[q * 4 + 1], h1[q * 4 + 2], h1[q * 4 + 3]);
        }
    }
    __syncthreads();

    // pe[k][c] = hidden[k][:] @ w2[:, c] + b2[c]  — packed over (k,k+1)
    ull acc0[8], acc1[8];
    {
        float2 b2v = *(const float2*)&pe1_b2[c0];
        ull bi0 = pk2(b2v.x, b2v.x);
        ull bi1 = pk2(b2v.y, b2v.y);
#pragma unroll
        for (int p = 0; p < 8; ++p) { acc0[p] = bi0; acc1[p] = bi1; }
    }

    const float* hbase = &s_hid[half][0][0];
#pragma unroll 4
    for (int j = 0; j < 256; ++j) {
        const ull* hrow = (const ull*)(hbase + j * 20);     // 8 packed k-pairs
        float2 w = __ldg((const float2*)&pe1_w2[j * CCH + c0]);
        ull wx = pk2(w.x, w.x);
        ull wy = pk2(w.y, w.y);
#pragma unroll
        for (int p = 0; p < 8; ++p) {
            ull h = hrow[p];
            acc0[p] = fma2(h, wx, acc0[p]);
            acc1[p] = fma2(h, wy, acc1[p]);
        }
    }

    float pe0[16], pe1v[16];
#pragma unroll
    for (int p = 0; p < 8; ++p) {
        float2 u0 = upk(acc0[p]);
        float2 u1 = upk(acc1[p]);
        pe0[2 * p] = u0.x; pe0[2 * p + 1] = u0.y;
        pe1v[2 * p] = u1.x; pe1v[2 * p + 1] = u1.y;
    }

    // delta_features = (pe*(theta - phi) + pe) / sqrt(C);  softmax over K per channel
    float th0 = g_theta[i * CCH + c0];
    float th1 = g_theta[i * CCH + c0 + 1];
#pragma unroll
    for (int k = 0; k < 16; ++k) {
        int nid = s_idx[half][k];
        float2 ph = *(const float2*)&g_phi[nid * CCH + c0];
        pe0[k]  = (pe0[k]  * (th0 - ph.x) + pe0[k])  * 0.0625f;
        pe1v[k] = (pe1v[k] * (th1 - ph.y) + pe1v[k]) * 0.0625f;
    }

    float m0 = pe0[0], m1 = pe1v[0];
#pragma unroll
    for (int k = 1; k < 16; ++k) { m0 = fmaxf(m0, pe0[k]); m1 = fmaxf(m1, pe1v[k]); }
    float sum0 = 0.0f, sum1 = 0.0f;
#pragma unroll
    for (int k = 0; k < 16; ++k) {
        pe0[k]  = expf(pe0[k]  - m0); sum0 += pe0[k];
        pe1v[k] = expf(pe1v[k] - m1); sum1 += pe1v[k];
    }
    float inv0 = 1.0f / sum0, inv1 = 1.0f / sum1;

    float y0 = 0.0f, y1 = 0.0f;
#pragma unroll
    for (int k = 0; k < 16; ++k) {
        int nid = s_idx[half][k];
        float2 gk = *(const float2*)&g_gv[nid * CCH + c0];
        y0 = fmaf(pe0[k]  * inv0, gk.x, y0);
        y1 = fmaf(pe1v[k] * inv1, gk.y, y1);
    }
    *(float2*)&g_y[i * CCH + c0] = make_float2(y0, y1);
}

// ---------------- launch ----------------
extern "C" void kernel_launch(void* const* d_in, const int* in_sizes, int n_in,
                              void* d_out, int out_size) {
    const float* coords  = (const float*)d_in[0];
    const float* feats   = (const float*)d_in[1];
    const float* theta_w = (const float*)d_in[2];
    const float* theta_b = (const float*)d_in[3];
    const float* phi_w   = (const float*)d_in[4];
    const float* phi_b   = (const float*)d_in[5];
    const float* g_w     = (const float*)d_in[6];
    const float* g_b     = (const float*)d_in[7];
    const float* pe1_w1  = (const float*)d_in[8];
    const float* pe1_b1  = (const float*)d_in[9];
    const float* pe1_w2  = (const float*)d_in[10];
    const float* pe1_b2  = (const float*)d_in[11];
    const float* W_w     = (const float*)d_in[12];
    const float* W_b     = (const float*)d_in[13];
    float* out = (float*)d_out;

    float *p_theta, *p_phi, *p_g, *p_y;
    cudaGetSymbolAddress((void**)&p_theta, g_theta);
    cudaGetSymbolAddress((void**)&p_phi,   g_phi);
    cudaGetSymbolAddress((void**)&p_g,     g_gv);
    cudaGetSymbolAddress((void**)&p_y,     g_y);

    prep_kernel<<<(NPTS + 255) / 256, 256>>>(coords);
    knn_kernel<<<NPTS / 8, 256>>>();

    // theta / phi / g fused into one launch (grid.y = 3)
    linear_kernel<<<dim3(NPTS / 64, 3), 256>>>(
        feats, theta_w, phi_w, g_w, theta_b, phi_b, g_b,
        p_theta, p_phi, p_g, nullptr);

    attn_kernel<<<NPTS / 2, 256>>>(coords, pe1_w1, pe1_b1, pe1_w2, pe1_b2);

    // final: out = y @ W_w + W_b + feats
    linear_kernel<<<dim3(NPTS / 64, 1), 256>>>(
        p_y, W_w, W_w, W_w, W_b, W_b, W_b,
        out, out, out, feats);
}

// round 4
// speedup vs baseline: 3.2301x; 1.8445x over previous
#include <cuda_runtime.h>
#include <math_constants.h>

#define NPTS 8192
#define CCH  256
#define KNB  16

typedef unsigned long long ull;

// ---------------- packed f32x2 helpers ----------------
__device__ __forceinline__ ull pk2(float x, float y) {
    ull r; asm("mov.b64 %0, {%1, %2};" : "=l"(r) : "f"(x), "f"(y)); return r;
}
__device__ __forceinline__ ull fma2(ull a, ull b, ull c) {
    ull d; asm("fma.rn.f32x2 %0, %1, %2, %3;" : "=l"(d) : "l"(a), "l"(b), "l"(c)); return d;
}
__device__ __forceinline__ float2 upk(ull v) {
    float2 f; asm("mov.b64 {%0, %1}, %2;" : "=f"(f.x), "=f"(f.y) : "l"(v)); return f;
}

// ---------------- scratch (device globals; no allocation APIs) ----------------
__device__ float4 g_pts[NPTS];          // x, y, z, |p|^2
__device__ int    g_idx[NPTS * KNB];    // knn indices
__device__ float  g_theta[NPTS * CCH];  // feats @ theta_w + theta_b
__device__ float  g_phi[NPTS * CCH];    // feats @ phi_w + phi_b
__device__ float  g_gv[NPTS * CCH];     // feats @ g_w + g_b
__device__ float  g_y[NPTS * CCH];      // attention output before final linear

// ---------------- prep: pack coords + squared norm ----------------
__global__ void prep_kernel(const float* __restrict__ coords) {
    int i = blockIdx.x * blockDim.x + threadIdx.x;
    if (i < NPTS) {
        float x = coords[3 * i + 0];
        float y = coords[3 * i + 1];
        float z = coords[3 * i + 2];
        g_pts[i] = make_float4(x, y, z, x * x + y * y + z * z);
    }
}

// ---------------- KNN: warp per query, lane-sliced top-16, smem tiles ----------------
// Warp-cooperative top-16: lane s (s<16) holds the s-th smallest 64-bit key
// (sortable-d2 bits << 32 | idx). Candidates are filtered against the true
// 16th-best (thr) so the insert path runs only ~120x per query, and each
// insert is ~14 warp-uniform instructions (ballot-position + shfl shift).
__global__ __launch_bounds__(256) void knn_kernel() {
    __shared__ float4 s_pts[1024];

    int warp = threadIdx.x >> 5;
    int lane = threadIdx.x & 31;
    int q = blockIdx.x * 8 + warp;

    float4 qp = g_pts[q];

    ull slot = ~0ull;   // this lane's slot (lanes 0..15 meaningful)
    ull thr  = ~0ull;   // current 16th-best key, replicated in all lanes

    for (int t0 = 0; t0 < NPTS; t0 += 1024) {
        for (int r = threadIdx.x; r < 1024; r += 256) s_pts[r] = g_pts[t0 + r];
        __syncthreads();

        for (int jj = lane; jj < 1024; jj += 32) {
            float4 p = s_pts[jj];
            float dot = qp.x * p.x + qp.y * p.y + qp.z * p.z;
            float d2 = (qp.w + p.w) - 2.0f * dot;     // matches reference formula
            unsigned u = __float_as_uint(d2);
            u = ((int)u < 0) ? ~u : (u | 0x80000000u); // monotonic float->uint
            ull key = ((ull)u << 32) | (unsigned)(t0 + jj);

            unsigned mask = __ballot_sync(0xffffffffu, key < thr);
            while (mask) {
                int src = __ffs(mask) - 1;
                mask &= mask - 1;
                ull cand = __shfl_sync(0xffffffffu, key, src);
                if (cand < thr) {                      // warp-uniform re-check
                    unsigned lt = __ballot_sync(0xffffffffu, (lane < 16) && (slot < cand));
                    int pos = __popc(lt);
                    ull prev = __shfl_up_sync(0xffffffffu, slot, 1);
                    if (lane >= pos && lane < 16) slot = (lane == pos) ? cand : prev;
                    thr = __shfl_sync(0xffffffffu, slot, 15);
                }
            }
        }
        __syncthreads();
    }

    if (lane < 16) g_idx[q * KNB + lane] = (int)(unsigned)(slot & 0xffffffffu);
}

// ---------------- linear: out = A @ W + b (+ resid), packed f32x2 ----------------
__global__ __launch_bounds__(256) void linear_kernel(
    const float* __restrict__ A,
    const float* __restrict__ W0, const float* __restrict__ W1, const float* __restrict__ W2,
    const float* __restrict__ b0_, const float* __restrict__ b1_, const float* __restrict__ b2_,
    float* __restrict__ o0, float* __restrict__ o1, float* __restrict__ o2,
    const float* __restrict__ resid)
{
    const float* W    = (blockIdx.y == 0) ? W0 : (blockIdx.y == 1) ? W1 : W2;
    const float* bias = (blockIdx.y == 0) ? b0_ : (blockIdx.y == 1) ? b1_ : b2_;
    float*       out  = (blockIdx.y == 0) ? o0 : (blockIdx.y == 1) ? o1 : o2;

    __shared__ float s_A[64][17];
    __shared__ float s_W[16][256];

    int t  = threadIdx.x;
    int tx = t & 31;
    int ty = t >> 5;
    int row0 = blockIdx.x * 64;

    ull acc[8][4];
#pragma unroll
    for (int i = 0; i < 8; ++i)
#pragma unroll
        for (int p = 0; p < 4; ++p) acc[i][p] = 0ull;

    int am = t >> 2;
    int ak = (t & 3) * 4;

    for (int ks = 0; ks < 16; ++ks) {
        float4 a4 = *(const float4*)&A[(row0 + am) * CCH + ks * 16 + ak];
        s_A[am][ak + 0] = a4.x; s_A[am][ak + 1] = a4.y;
        s_A[am][ak + 2] = a4.z; s_A[am][ak + 3] = a4.w;
#pragma unroll
        for (int r = 0; r < 4; ++r) {
            int kk = (t >> 6) + r * 4;
            int c  = (t & 63) * 4;
            *(float4*)&s_W[kk][c] = *(const float4*)&W[(ks * 16 + kk) * CCH + c];
        }
        __syncthreads();
#pragma unroll
        for (int kk = 0; kk < 16; ++kk) {
            ull av[8];
#pragma unroll
            for (int i = 0; i < 8; ++i) {
                float a = s_A[ty * 8 + i][kk];
                av[i] = pk2(a, a);
            }
            const ull* wrow = (const ull*)&s_W[kk][tx * 8];
            ull wp0 = wrow[0], wp1 = wrow[1], wp2 = wrow[2], wp3 = wrow[3];
#pragma unroll
            for (int i = 0; i < 8; ++i) {
                acc[i][0] = fma2(av[i], wp0, acc[i][0]);
                acc[i][1] = fma2(av[i], wp1, acc[i][1]);
                acc[i][2] = fma2(av[i], wp2, acc[i][2]);
                acc[i][3] = fma2(av[i], wp3, acc[i][3]);
            }
        }
        __syncthreads();
    }

    float4 b0 = *(const float4*)&bias[tx * 8];
    float4 b1 = *(const float4*)&bias[tx * 8 + 4];
#pragma unroll
    for (int i = 0; i < 8; ++i) {
        int row = row0 + ty * 8 + i;
        float2 c01 = upk(acc[i][0]);
        float2 c23 = upk(acc[i][1]);
        float2 c45 = upk(acc[i][2]);
        float2 c67 = upk(acc[i][3]);
        float4 r0, r1;
        r0.x = c01.x + b0.x; r0.y = c01.y + b0.y;
        r0.z = c23.x + b0.z; r0.w = c23.y + b0.w;
        r1.x = c45.x + b1.x; r1.y = c45.y + b1.y;
        r1.z = c67.x + b1.z; r1.w = c67.y + b1.w;
        if (resid != nullptr) {
            float4 f0 = *(const float4*)&resid[row * CCH + tx * 8];
            float4 f1 = *(const float4*)&resid[row * CCH + tx * 8 + 4];
            r0.x += f0.x; r0.y += f0.y; r0.z += f0.z; r0.w += f0.w;
            r1.x += f1.x; r1.y += f1.y; r1.z += f1.z; r1.w += f1.w;
        }
        *(float4*)&out[row * CCH + tx * 8]     = r0;
        *(float4*)&out[row * CCH + tx * 8 + 4] = r1;
    }
}

// ---------------- fused attention with packed f32x2 pe-GEMM ----------------
__global__ __launch_bounds__(256) void attn_kernel(
    const float* __restrict__ coords,
    const float* __restrict__ pe1_w1, const float* __restrict__ pe1_b1,
    const float* __restrict__ pe1_w2, const float* __restrict__ pe1_b2)
{
    __shared__ float s_w1[3 * 256];
    __shared__ float s_b1[256];
    __shared__ float s_hid[2][256][20];   // 40 KB
    __shared__ int   s_idx[2][16];
    __shared__ float s_delta[2][16][3];

    int t    = threadIdx.x;
    int half = t >> 7;
    int lt   = t & 127;
    int i    = blockIdx.x * 2 + half;
    int c0   = lt * 2;

    s_b1[t] = pe1_b1[t];
    { int r = t; if (r < 768) s_w1[r] = pe1_w1[r]; r += 256; if (r < 768) s_w1[r] = pe1_w1[r]; r += 256; if (r < 768) s_w1[r] = pe1_w1[r]; }
    if (lt < 16) s_idx[half][lt] = g_idx[i * KNB + lt];
    __syncthreads();

    if (lt < 48) {
        int k = lt / 3, d = lt % 3;
        s_delta[half][k][d] = coords[s_idx[half][k] * 3 + d] - coords[i * 3 + d];
    }
    __syncthreads();

    {
        float h0[16], h1[16];
        float w1x0 = s_w1[c0],       w1x1 = s_w1[c0 + 1];
        float w1y0 = s_w1[256 + c0], w1y1 = s_w1[256 + c0 + 1];
        float w1z0 = s_w1[512 + c0], w1z1 = s_w1[512 + c0 + 1];
        float bb0 = s_b1[c0], bb1 = s_b1[c0 + 1];
#pragma unroll
        for (int k = 0; k < 16; ++k) {
            float dx = s_delta[half][k][0];
            float dy = s_delta[half][k][1];
            float dz = s_delta[half][k][2];
            h0[k] = fmaxf(fmaf(dz, w1z0, fmaf(dy, w1y0, fmaf(dx, w1x0, bb0))), 0.0f);
            h1[k] = fmaxf(fmaf(dz, w1z1, fmaf(dy, w1y1, fmaf(dx, w1x1, bb1))), 0.0f);
        }
        float* r0 = &s_hid[half][c0][0];
        float* r1 = &s_hid[half][c0 + 1][0];
#pragma unroll
        for (int q = 0; q < 4; ++q) {
            *(float4*)&r0[q * 4] = make_float4(h0[q * 4], h0[q * 4 + 1], h0[q * 4 + 2], h0[q * 4 + 3]);
            *(float4*)&r1[q * 4] = make_float4(h1[q * 4], h1[q * 4 + 1], h1[q * 4 + 2], h1[q * 4 + 3]);
        }
    }
    __syncthreads();

    ull acc0[8], acc1[8];
    {
        float2 b2v = *(const float2*)&pe1_b2[c0];
        ull bi0 = pk2(b2v.x, b2v.x);
        ull bi1 = pk2(b2v.y, b2v.y);
#pragma unroll
        for (int p = 0; p < 8; ++p) { acc0[p] = bi0; acc1[p] = bi1; }
    }

    const float* hbase = &s_hid[half][0][0];
#pragma unroll 4
    for (int j = 0; j < 256; ++j) {
        const ull* hrow = (const ull*)(hbase + j * 20);
        float2 w = __ldg((const float2*)&pe1_w2[j * CCH + c0]);
        ull wx = pk2(w.x, w.x);
        ull wy = pk2(w.y, w.y);
#pragma unroll
        for (int p = 0; p < 8; ++p) {
            ull h = hrow[p];
            acc0[p] = fma2(h, wx, acc0[p]);
            acc1[p] = fma2(h, wy, acc1[p]);
        }
    }

    float pe0[16], pe1v[16];
#pragma unroll
    for (int p = 0; p < 8; ++p) {
        float2 u0 = upk(acc0[p]);
        float2 u1 = upk(acc1[p]);
        pe0[2 * p] = u0.x; pe0[2 * p + 1] = u0.y;
        pe1v[2 * p] = u1.x; pe1v[2 * p + 1] = u1.y;
    }

    float th0 = g_theta[i * CCH + c0];
    float th1 = g_theta[i * CCH + c0 + 1];
#pragma unroll
    for (int k = 0; k < 16; ++k) {
        int nid = s_idx[half][k];
        float2 ph = *(const float2*)&g_phi[nid * CCH + c0];
        pe0[k]  = (pe0[k]  * (th0 - ph.x) + pe0[k])  * 0.0625f;
        pe1v[k] = (pe1v[k] * (th1 - ph.y) + pe1v[k]) * 0.0625f;
    }

    float m0 = pe0[0], m1 = pe1v[0];
#pragma unroll
    for (int k = 1; k < 16; ++k) { m0 = fmaxf(m0, pe0[k]); m1 = fmaxf(m1, pe1v[k]); }
    float sum0 = 0.0f, sum1 = 0.0f;
#pragma unroll
    for (int k = 0; k < 16; ++k) {
        pe0[k]  = expf(pe0[k]  - m0); sum0 += pe0[k];
        pe1v[k] = expf(pe1v[k] - m1); sum1 += pe1v[k];
    }
    float inv0 = 1.0f / sum0, inv1 = 1.0f / sum1;

    float y0 = 0.0f, y1 = 0.0f;
#pragma unroll
    for (int k = 0; k < 16; ++k) {
        int nid = s_idx[half][k];
        float2 gk = *(const float2*)&g_gv[nid * CCH + c0];
        y0 = fmaf(pe0[k]  * inv0, gk.x, y0);
        y1 = fmaf(pe1v[k] * inv1, gk.y, y1);
    }
    *(float2*)&g_y[i * CCH + c0] = make_float2(y0, y1);
}

// ---------------- launch ----------------
extern "C" void kernel_launch(void* const* d_in, const int* in_sizes, int n_in,
                              void* d_out, int out_size) {
    const float* coords  = (const float*)d_in[0];
    const float* feats   = (const float*)d_in[1];
    const float* theta_w = (const float*)d_in[2];
    const float* theta_b = (const float*)d_in[3];
    const float* phi_w   = (const float*)d_in[4];
    const float* phi_b   = (const float*)d_in[5];
    const float* g_w     = (const float*)d_in[6];
    const float* g_b     = (const float*)d_in[7];
    const float* pe1_w1  = (const float*)d_in[8];
    const float* pe1_b1  = (const float*)d_in[9];
    const float* pe1_w2  = (const float*)d_in[10];
    const float* pe1_b2  = (const float*)d_in[11];
    const float* W_w     = (const float*)d_in[12];
    const float* W_b     = (const float*)d_in[13];
    float* out = (float*)d_out;

    float *p_theta, *p_phi, *p_g, *p_y;
    cudaGetSymbolAddress((void**)&p_theta, g_theta);
    cudaGetSymbolAddress((void**)&p_phi,   g_phi);
    cudaGetSymbolAddress((void**)&p_g,     g_gv);
    cudaGetSymbolAddress((void**)&p_y,     g_y);

    prep_kernel<<<(NPTS + 255) / 256, 256>>>(coords);
    knn_kernel<<<NPTS / 8, 256>>>();

    linear_kernel<<<dim3(NPTS / 64, 3), 256>>>(
        feats, theta_w, phi_w, g_w, theta_b, phi_b, g_b,
        p_theta, p_phi, p_g, nullptr);

    attn_kernel<<<NPTS / 2, 256>>>(coords, pe1_w1, pe1_b1, pe1_w2, pe1_b2);

    linear_kernel<<<dim3(NPTS / 64, 1), 256>>>(
        p_y, W_w, W_w, W_w, W_b, W_b, W_b,
        out, out, out, feats);
}

// round 6
// speedup vs baseline: 4.4101x; 1.3653x over previous
#include <cuda_runtime.h>
#include <cuda_bf16.h>
#include <math_constants.h>
#include <cstdint>

#define NPTS 8192
#define CCH  256
#define KNB  16

typedef unsigned long long ull;

// ---------------- packed f32x2 helpers (linear kernels) ----------------
__device__ __forceinline__ ull pk2(float x, float y) {
    ull r; asm("mov.b64 %0, {%1, %2};" : "=l"(r) : "f"(x), "f"(y)); return r;
}
__device__ __forceinline__ ull fma2(ull a, ull b, ull c) {
    ull d; asm("fma.rn.f32x2 %0, %1, %2, %3;" : "=l"(d) : "l"(a), "l"(b), "l"(c)); return d;
}
__device__ __forceinline__ float2 upk(ull v) {
    float2 f; asm("mov.b64 {%0, %1}, %2;" : "=f"(f.x), "=f"(f.y) : "l"(v)); return f;
}

// ---------------- bf16 pack helpers ----------------
// returns packed bf16x2 with 'lo' in bits[15:0], 'hi' in bits[31:16]
__device__ __forceinline__ uint32_t bf2pack(float lo, float hi) {
    uint32_t r;
    asm("cvt.rn.bf16x2.f32 %0, %1, %2;" : "=r"(r) : "f"(hi), "f"(lo));
    return r;
}
__device__ __forceinline__ float bflo_f(uint32_t u) { return __uint_as_float(u << 16); }
__device__ __forceinline__ float bfhi_f(uint32_t u) { return __uint_as_float(u & 0xffff0000u); }

// mma.sync m16n8k16 row.col f32.bf16.bf16.f32 (baseline sm_80 PTX — no 'a' target needed)
__device__ __forceinline__ void mma16816(float* d,
                                         uint32_t a0, uint32_t a1, uint32_t a2, uint32_t a3,
                                         uint32_t b0, uint32_t b1) {
    asm volatile(
        "mma.sync.aligned.m16n8k16.row.col.f32.bf16.bf16.f32 "
        "{%0,%1,%2,%3}, {%4,%5,%6,%7}, {%8,%9}, {%0,%1,%2,%3};"
        : "+f"(d[0]), "+f"(d[1]), "+f"(d[2]), "+f"(d[3])
        : "r"(a0), "r"(a1), "r"(a2), "r"(a3), "r"(b0), "r"(b1));
}

// ---------------- scratch (device globals; no allocation APIs) ----------------
__device__ float4 g_pts[NPTS];
__device__ int    g_idx[NPTS * KNB];
__device__ float  g_theta[NPTS * CCH];
__device__ float  g_phi[NPTS * CCH];
__device__ float  g_gv[NPTS * CCH];
__device__ float  g_y[NPTS * CCH];
// w2 pre-packed into mma B-fragment layout, hi/lo bf16 planes.
// index = (((cc*16 + kt)*8 + nt)*64 + lane*2 + reg)
__device__ uint32_t g_w2f_hi[32768];
__device__ uint32_t g_w2f_lo[32768];

// ---------------- prep: pack coords + squared norm ----------------
__global__ void prep_kernel(const float* __restrict__ coords) {
    int i = blockIdx.x * blockDim.x + threadIdx.x;
    if (i < NPTS) {
        float x = coords[3 * i + 0];
        float y = coords[3 * i + 1];
        float z = coords[3 * i + 2];
        g_pts[i] = make_float4(x, y, z, x * x + y * y + z * z);
    }
}

// ---------------- prep: w2 -> B fragments (hi/lo split) ----------------
__global__ void prep_w2_frag(const float* __restrict__ w2) {
    int tid = blockIdx.x * 256 + threadIdx.x;           // 0..32767
    int reg = tid & 1;
    int ln  = (tid >> 1) & 31;
    int nt  = (tid >> 6) & 7;
    int kt  = (tid >> 9) & 15;
    int cc  = (tid >> 13) & 3;
    int gq  = ln >> 2, c4 = ln & 3;
    int n = cc * 64 + nt * 8 + gq;
    int k = kt * 16 + 2 * c4 + reg * 8;
    float v0 = w2[k * CCH + n];
    float v1 = w2[(k + 1) * CCH + n];
    uint32_t hi = bf2pack(v0, v1);
    float r0 = v0 - bflo_f(hi);
    float r1 = v1 - bfhi_f(hi);
    g_w2f_hi[tid] = hi;
    g_w2f_lo[tid] = bf2pack(r0, r1);
}

// ---------------- KNN: warp per query, lane-sliced top-16, smem tiles ----------------
__global__ __launch_bounds__(256) void knn_kernel() {
    __shared__ float4 s_pts[1024];

    int warp = threadIdx.x >> 5;
    int lane = threadIdx.x & 31;
    int q = blockIdx.x * 8 + warp;

    float4 qp = g_pts[q];

    ull slot = ~0ull;
    ull thr  = ~0ull;

    for (int t0 = 0; t0 < NPTS; t0 += 1024) {
        for (int r = threadIdx.x; r < 1024; r += 256) s_pts[r] = g_pts[t0 + r];
        __syncthreads();

        for (int jj = lane; jj < 1024; jj += 32) {
            float4 p = s_pts[jj];
            float dot = qp.x * p.x + qp.y * p.y + qp.z * p.z;
            float d2 = (qp.w + p.w) - 2.0f * dot;
            unsigned u = __float_as_uint(d2);
            u = ((int)u < 0) ? ~u : (u | 0x80000000u);
            ull key = ((ull)u << 32) | (unsigned)(t0 + jj);

            unsigned mask = __ballot_sync(0xffffffffu, key < thr);
            while (mask) {
                int src = __ffs(mask) - 1;
                mask &= mask - 1;
                ull cand = __shfl_sync(0xffffffffu, key, src);
                if (cand < thr) {
                    unsigned lt = __ballot_sync(0xffffffffu, (lane < 16) && (slot < cand));
                    int pos = __popc(lt);
                    ull prev = __shfl_up_sync(0xffffffffu, slot, 1);
                    if (lane >= pos && lane < 16) slot = (lane == pos) ? cand : prev;
                    thr = __shfl_sync(0xffffffffu, slot, 15);
                }
            }
        }
        __syncthreads();
    }

    if (lane < 16) g_idx[q * KNB + lane] = (int)(unsigned)(slot & 0xffffffffu);
}

// ---------------- linear: out = A @ W + b (+ resid), packed f32x2 ----------------
__global__ __launch_bounds__(256) void linear_kernel(
    const float* __restrict__ A,
    const float* __restrict__ W0, const float* __restrict__ W1, const float* __restrict__ W2,
    const float* __restrict__ b0_, const float* __restrict__ b1_, const float* __restrict__ b2_,
    float* __restrict__ o0, float* __restrict__ o1, float* __restrict__ o2,
    const float* __restrict__ resid)
{
    const float* W    = (blockIdx.y == 0) ? W0 : (blockIdx.y == 1) ? W1 : W2;
    const float* bias = (blockIdx.y == 0) ? b0_ : (blockIdx.y == 1) ? b1_ : b2_;
    float*       out  = (blockIdx.y == 0) ? o0 : (blockIdx.y == 1) ? o1 : o2;

    __shared__ float s_A[64][17];
    __shared__ float s_W[16][256];

    int t  = threadIdx.x;
    int tx = t & 31;
    int ty = t >> 5;
    int row0 = blockIdx.x * 64;

    ull acc[8][4];
#pragma unroll
    for (int i = 0; i < 8; ++i)
#pragma unroll
        for (int p = 0; p < 4; ++p) acc[i][p] = 0ull;

    int am = t >> 2;
    int ak = (t & 3) * 4;

    for (int ks = 0; ks < 16; ++ks) {
        float4 a4 = *(const float4*)&A[(row0 + am) * CCH + ks * 16 + ak];
        s_A[am][ak + 0] = a4.x; s_A[am][ak + 1] = a4.y;
        s_A[am][ak + 2] = a4.z; s_A[am][ak + 3] = a4.w;
#pragma unroll
        for (int r = 0; r < 4; ++r) {
            int kk = (t >> 6) + r * 4;
            int c  = (t & 63) * 4;
            *(float4*)&s_W[kk][c] = *(const float4*)&W[(ks * 16 + kk) * CCH + c];
        }
        __syncthreads();
#pragma unroll
        for (int kk = 0; kk < 16; ++kk) {
            ull av[8];
#pragma unroll
            for (int i = 0; i < 8; ++i) {
                float a = s_A[ty * 8 + i][kk];
                av[i] = pk2(a, a);
            }
            const ull* wrow = (const ull*)&s_W[kk][tx * 8];
            ull wp0 = wrow[0], wp1 = wrow[1], wp2 = wrow[2], wp3 = wrow[3];
#pragma unroll
            for (int i = 0; i < 8; ++i) {
                acc[i][0] = fma2(av[i], wp0, acc[i][0]);
                acc[i][1] = fma2(av[i], wp1, acc[i][1]);
                acc[i][2] = fma2(av[i], wp2, acc[i][2]);
                acc[i][3] = fma2(av[i], wp3, acc[i][3]);
            }
        }
        __syncthreads();
    }

    float4 b0 = *(const float4*)&bias[tx * 8];
    float4 b1 = *(const float4*)&bias[tx * 8 + 4];
#pragma unroll
    for (int i = 0; i < 8; ++i) {
        int row = row0 + ty * 8 + i;
        float2 c01 = upk(acc[i][0]);
        float2 c23 = upk(acc[i][1]);
        float2 c45 = upk(acc[i][2]);
        float2 c67 = upk(acc[i][3]);
        float4 r0, r1;
        r0.x = c01.x + b0.x; r0.y = c01.y + b0.y;
        r0.z = c23.x + b0.z; r0.w = c23.y + b0.w;
        r1.x = c45.x + b1.x; r1.y = c45.y + b1.y;
        r1.z = c67.x + b1.z; r1.w = c67.y + b1.w;
        if (resid != nullptr) {
            float4 f0 = *(const float4*)&resid[row * CCH + tx * 8];
            float4 f1 = *(const float4*)&resid[row * CCH + tx * 8 + 4];
            r0.x += f0.x; r0.y += f0.y; r0.z += f0.z; r0.w += f0.w;
            r1.x += f1.x; r1.y += f1.y; r1.z += f1.z; r1.w += f1.w;
        }
        *(float4*)&out[row * CCH + tx * 8]     = r0;
        *(float4*)&out[row * CCH + tx * 8 + 4] = r1;
    }
}

// ---------------- h-pair: 2 hidden values -> bf16 hi/lo fragment regs ----------------
// pa = [wx0,wx1,wy0,wy1], pb = [wz0,wz1,b0,b1]
__device__ __forceinline__ void hpair(float4 pa, float4 pb,
                                      float dx, float dy, float dz,
                                      uint32_t& hi, uint32_t& lo) {
    float h0 = fmaxf(fmaf(dz, pb.x, fmaf(dy, pa.z, fmaf(dx, pa.x, pb.z))), 0.0f);
    float h1 = fmaxf(fmaf(dz, pb.y, fmaf(dy, pa.w, fmaf(dx, pa.y, pb.w))), 0.0f);
    hi = bf2pack(h0, h1);
    float r0 = h0 - bflo_f(hi);
    float r1 = h1 - bfhi_f(hi);
    lo = bf2pack(r0, r1);
}

// ---------------- attention: mma.sync bf16x3 pe-GEMM + warp-local softmax ----------------
// 8 points/block, warp w owns point w (m16 rows = its 16 neighbors).
// N=256 processed in 4 chunks of 64; K=256 in 16 k-tiles of 16.
// D = Ahi*Bhi + Ahi*Blo + Alo*Bhi  (fp32 accum), A computed in-register.
// dyn smem (uint32 units): BHI[8192] | BLO[8192] | W1P[1024f] | DL[384f] | ID[128]
#define ATTN_SMEM_U32 17920
#define ATTN_SMEM_B   (ATTN_SMEM_U32 * 4)

__global__ void __launch_bounds__(256, 1) attn_tc_kernel(
    const float* __restrict__ coords,
    const float* __restrict__ pe1_w1, const float* __restrict__ pe1_b1,
    const float* __restrict__ pe1_b2)
{
    extern __shared__ uint32_t dsm[];
    uint32_t* BHI = dsm;
    uint32_t* BLO = dsm + 8192;
    float*    W1P = (float*)(dsm + 16384);
    float*    DL  = (float*)(dsm + 17408);
    int*      ID  = (int*)(dsm + 17792);

    int t = threadIdx.x;
    int lane = t & 31;
    int w = t >> 5;
    int g = lane >> 2;
    int c4 = lane & 3;

    // w1 repack: pair p -> [wx0,wx1,wy0,wy1] [wz0,wz1,b0,b1]
    {
        int f = 4 * t;
#pragma unroll
        for (int u = 0; u < 4; ++u) {
            int ff = f + u, p = ff >> 3, comp = ff & 7;
            float v;
            if (comp < 6) v = pe1_w1[(comp >> 1) * CCH + 2 * p + (comp & 1)];
            else          v = pe1_b1[2 * p + (comp & 1)];
            W1P[ff] = v;
        }
    }
    if (t < 128) ID[t] = g_idx[blockIdx.x * 128 + t];
    __syncthreads();
    if (t < 128) {
        int nid = ID[t];
        int ip = blockIdx.x * 8 + (t >> 4);
#pragma unroll
        for (int d = 0; d < 3; ++d)
            DL[t * 3 + d] = coords[nid * 3 + d] - coords[ip * 3 + d];
    }
    __syncthreads();

    int rA = w * 16 + g, rB = rA + 8;
    float dxa = DL[rA * 3], dya = DL[rA * 3 + 1], dza = DL[rA * 3 + 2];
    float dxb = DL[rB * 3], dyb = DL[rB * 3 + 1], dzb = DL[rB * 3 + 2];
    int nid0 = ID[rA], nid1 = ID[rB];
    int ipt = blockIdx.x * 8 + w;

    const float4* w1p4 = (const float4*)W1P;

    for (int cc = 0; cc < 4; ++cc) {
        __syncthreads();
        {   // stage this n-chunk's B fragments (hi+lo, 64KB) into smem
            const uint4* sh = (const uint4*)(g_w2f_hi + cc * 8192);
            const uint4* sl = (const uint4*)(g_w2f_lo + cc * 8192);
            uint4* dh = (uint4*)BHI;
            uint4* dl4 = (uint4*)BLO;
            for (int u = t; u < 2048; u += 256) { dh[u] = sh[u]; dl4[u] = sl[u]; }
        }
        __syncthreads();

        float acc[8][4];
#pragma unroll
        for (int nt = 0; nt < 8; ++nt)
#pragma unroll
            for (int r = 0; r < 4; ++r) acc[nt][r] = 0.0f;

#pragma unroll 4
        for (int kt = 0; kt < 16; ++kt) {
            int jp0 = kt * 8 + c4;
            float4 p0a = w1p4[jp0 * 2],     p0b = w1p4[jp0 * 2 + 1];
            float4 p1a = w1p4[jp0 * 2 + 8], p1b = w1p4[jp0 * 2 + 9];
            uint32_t a0, l0, a1, l1, a2, l2, a3, l3;
            hpair(p0a, p0b, dxa, dya, dza, a0, l0);
            hpair(p0a, p0b, dxb, dyb, dzb, a1, l1);
            hpair(p1a, p1b, dxa, dya, dza, a2, l2);
            hpair(p1a, p1b, dxb, dyb, dzb, a3, l3);
            int bbase = kt * 512 + lane * 2;
#pragma unroll
            for (int nt = 0; nt < 8; ++nt) {
                uint2 bh = *(const uint2*)&BHI[bbase + nt * 64];
                uint2 bl = *(const uint2*)&BLO[bbase + nt * 64];
                mma16816(acc[nt], a0, a1, a2, a3, bh.x, bh.y);
                mma16816(acc[nt], a0, a1, a2, a3, bl.x, bl.y);
                mma16816(acc[nt], l0, l1, l2, l3, bh.x, bh.y);
            }
        }

        // epilogue: softmax over the 16 rows (within warp) + weighted g-sum
#pragma unroll
        for (int nt = 0; nt < 8; ++nt) {
            int n0 = cc * 64 + nt * 8 + 2 * c4;
            float2 b2v = *(const float2*)&pe1_b2[n0];
            float2 th  = *(const float2*)&g_theta[ipt * CCH + n0];
            float2 ph0 = *(const float2*)&g_phi[nid0 * CCH + n0];
            float2 ph1 = *(const float2*)&g_phi[nid1 * CCH + n0];

            float pe00 = acc[nt][0] + b2v.x, pe01 = acc[nt][1] + b2v.y;
            float pe10 = acc[nt][2] + b2v.x, pe11 = acc[nt][3] + b2v.y;

            float v00 = (pe00 * (th.x - ph0.x) + pe00) * 0.0625f;
            float v01 = (pe01 * (th.y - ph0.y) + pe01) * 0.0625f;
            float v10 = (pe10 * (th.x - ph1.x) + pe10) * 0.0625f;
            float v11 = (pe11 * (th.y - ph1.y) + pe11) * 0.0625f;

            float m0 = fmaxf(v00, v10), m1 = fmaxf(v01, v11);
#pragma unroll
            for (int off = 4; off <= 16; off <<= 1) {
                m0 = fmaxf(m0, __shfl_xor_sync(0xffffffffu, m0, off));
                m1 = fmaxf(m1, __shfl_xor_sync(0xffffffffu, m1, off));
            }
            float e00 = expf(v00 - m0), e10 = expf(v10 - m0);
            float e01 = expf(v01 - m1), e11 = expf(v11 - m1);
            float s0 = e00 + e10, s1 = e01 + e11;
#pragma unroll
            for (int off = 4; off <= 16; off <<= 1) {
                s0 += __shfl_xor_sync(0xffffffffu, s0, off);
                s1 += __shfl_xor_sync(0xffffffffu, s1, off);
            }
            float2 gv0 = *(const float2*)&g_gv[nid0 * CCH + n0];
            float2 gv1 = *(const float2*)&g_gv[nid1 * CCH + n0];
            float y0 = e00 * gv0.x + e10 * gv1.x;
            float y1 = e01 * gv0.y + e11 * gv1.y;
#pragma unroll
            for (int off = 4; off <= 16; off <<= 1) {
                y0 += __shfl_xor_sync(0xffffffffu, y0, off);
                y1 += __shfl_xor_sync(0xffffffffu, y1, off);
            }
            if (g == 0)
                *(float2*)&g_y[ipt * CCH + n0] = make_float2(y0 / s0, y1 / s1);
        }
    }
}

// ---------------- launch ----------------
extern "C" void kernel_launch(void* const* d_in, const int* in_sizes, int n_in,
                              void* d_out, int out_size) {
    const float* coords  = (const float*)d_in[0];
    const float* feats   = (const float*)d_in[1];
    const float* theta_w = (const float*)d_in[2];
    const float* theta_b = (const float*)d_in[3];
    const float* phi_w   = (const float*)d_in[4];
    const float* phi_b   = (const float*)d_in[5];
    const float* g_w     = (const float*)d_in[6];
    const float* g_b     = (const float*)d_in[7];
    const float* pe1_w1  = (const float*)d_in[8];
    const float* pe1_b1  = (const float*)d_in[9];
    const float* pe1_w2  = (const float*)d_in[10];
    const float* pe1_b2  = (const float*)d_in[11];
    const float* W_w     = (const float*)d_in[12];
    const float* W_b     = (const float*)d_in[13];
    float* out = (float*)d_out;

    float *p_theta, *p_phi, *p_g, *p_y;
    cudaGetSymbolAddress((void**)&p_theta, g_theta);
    cudaGetSymbolAddress((void**)&p_phi,   g_phi);
    cudaGetSymbolAddress((void**)&p_g,     g_gv);
    cudaGetSymbolAddress((void**)&p_y,     g_y);

    cudaFuncSetAttribute(attn_tc_kernel,
                         cudaFuncAttributeMaxDynamicSharedMemorySize, ATTN_SMEM_B);

    prep_kernel<<<(NPTS + 255) / 256, 256>>>(coords);
    prep_w2_frag<<<128, 256>>>(pe1_w2);
    knn_kernel<<<NPTS / 8, 256>>>();

    linear_kernel<<<dim3(NPTS / 64, 3), 256>>>(
        feats, theta_w, phi_w, g_w, theta_b, phi_b, g_b,
        p_theta, p_phi, p_g, nullptr);

    attn_tc_kernel<<<NPTS / 8, 256, ATTN_SMEM_B>>>(coords, pe1_w1, pe1_b1, pe1_b2);

    linear_kernel<<<dim3(NPTS / 64, 1), 256>>>(
        p_y, W_w, W_w, W_w, W_b, W_b, W_b,
        out, out, out, feats);
}

// round 7
// speedup vs baseline: 6.3021x; 1.4290x over previous
#include <cuda_runtime.h>
#include <cuda_bf16.h>
#include <math_constants.h>
#include <cstdint>

#define NPTS 8192
#define CCH  256
#define KNB  16

typedef unsigned long long ull;

// ---------------- pack helpers ----------------
// bf16x2: bits[15:0] = lo arg, bits[31:16] = hi arg
__device__ __forceinline__ uint32_t bf2pack(float lo, float hi) {
    uint32_t r;
    asm("cvt.rn.bf16x2.f32 %0, %1, %2;" : "=r"(r) : "f"(hi), "f"(lo));
    return r;
}
__device__ __forceinline__ float bflo_f(uint32_t u) { return __uint_as_float(u << 16); }
__device__ __forceinline__ float bfhi_f(uint32_t u) { return __uint_as_float(u & 0xffff0000u); }
// f16x2: bits[15:0] = lo arg, bits[31:16] = hi arg
__device__ __forceinline__ uint32_t f16pack(float lo, float hi) {
    uint32_t r;
    asm("cvt.rn.f16x2.f32 %0, %1, %2;" : "=r"(r) : "f"(hi), "f"(lo));
    return r;
}

// mma.sync m16n8k16 row.col f32 accum (baseline sm_80 PTX)
__device__ __forceinline__ void mma_bf16(float* d,
                                         uint32_t a0, uint32_t a1, uint32_t a2, uint32_t a3,
                                         uint32_t b0, uint32_t b1) {
    asm volatile(
        "mma.sync.aligned.m16n8k16.row.col.f32.bf16.bf16.f32 "
        "{%0,%1,%2,%3}, {%4,%5,%6,%7}, {%8,%9}, {%0,%1,%2,%3};"
        : "+f"(d[0]), "+f"(d[1]), "+f"(d[2]), "+f"(d[3])
        : "r"(a0), "r"(a1), "r"(a2), "r"(a3), "r"(b0), "r"(b1));
}
__device__ __forceinline__ void mma_f16(float* d,
                                        uint32_t a0, uint32_t a1, uint32_t a2, uint32_t a3,
                                        uint32_t b0, uint32_t b1) {
    asm volatile(
        "mma.sync.aligned.m16n8k16.row.col.f32.f16.f16.f32 "
        "{%0,%1,%2,%3}, {%4,%5,%6,%7}, {%8,%9}, {%0,%1,%2,%3};"
        : "+f"(d[0]), "+f"(d[1]), "+f"(d[2]), "+f"(d[3])
        : "r"(a0), "r"(a1), "r"(a2), "r"(a3), "r"(b0), "r"(b1));
}

// ---------------- scratch (device globals; no allocation APIs) ----------------
__device__ float4 g_pts[NPTS];
__device__ int    g_idx[NPTS * KNB];
__device__ float  g_theta[NPTS * CCH];
__device__ float  g_phi[NPTS * CCH];
__device__ float  g_gv[NPTS * CCH];
__device__ float  g_y[NPTS * CCH];
// attn w2 -> fp16 B fragments: idx = (kt*8+nt_in_chunk + cc*...) see prep_w2_frag
__device__ uint32_t g_w2f[32768];
// linear weights (theta, phi, g, W) -> bf16 hi/lo B fragments:
// idx = m*32768 + kt*2048 + nt*64 + lane*2 + reg
__device__ uint32_t g_wf_hi[4 * 32768];
__device__ uint32_t g_wf_lo[4 * 32768];

// ---------------- prep: pack coords + squared norm ----------------
__global__ void prep_kernel(const float* __restrict__ coords) {
    int i = blockIdx.x * blockDim.x + threadIdx.x;
    if (i < NPTS) {
        float x = coords[3 * i + 0];
        float y = coords[3 * i + 1];
        float z = coords[3 * i + 2];
        g_pts[i] = make_float4(x, y, z, x * x + y * y + z * z);
    }
}

// ---------------- prep: w2 -> fp16 B fragments ----------------
__global__ void prep_w2_frag(const float* __restrict__ w2) {
    int tid = blockIdx.x * 256 + threadIdx.x;           // 0..32767
    int reg = tid & 1;
    int ln  = (tid >> 1) & 31;
    int nt  = (tid >> 6) & 7;
    int kt  = (tid >> 9) & 15;
    int cc  = (tid >> 13) & 3;
    int n = cc * 64 + nt * 8 + (ln >> 2);
    int k = kt * 16 + 2 * (ln & 3) + reg * 8;
    float v0 = w2[k * CCH + n];
    float v1 = w2[(k + 1) * CCH + n];
    g_w2f[tid] = f16pack(v0, v1);
}

// ---------------- prep: 4 linear weights -> bf16 hi/lo B fragments ----------------
__global__ void prep_wf_frag(const float* __restrict__ w0, const float* __restrict__ w1,
                             const float* __restrict__ w2, const float* __restrict__ w3) {
    int tid = blockIdx.x * 256 + threadIdx.x;           // 0..131071
    int m = tid >> 15;
    int r = tid & 32767;
    int reg = r & 1;
    int ln  = (r >> 1) & 31;
    int nt  = (r >> 6) & 31;
    int kt  = (r >> 11) & 15;
    int n = nt * 8 + (ln >> 2);
    int k = kt * 16 + 2 * (ln & 3) + reg * 8;
    const float* W = (m == 0) ? w0 : (m == 1) ? w1 : (m == 2) ? w2 : w3;
    float v0 = W[k * CCH + n];
    float v1 = W[(k + 1) * CCH + n];
    uint32_t hi = bf2pack(v0, v1);
    g_wf_hi[tid] = hi;
    g_wf_lo[tid] = bf2pack(v0 - bflo_f(hi), v1 - bfhi_f(hi));
}

// ---------------- KNN: warp per query, lane-sliced top-16, smem tiles ----------------
__global__ __launch_bounds__(256) void knn_kernel() {
    __shared__ float4 s_pts[1024];

    int warp = threadIdx.x >> 5;
    int lane = threadIdx.x & 31;
    int q = blockIdx.x * 8 + warp;

    float4 qp = g_pts[q];

    ull slot = ~0ull;
    ull thr  = ~0ull;

    for (int t0 = 0; t0 < NPTS; t0 += 1024) {
        for (int r = threadIdx.x; r < 1024; r += 256) s_pts[r] = g_pts[t0 + r];
        __syncthreads();

        for (int jj = lane; jj < 1024; jj += 32) {
            float4 p = s_pts[jj];
            float dot = qp.x * p.x + qp.y * p.y + qp.z * p.z;
            float d2 = (qp.w + p.w) - 2.0f * dot;
            unsigned u = __float_as_uint(d2);
            u = ((int)u < 0) ? ~u : (u | 0x80000000u);
            ull key = ((ull)u << 32) | (unsigned)(t0 + jj);

            unsigned mask = __ballot_sync(0xffffffffu, key < thr);
            while (mask) {
                int src = __ffs(mask) - 1;
                mask &= mask - 1;
                ull cand = __shfl_sync(0xffffffffu, key, src);
                if (cand < thr) {
                    unsigned lt = __ballot_sync(0xffffffffu, (lane < 16) && (slot < cand));
                    int pos = __popc(lt);
                    ull prev = __shfl_up_sync(0xffffffffu, slot, 1);
                    if (lane >= pos && lane < 16) slot = (lane == pos) ? cand : prev;
                    thr = __shfl_sync(0xffffffffu, slot, 15);
                }
            }
        }
        __syncthreads();
    }

    if (lane < 16) g_idx[q * KNB + lane] = (int)(unsigned)(slot & 0xffffffffu);
}

// ---------------- tensor-core linear: out = A @ W + b (+ resid), bf16x3 ----------------
// block: M=64 rows x N=256; 8 warps as 4(m-slab of 16) x 2(n-half of 128).
// A staged in smem pre-split into bf16 hi/lo packed k-pairs, stride 132 (conflict-free).
#define LIN_SMEM (2 * 64 * 132 * 4)

__global__ void __launch_bounds__(256, 2) linear_tc_kernel(
    const float* __restrict__ A, int m0,
    const float* __restrict__ b0_, const float* __restrict__ b1_, const float* __restrict__ b2_,
    float* __restrict__ o0, float* __restrict__ o1, float* __restrict__ o2,
    const float* __restrict__ resid)
{
    extern __shared__ uint32_t dsm[];
    uint32_t* sAhi = dsm;
    uint32_t* sAlo = dsm + 64 * 132;

    int mat = m0 + blockIdx.y;
    const float* bias = (blockIdx.y == 0) ? b0_ : (blockIdx.y == 1) ? b1_ : b2_;
    float*       out  = (blockIdx.y == 0) ? o0 : (blockIdx.y == 1) ? o1 : o2;

    int t = threadIdx.x;
    int lane = t & 31;
    int w = t >> 5;
    int wm = w & 3;          // m-slab
    int wn = w >> 2;         // n-half
    int g = lane >> 2;
    int c4 = lane & 3;
    int row0 = blockIdx.x * 64;

    // stage A tile, split to bf16 hi/lo packed pairs
    for (int idx = t; idx < 4096; idx += 256) {
        int row = idx >> 6;
        int q = idx & 63;
        float4 v = *(const float4*)&A[(row0 + row) * CCH + q * 4];
        uint32_t h0 = bf2pack(v.x, v.y);
        uint32_t h1 = bf2pack(v.z, v.w);
        uint32_t l0 = bf2pack(v.x - bflo_f(h0), v.y - bfhi_f(h0));
        uint32_t l1 = bf2pack(v.z - bflo_f(h1), v.w - bfhi_f(h1));
        *(uint2*)&sAhi[row * 132 + q * 2] = make_uint2(h0, h1);
        *(uint2*)&sAlo[row * 132 + q * 2] = make_uint2(l0, l1);
    }
    __syncthreads();

    float acc[16][4];
#pragma unroll
    for (int nt = 0; nt < 16; ++nt)
#pragma unroll
        for (int r = 0; r < 4; ++r) acc[nt][r] = 0.0f;

    int rA = wm * 16 + g;
    const uint32_t* bfrag_hi = g_wf_hi + mat * 32768;
    const uint32_t* bfrag_lo = g_wf_lo + mat * 32768;

#pragma unroll 2
    for (int kt = 0; kt < 16; ++kt) {
        uint32_t a0h = sAhi[rA * 132 + kt * 8 + c4];
        uint32_t a1h = sAhi[(rA + 8) * 132 + kt * 8 + c4];
        uint32_t a2h = sAhi[rA * 132 + kt * 8 + c4 + 4];
        uint32_t a3h = sAhi[(rA + 8) * 132 + kt * 8 + c4 + 4];
        uint32_t a0l = sAlo[rA * 132 + kt * 8 + c4];
        uint32_t a1l = sAlo[(rA + 8) * 132 + kt * 8 + c4];
        uint32_t a2l = sAlo[rA * 132 + kt * 8 + c4 + 4];
        uint32_t a3l = sAlo[(rA + 8) * 132 + kt * 8 + c4 + 4];
#pragma unroll
        for (int nt = 0; nt < 16; ++nt) {
            int ntg = wn * 16 + nt;
            uint2 bh = *(const uint2*)&bfrag_hi[kt * 2048 + ntg * 64 + lane * 2];
            uint2 bl = *(const uint2*)&bfrag_lo[kt * 2048 + ntg * 64 + lane * 2];
            mma_bf16(acc[nt], a0h, a1h, a2h, a3h, bh.x, bh.y);
            mma_bf16(acc[nt], a0h, a1h, a2h, a3h, bl.x, bl.y);
            mma_bf16(acc[nt], a0l, a1l, a2l, a3l, bh.x, bh.y);
        }
    }

    // epilogue
#pragma unroll
    for (int nt = 0; nt < 16; ++nt) {
        int ntg = wn * 16 + nt;
        int n0 = ntg * 8 + 2 * c4;
        float2 bv = *(const float2*)&bias[n0];
        int r0 = row0 + rA;
        int r1 = r0 + 8;
        float2 v0 = make_float2(acc[nt][0] + bv.x, acc[nt][1] + bv.y);
        float2 v1 = make_float2(acc[nt][2] + bv.x, acc[nt][3] + bv.y);
        if (resid != nullptr) {
            float2 f0 = *(const float2*)&resid[r0 * CCH + n0];
            float2 f1 = *(const float2*)&resid[r1 * CCH + n0];
            v0.x += f0.x; v0.y += f0.y;
            v1.x += f1.x; v1.y += f1.y;
        }
        *(float2*)&out[r0 * CCH + n0] = v0;
        *(float2*)&out[r1 * CCH + n0] = v1;
    }
}

// ---------------- h-pair: 2 hidden values -> packed fp16 fragment reg ----------------
__device__ __forceinline__ uint32_t hpair16(float4 pa, float4 pb,
                                            float dx, float dy, float dz) {
    float h0 = fmaxf(fmaf(dz, pb.x, fmaf(dy, pa.z, fmaf(dx, pa.x, pb.z))), 0.0f);
    float h1 = fmaxf(fmaf(dz, pb.y, fmaf(dy, pa.w, fmaf(dx, pa.y, pb.w))), 0.0f);
    return f16pack(h0, h1);
}

// ---------------- attention: mma.sync fp16 pe-GEMM + warp-local softmax ----------------
// 8 points/block, warp w owns point w (m16 rows = its 16 neighbors).
// N=256 in 4 chunks of 64; K=256 in 16 k-tiles of 16; single-pass fp16.
// dyn smem (u32): BH[8192] | W1P[1024f] | DL[384f] | ID[128]
#define ATTN_SMEM_U32 9728
#define ATTN_SMEM_B   (ATTN_SMEM_U32 * 4)

__global__ void __launch_bounds__(256) attn_tc_kernel(
    const float* __restrict__ coords,
    const float* __restrict__ pe1_w1, const float* __restrict__ pe1_b1,
    const float* __restrict__ pe1_b2)
{
    extern __shared__ uint32_t dsm[];
    uint32_t* BH  = dsm;
    float*    W1P = (float*)(dsm + 8192);
    float*    DL  = (float*)(dsm + 9216);
    int*      ID  = (int*)(dsm + 9600);

    int t = threadIdx.x;
    int lane = t & 31;
    int w = t >> 5;
    int g = lane >> 2;
    int c4 = lane & 3;

    // w1 repack: pair p -> [wx0,wx1,wy0,wy1] [wz0,wz1,b0,b1]
    {
        int f = 4 * t;
#pragma unroll
        for (int u = 0; u < 4; ++u) {
            int ff = f + u, p = ff >> 3, comp = ff & 7;
            float v;
            if (comp < 6) v = pe1_w1[(comp >> 1) * CCH + 2 * p + (comp & 1)];
            else          v = pe1_b1[2 * p + (comp & 1)];
            W1P[ff] = v;
        }
    }
    if (t < 128) ID[t] = g_idx[blockIdx.x * 128 + t];
    __syncthreads();
    if (t < 128) {
        int nid = ID[t];
        int ip = blockIdx.x * 8 + (t >> 4);
#pragma unroll
        for (int d = 0; d < 3; ++d)
            DL[t * 3 + d] = coords[nid * 3 + d] - coords[ip * 3 + d];
    }
    __syncthreads();

    int rA = w * 16 + g, rB = rA + 8;
    float dxa = DL[rA * 3], dya = DL[rA * 3 + 1], dza = DL[rA * 3 + 2];
    float dxb = DL[rB * 3], dyb = DL[rB * 3 + 1], dzb = DL[rB * 3 + 2];
    int nid0 = ID[rA], nid1 = ID[rB];
    int ipt = blockIdx.x * 8 + w;

    const float4* w1p4 = (const float4*)W1P;

    for (int cc = 0; cc < 4; ++cc) {
        __syncthreads();
        {   // stage this n-chunk's fp16 B fragments (32KB)
            const uint4* sh = (const uint4*)(g_w2f + cc * 8192);
            uint4* dh = (uint4*)BH;
            for (int u = t; u < 2048; u += 256) dh[u] = sh[u];
        }
        __syncthreads();

        float acc[8][4];
#pragma unroll
        for (int nt = 0; nt < 8; ++nt)
#pragma unroll
            for (int r = 0; r < 4; ++r) acc[nt][r] = 0.0f;

#pragma unroll 4
        for (int kt = 0; kt < 16; ++kt) {
            int jp0 = kt * 8 + c4;
            float4 p0a = w1p4[jp0 * 2],     p0b = w1p4[jp0 * 2 + 1];
            float4 p1a = w1p4[jp0 * 2 + 8], p1b = w1p4[jp0 * 2 + 9];
            uint32_t a0 = hpair16(p0a, p0b, dxa, dya, dza);
            uint32_t a1 = hpair16(p0a, p0b, dxb, dyb, dzb);
            uint32_t a2 = hpair16(p1a, p1b, dxa, dya, dza);
            uint32_t a3 = hpair16(p1a, p1b, dxb, dyb, dzb);
            int bbase = kt * 512 + lane * 2;
#pragma unroll
            for (int nt = 0; nt < 8; ++nt) {
                uint2 bh = *(const uint2*)&BH[bbase + nt * 64];
                mma_f16(acc[nt], a0, a1, a2, a3, bh.x, bh.y);
            }
        }

        // epilogue: softmax over 16 rows (in-warp) + weighted g-sum
#pragma unroll
        for (int nt = 0; nt < 8; ++nt) {
            int n0 = cc * 64 + nt * 8 + 2 * c4;
            float2 b2v = *(const float2*)&pe1_b2[n0];
            float2 th  = *(const float2*)&g_theta[ipt * CCH + n0];
            float2 ph0 = *(const float2*)&g_phi[nid0 * CCH + n0];
            float2 ph1 = *(const float2*)&g_phi[nid1 * CCH + n0];

            float pe00 = acc[nt][0] + b2v.x, pe01 = acc[nt][1] + b2v.y;
            float pe10 = acc[nt][2] + b2v.x, pe11 = acc[nt][3] + b2v.y;

            float v00 = (pe00 * (th.x - ph0.x) + pe00) * 0.0625f;
            float v01 = (pe01 * (th.y - ph0.y) + pe01) * 0.0625f;
            float v10 = (pe10 * (th.x - ph1.x) + pe10) * 0.0625f;
            float v11 = (pe11 * (th.y - ph1.y) + pe11) * 0.0625f;

            float m0 = fmaxf(v00, v10), m1 = fmaxf(v01, v11);
#pragma unroll
            for (int off = 4; off <= 16; off <<= 1) {
                m0 = fmaxf(m0, __shfl_xor_sync(0xffffffffu, m0, off));
                m1 = fmaxf(m1, __shfl_xor_sync(0xffffffffu, m1, off));
            }
            float e00 = expf(v00 - m0), e10 = expf(v10 - m0);
            float e01 = expf(v01 - m1), e11 = expf(v11 - m1);
            float s0 = e00 + e10, s1 = e01 + e11;
#pragma unroll
            for (int off = 4; off <= 16; off <<= 1) {
                s0 += __shfl_xor_sync(0xffffffffu, s0, off);
                s1 += __shfl_xor_sync(0xffffffffu, s1, off);
            }
            float2 gv0 = *(const float2*)&g_gv[nid0 * CCH + n0];
            float2 gv1 = *(const float2*)&g_gv[nid1 * CCH + n0];
            float y0 = e00 * gv0.x + e10 * gv1.x;
            float y1 = e01 * gv0.y + e11 * gv1.y;
#pragma unroll
            for (int off = 4; off <= 16; off <<= 1) {
                y0 += __shfl_xor_sync(0xffffffffu, y0, off);
                y1 += __shfl_xor_sync(0xffffffffu, y1, off);
            }
            if (g == 0)
                *(float2*)&g_y[ipt * CCH + n0] = make_float2(y0 / s0, y1 / s1);
        }
    }
}

// ---------------- launch ----------------
extern "C" void kernel_launch(void* const* d_in, const int* in_sizes, int n_in,
                              void* d_out, int out_size) {
    const float* coords  = (const float*)d_in[0];
    const float* feats   = (const float*)d_in[1];
    const float* theta_w = (const float*)d_in[2];
    const float* theta_b = (const float*)d_in[3];
    const float* phi_w   = (const float*)d_in[4];
    const float* phi_b   = (const float*)d_in[5];
    const float* g_w     = (const float*)d_in[6];
    const float* g_b     = (const float*)d_in[7];
    const float* pe1_w1  = (const float*)d_in[8];
    const float* pe1_b1  = (const float*)d_in[9];
    const float* pe1_w2  = (const float*)d_in[10];
    const float* pe1_b2  = (const float*)d_in[11];
    const float* W_w     = (const float*)d_in[12];
    const float* W_b     = (const float*)d_in[13];
    float* out = (float*)d_out;

    float *p_theta, *p_phi, *p_g, *p_y;
    cudaGetSymbolAddress((void**)&p_theta, g_theta);
    cudaGetSymbolAddress((void**)&p_phi,   g_phi);
    cudaGetSymbolAddress((void**)&p_g,     g_gv);
    cudaGetSymbolAddress((void**)&p_y,     g_y);

    cudaFuncSetAttribute(attn_tc_kernel,
                         cudaFuncAttributeMaxDynamicSharedMemorySize, ATTN_SMEM_B);
    cudaFuncSetAttribute(linear_tc_kernel,
                         cudaFuncAttributeMaxDynamicSharedMemorySize, LIN_SMEM);

    prep_kernel<<<(NPTS + 255) / 256, 256>>>(coords);
    prep_w2_frag<<<128, 256>>>(pe1_w2);
    prep_wf_frag<<<512, 256>>>(theta_w, phi_w, g_w, W_w);
    knn_kernel<<<NPTS / 8, 256>>>();

    // theta / phi / g in one tensor-core launch
    linear_tc_kernel<<<dim3(NPTS / 64, 3), 256, LIN_SMEM>>>(
        feats, 0, theta_b, phi_b, g_b, p_theta, p_phi, p_g, nullptr);

    attn_tc_kernel<<<NPTS / 8, 256, ATTN_SMEM_B>>>(coords, pe1_w1, pe1_b1, pe1_b2);

    // final: out = y @ W_w + W_b + feats
    linear_tc_kernel<<<dim3(NPTS / 64, 1), 256, LIN_SMEM>>>(
        p_y, 3, W_b, W_b, W_b, out, out, out, feats);
}

// round 8
// speedup vs baseline: 6.5886x; 1.0455x over previous
#include <cuda_runtime.h>
#include <cuda_bf16.h>
#include <math_constants.h>
#include <cstdint>

#define NPTS 8192
#define CCH  256
#define KNB  16

typedef unsigned long long ull;

// ---------------- pack helpers ----------------
// bf16x2: bits[15:0] = lo arg, bits[31:16] = hi arg
__device__ __forceinline__ uint32_t bf2pack(float lo, float hi) {
    uint32_t r;
    asm("cvt.rn.bf16x2.f32 %0, %1, %2;" : "=r"(r) : "f"(hi), "f"(lo));
    return r;
}
__device__ __forceinline__ float bflo_f(uint32_t u) { return __uint_as_float(u << 16); }
__device__ __forceinline__ float bfhi_f(uint32_t u) { return __uint_as_float(u & 0xffff0000u); }
// f16x2: bits[15:0] = lo arg, bits[31:16] = hi arg
__device__ __forceinline__ uint32_t f16pack(float lo, float hi) {
    uint32_t r;
    asm("cvt.rn.f16x2.f32 %0, %1, %2;" : "=r"(r) : "f"(hi), "f"(lo));
    return r;
}

// mma.sync m16n8k16 row.col f32 accum (baseline sm_80 PTX)
__device__ __forceinline__ void mma_bf16(float* d,
                                         uint32_t a0, uint32_t a1, uint32_t a2, uint32_t a3,
                                         uint32_t b0, uint32_t b1) {
    asm volatile(
        "mma.sync.aligned.m16n8k16.row.col.f32.bf16.bf16.f32 "
        "{%0,%1,%2,%3}, {%4,%5,%6,%7}, {%8,%9}, {%0,%1,%2,%3};"
        : "+f"(d[0]), "+f"(d[1]), "+f"(d[2]), "+f"(d[3])
        : "r"(a0), "r"(a1), "r"(a2), "r"(a3), "r"(b0), "r"(b1));
}
__device__ __forceinline__ void mma_f16(float* d,
                                        uint32_t a0, uint32_t a1, uint32_t a2, uint32_t a3,
                                        uint32_t b0, uint32_t b1) {
    asm volatile(
        "mma.sync.aligned.m16n8k16.row.col.f32.f16.f16.f32 "
        "{%0,%1,%2,%3}, {%4,%5,%6,%7}, {%8,%9}, {%0,%1,%2,%3};"
        : "+f"(d[0]), "+f"(d[1]), "+f"(d[2]), "+f"(d[3])
        : "r"(a0), "r"(a1), "r"(a2), "r"(a3), "r"(b0), "r"(b1));
}

// ---------------- scratch (device globals; no allocation APIs) ----------------
__device__ float4 g_pts[NPTS];
__device__ int    g_idx[NPTS * KNB];
__device__ float  g_theta[NPTS * CCH];
__device__ float  g_phi[NPTS * CCH];
__device__ float  g_gv[NPTS * CCH];
__device__ float  g_y[NPTS * CCH];
// attn w2 -> fp16 B fragments
__device__ uint32_t g_w2f[32768];
// linear weights (theta, phi, g, W) -> bf16 hi/lo B fragments
__device__ uint32_t g_wf_hi[4 * 32768];
__device__ uint32_t g_wf_lo[4 * 32768];

// ---------------- prep: pack coords + squared norm ----------------
__global__ void prep_kernel(const float* __restrict__ coords) {
    int i = blockIdx.x * blockDim.x + threadIdx.x;
    if (i < NPTS) {
        float x = coords[3 * i + 0];
        float y = coords[3 * i + 1];
        float z = coords[3 * i + 2];
        g_pts[i] = make_float4(x, y, z, x * x + y * y + z * z);
    }
}

// ---------------- prep: w2 -> fp16 B fragments ----------------
__global__ void prep_w2_frag(const float* __restrict__ w2) {
    int tid = blockIdx.x * 256 + threadIdx.x;           // 0..32767
    int reg = tid & 1;
    int ln  = (tid >> 1) & 31;
    int nt  = (tid >> 6) & 7;
    int kt  = (tid >> 9) & 15;
    int cc  = (tid >> 13) & 3;
    int n = cc * 64 + nt * 8 + (ln >> 2);
    int k = kt * 16 + 2 * (ln & 3) + reg * 8;
    float v0 = w2[k * CCH + n];
    float v1 = w2[(k + 1) * CCH + n];
    g_w2f[tid] = f16pack(v0, v1);
}

// ---------------- prep: 4 linear weights -> bf16 hi/lo B fragments ----------------
__global__ void prep_wf_frag(const float* __restrict__ w0, const float* __restrict__ w1,
                             const float* __restrict__ w2, const float* __restrict__ w3) {
    int tid = blockIdx.x * 256 + threadIdx.x;           // 0..131071
    int m = tid >> 15;
    int r = tid & 32767;
    int reg = r & 1;
    int ln  = (r >> 1) & 31;
    int nt  = (r >> 6) & 31;
    int kt  = (r >> 11) & 15;
    int n = nt * 8 + (ln >> 2);
    int k = kt * 16 + 2 * (ln & 3) + reg * 8;
    const float* W = (m == 0) ? w0 : (m == 1) ? w1 : (m == 2) ? w2 : w3;
    float v0 = W[k * CCH + n];
    float v1 = W[(k + 1) * CCH + n];
    uint32_t hi = bf2pack(v0, v1);
    g_wf_hi[tid] = hi;
    g_wf_lo[tid] = bf2pack(v0 - bflo_f(hi), v1 - bfhi_f(hi));
}

// ---------------- KNN: warp/query, 4-wide batched filter + rare exact insert ----------------
__global__ __launch_bounds__(256) void knn_kernel() {
    __shared__ float4 s_pts[1024];

    int warp = threadIdx.x >> 5;
    int lane = threadIdx.x & 31;
    int q = blockIdx.x * 8 + warp;

    float4 qp = g_pts[q];

    ull slot = ~0ull;             // lane s (<16) holds s-th smallest key
    ull thr  = ~0ull;             // 16th-best key (all lanes)
    float thrf = CUDART_INF_F;    // float d2 of 16th-best (filter threshold)

    for (int t0 = 0; t0 < NPTS; t0 += 1024) {
        for (int r = threadIdx.x; r < 1024; r += 256) s_pts[r] = g_pts[t0 + r];
        __syncthreads();

#pragma unroll 1
        for (int b = 0; b < 8; ++b) {
            int j0 = b * 128 + lane;
            float4 p0 = s_pts[j0];
            float4 p1 = s_pts[j0 + 32];
            float4 p2 = s_pts[j0 + 64];
            float4 p3 = s_pts[j0 + 96];
            float dot0 = qp.x * p0.x + qp.y * p0.y + qp.z * p0.z;
            float dot1 = qp.x * p1.x + qp.y * p1.y + qp.z * p1.z;
            float dot2 = qp.x * p2.x + qp.y * p2.y + qp.z * p2.z;
            float dot3 = qp.x * p3.x + qp.y * p3.y + qp.z * p3.z;
            float d0 = (qp.w + p0.w) - 2.0f * dot0;
            float d1 = (qp.w + p1.w) - 2.0f * dot1;
            float d2 = (qp.w + p2.w) - 2.0f * dot2;
            float d3 = (qp.w + p3.w) - 2.0f * dot3;
            bool pr0 = d0 <= thrf;
            bool pr1 = d1 <= thrf;
            bool pr2 = d2 <= thrf;
            bool pr3 = d3 <= thrf;

            unsigned any = __ballot_sync(0xffffffffu, pr0 | pr1 | pr2 | pr3);
            if (any) {
                float dv[4] = {d0, d1, d2, d3};
                bool  pv[4] = {pr0, pr1, pr2, pr3};
#pragma unroll
                for (int u = 0; u < 4; ++u) {
                    ull key = ~0ull;
                    if (pv[u]) {
                        unsigned uu = __float_as_uint(dv[u]);
                        uu = ((int)uu < 0) ? ~uu : (uu | 0x80000000u);
                        key = ((ull)uu << 32) | (unsigned)(t0 + j0 + u * 32);
                    }
                    unsigned mask = __ballot_sync(0xffffffffu, key < thr);
                    while (mask) {
                        int src = __ffs(mask) - 1;
                        mask &= mask - 1;
                        ull cand = __shfl_sync(0xffffffffu, key, src);
                        if (cand < thr) {
                            unsigned lt = __ballot_sync(0xffffffffu, (lane < 16) && (slot < cand));
                            int pos = __popc(lt);
                            ull prev = __shfl_up_sync(0xffffffffu, slot, 1);
                            if (lane >= pos && lane < 16) slot = (lane == pos) ? cand : prev;
                            thr = __shfl_sync(0xffffffffu, slot, 15);
                        }
                    }
                }
                // refresh float threshold from the 16th-best key
                unsigned hb = (unsigned)(thr >> 32);
                unsigned ub = (hb & 0x80000000u) ? (hb & 0x7fffffffu) : ~hb;
                thrf = __uint_as_float(ub);
            }
        }
        __syncthreads();
    }

    if (lane < 16) g_idx[q * KNB + lane] = (int)(unsigned)(slot & 0xffffffffu);
}

// ---------------- tensor-core linear: out = A @ W + b (+ resid), bf16x3 ----------------
#define LIN_SMEM (2 * 64 * 132 * 4)

__global__ void __launch_bounds__(256, 2) linear_tc_kernel(
    const float* __restrict__ A, int m0,
    const float* __restrict__ b0_, const float* __restrict__ b1_, const float* __restrict__ b2_,
    float* __restrict__ o0, float* __restrict__ o1, float* __restrict__ o2,
    const float* __restrict__ resid)
{
    extern __shared__ uint32_t dsm[];
    uint32_t* sAhi = dsm;
    uint32_t* sAlo = dsm + 64 * 132;

    int mat = m0 + blockIdx.y;
    const float* bias = (blockIdx.y == 0) ? b0_ : (blockIdx.y == 1) ? b1_ : b2_;
    float*       out  = (blockIdx.y == 0) ? o0 : (blockIdx.y == 1) ? o1 : o2;

    int t = threadIdx.x;
    int lane = t & 31;
    int w = t >> 5;
    int wm = w & 3;
    int wn = w >> 2;
    int g = lane >> 2;
    int c4 = lane & 3;
    int row0 = blockIdx.x * 64;

    for (int idx = t; idx < 4096; idx += 256) {
        int row = idx >> 6;
        int qq = idx & 63;
        float4 v = *(const float4*)&A[(row0 + row) * CCH + qq * 4];
        uint32_t h0 = bf2pack(v.x, v.y);
        uint32_t h1 = bf2pack(v.z, v.w);
        uint32_t l0 = bf2pack(v.x - bflo_f(h0), v.y - bfhi_f(h0));
        uint32_t l1 = bf2pack(v.z - bflo_f(h1), v.w - bfhi_f(h1));
        *(uint2*)&sAhi[row * 132 + qq * 2] = make_uint2(h0, h1);
        *(uint2*)&sAlo[row * 132 + qq * 2] = make_uint2(l0, l1);
    }
    __syncthreads();

    float acc[16][4];
#pragma unroll
    for (int nt = 0; nt < 16; ++nt)
#pragma unroll
        for (int r = 0; r < 4; ++r) acc[nt][r] = 0.0f;

    int rA = wm * 16 + g;
    const uint32_t* bfrag_hi = g_wf_hi + mat * 32768;
    const uint32_t* bfrag_lo = g_wf_lo + mat * 32768;

#pragma unroll 2
    for (int kt = 0; kt < 16; ++kt) {
        uint32_t a0h = sAhi[rA * 132 + kt * 8 + c4];
        uint32_t a1h = sAhi[(rA + 8) * 132 + kt * 8 + c4];
        uint32_t a2h = sAhi[rA * 132 + kt * 8 + c4 + 4];
        uint32_t a3h = sAhi[(rA + 8) * 132 + kt * 8 + c4 + 4];
        uint32_t a0l = sAlo[rA * 132 + kt * 8 + c4];
        uint32_t a1l = sAlo[(rA + 8) * 132 + kt * 8 + c4];
        uint32_t a2l = sAlo[rA * 132 + kt * 8 + c4 + 4];
        uint32_t a3l = sAlo[(rA + 8) * 132 + kt * 8 + c4 + 4];
#pragma unroll
        for (int nt = 0; nt < 16; ++nt) {
            int ntg = wn * 16 + nt;
            uint2 bh = *(const uint2*)&bfrag_hi[kt * 2048 + ntg * 64 + lane * 2];
            uint2 bl = *(const uint2*)&bfrag_lo[kt * 2048 + ntg * 64 + lane * 2];
            mma_bf16(acc[nt], a0h, a1h, a2h, a3h, bh.x, bh.y);
            mma_bf16(acc[nt], a0h, a1h, a2h, a3h, bl.x, bl.y);
            mma_bf16(acc[nt], a0l, a1l, a2l, a3l, bh.x, bh.y);
        }
    }

#pragma unroll
    for (int nt = 0; nt < 16; ++nt) {
        int ntg = wn * 16 + nt;
        int n0 = ntg * 8 + 2 * c4;
        float2 bv = *(const float2*)&bias[n0];
        int r0 = row0 + rA;
        int r1 = r0 + 8;
        float2 v0 = make_float2(acc[nt][0] + bv.x, acc[nt][1] + bv.y);
        float2 v1 = make_float2(acc[nt][2] + bv.x, acc[nt][3] + bv.y);
        if (resid != nullptr) {
            float2 f0 = *(const float2*)&resid[r0 * CCH + n0];
            float2 f1 = *(const float2*)&resid[r1 * CCH + n0];
            v0.x += f0.x; v0.y += f0.y;
            v1.x += f1.x; v1.y += f1.y;
        }
        *(float2*)&out[r0 * CCH + n0] = v0;
        *(float2*)&out[r1 * CCH + n0] = v1;
    }
}

// ---------------- h-pair: 2 hidden values -> packed fp16 fragment reg ----------------
__device__ __forceinline__ uint32_t hpair16(float4 pa, float4 pb,
                                            float dx, float dy, float dz) {
    float h0 = fmaxf(fmaf(dz, pb.x, fmaf(dy, pa.z, fmaf(dx, pa.x, pb.z))), 0.0f);
    float h1 = fmaxf(fmaf(dz, pb.y, fmaf(dy, pa.w, fmaf(dx, pa.y, pb.w))), 0.0f);
    return f16pack(h0, h1);
}

// ---------------- attention: mma.sync fp16 pe-GEMM + warp-local softmax ----------------
#define ATTN_SMEM_U32 9728
#define ATTN_SMEM_B   (ATTN_SMEM_U32 * 4)

__global__ void __launch_bounds__(256) attn_tc_kernel(
    const float* __restrict__ coords,
    const float* __restrict__ pe1_w1, const float* __restrict__ pe1_b1,
    const float* __restrict__ pe1_b2)
{
    extern __shared__ uint32_t dsm[];
    uint32_t* BH  = dsm;
    float*    W1P = (float*)(dsm + 8192);
    float*    DL  = (float*)(dsm + 9216);
    int*      ID  = (int*)(dsm + 9600);

    int t = threadIdx.x;
    int lane = t & 31;
    int w = t >> 5;
    int g = lane >> 2;
    int c4 = lane & 3;

    {
        int f = 4 * t;
#pragma unroll
        for (int u = 0; u < 4; ++u) {
            int ff = f + u, p = ff >> 3, comp = ff & 7;
            float v;
            if (comp < 6) v = pe1_w1[(comp >> 1) * CCH + 2 * p + (comp & 1)];
            else          v = pe1_b1[2 * p + (comp & 1)];
            W1P[ff] = v;
        }
    }
    if (t < 128) ID[t] = g_idx[blockIdx.x * 128 + t];
    __syncthreads();
    if (t < 128) {
        int nid = ID[t];
        int ip = blockIdx.x * 8 + (t >> 4);
#pragma unroll
        for (int d = 0; d < 3; ++d)
            DL[t * 3 + d] = coords[nid * 3 + d] - coords[ip * 3 + d];
    }
    __syncthreads();

    int rA = w * 16 + g, rB = rA + 8;
    float dxa = DL[rA * 3], dya = DL[rA * 3 + 1], dza = DL[rA * 3 + 2];
    float dxb = DL[rB * 3], dyb = DL[rB * 3 + 1], dzb = DL[rB * 3 + 2];
    int nid0 = ID[rA], nid1 = ID[rB];
    int ipt = blockIdx.x * 8 + w;

    const float4* w1p4 = (const float4*)W1P;

    for (int cc = 0; cc < 4; ++cc) {
        __syncthreads();
        {
            const uint4* sh = (const uint4*)(g_w2f + cc * 8192);
            uint4* dh = (uint4*)BH;
            for (int u = t; u < 2048; u += 256) dh[u] = sh[u];
        }
        __syncthreads();

        float acc[8][4];
#pragma unroll
        for (int nt = 0; nt < 8; ++nt)
#pragma unroll
            for (int r = 0; r < 4; ++r) acc[nt][r] = 0.0f;

#pragma unroll 4
        for (int kt = 0; kt < 16; ++kt) {
            int jp0 = kt * 8 + c4;
            float4 p0a = w1p4[jp0 * 2],     p0b = w1p4[jp0 * 2 + 1];
            float4 p1a = w1p4[jp0 * 2 + 8], p1b = w1p4[jp0 * 2 + 9];
            uint32_t a0 = hpair16(p0a, p0b, dxa, dya, dza);
            uint32_t a1 = hpair16(p0a, p0b, dxb, dyb, dzb);
            uint32_t a2 = hpair16(p1a, p1b, dxa, dya, dza);
            uint32_t a3 = hpair16(p1a, p1b, dxb, dyb, dzb);
            int bbase = kt * 512 + lane * 2;
#pragma unroll
            for (int nt = 0; nt < 8; ++nt) {
                uint2 bh = *(const uint2*)&BH[bbase + nt * 64];
                mma_f16(acc[nt], a0, a1, a2, a3, bh.x, bh.y);
            }
        }

#pragma unroll
        for (int nt = 0; nt < 8; ++nt) {
            int n0 = cc * 64 + nt * 8 + 2 * c4;
            float2 b2v = *(const float2*)&pe1_b2[n0];
            float2 th  = *(const float2*)&g_theta[ipt * CCH + n0];
            float2 ph0 = *(const float2*)&g_phi[nid0 * CCH + n0];
            float2 ph1 = *(const float2*)&g_phi[nid1 * CCH + n0];

            float pe00 = acc[nt][0] + b2v.x, pe01 = acc[nt][1] + b2v.y;
            float pe10 = acc[nt][2] + b2v.x, pe11 = acc[nt][3] + b2v.y;

            float v00 = (pe00 * (th.x - ph0.x) + pe00) * 0.0625f;
            float v01 = (pe01 * (th.y - ph0.y) + pe01) * 0.0625f;
            float v10 = (pe10 * (th.x - ph1.x) + pe10) * 0.0625f;
            float v11 = (pe11 * (th.y - ph1.y) + pe11) * 0.0625f;

            float m0 = fmaxf(v00, v10), m1 = fmaxf(v01, v11);
#pragma unroll
            for (int off = 4; off <= 16; off <<= 1) {
                m0 = fmaxf(m0, __shfl_xor_sync(0xffffffffu, m0, off));
                m1 = fmaxf(m1, __shfl_xor_sync(0xffffffffu, m1, off));
            }
            float e00 = expf(v00 - m0), e10 = expf(v10 - m0);
            float e01 = expf(v01 - m1), e11 = expf(v11 - m1);
            float s0 = e00 + e10, s1 = e01 + e11;
#pragma unroll
            for (int off = 4; off <= 16; off <<= 1) {
                s0 += __shfl_xor_sync(0xffffffffu, s0, off);
                s1 += __shfl_xor_sync(0xffffffffu, s1, off);
            }
            float2 gv0 = *(const float2*)&g_gv[nid0 * CCH + n0];
            float2 gv1 = *(const float2*)&g_gv[nid1 * CCH + n0];
            float y0 = e00 * gv0.x + e10 * gv1.x;
            float y1 = e01 * gv0.y + e11 * gv1.y;
#pragma unroll
            for (int off = 4; off <= 16; off <<= 1) {
                y0 += __shfl_xor_sync(0xffffffffu, y0, off);
                y1 += __shfl_xor_sync(0xffffffffu, y1, off);
            }
            if (g == 0)
                *(float2*)&g_y[ipt * CCH + n0] = make_float2(y0 / s0, y1 / s1);
        }
    }
}

// ---------------- launch ----------------
extern "C" void kernel_launch(void* const* d_in, const int* in_sizes, int n_in,
                              void* d_out, int out_size) {
    const float* coords  = (const float*)d_in[0];
    const float* feats   = (const float*)d_in[1];
    const float* theta_w = (const float*)d_in[2];
    const float* theta_b = (const float*)d_in[3];
    const float* phi_w   = (const float*)d_in[4];
    const float* phi_b   = (const float*)d_in[5];
    const float* g_w     = (const float*)d_in[6];
    const float* g_b     = (const float*)d_in[7];
    const float* pe1_w1  = (const float*)d_in[8];
    const float* pe1_b1  = (const float*)d_in[9];
    const float* pe1_w2  = (const float*)d_in[10];
    const float* pe1_b2  = (const float*)d_in[11];
    const float* W_w     = (const float*)d_in[12];
    const float* W_b     = (const float*)d_in[13];
    float* out = (float*)d_out;

    float *p_theta, *p_phi, *p_g, *p_y;
    cudaGetSymbolAddress((void**)&p_theta, g_theta);
    cudaGetSymbolAddress((void**)&p_phi,   g_phi);
    cudaGetSymbolAddress((void**)&p_g,     g_gv);
    cudaGetSymbolAddress((void**)&p_y,     g_y);

    cudaFuncSetAttribute(attn_tc_kernel,
                         cudaFuncAttributeMaxDynamicSharedMemorySize, ATTN_SMEM_B);
    cudaFuncSetAttribute(linear_tc_kernel,
                         cudaFuncAttributeMaxDynamicSharedMemorySize, LIN_SMEM);

    prep_kernel<<<(NPTS + 255) / 256, 256>>>(coords);
    prep_w2_frag<<<128, 256>>>(pe1_w2);
    prep_wf_frag<<<512, 256>>>(theta_w, phi_w, g_w, W_w);
    knn_kernel<<<NPTS / 8, 256>>>();

    linear_tc_kernel<<<dim3(NPTS / 64, 3), 256, LIN_SMEM>>>(
        feats, 0, theta_b, phi_b, g_b, p_theta, p_phi, p_g, nullptr);

    attn_tc_kernel<<<NPTS / 8, 256, ATTN_SMEM_B>>>(coords, pe1_w1, pe1_b1, pe1_b2);

    linear_tc_kernel<<<dim3(NPTS / 64, 1), 256, LIN_SMEM>>>(
        p_y, 3, W_b, W_b, W_b, out, out, out, feats);
}

// round 11
// speedup vs baseline: 7.3988x; 1.1230x over previous
#include <cuda_runtime.h>
#include <cuda_bf16.h>
#include <math_constants.h>
#include <cstdint>

#define NPTS 8192
#define CCH  256
#define KNB  16

typedef unsigned long long ull;

// ---------------- pack helpers ----------------
__device__ __forceinline__ uint32_t bf2pack(float lo, float hi) {
    uint32_t r;
    asm("cvt.rn.bf16x2.f32 %0, %1, %2;" : "=r"(r) : "f"(hi), "f"(lo));
    return r;
}
__device__ __forceinline__ float bflo_f(uint32_t u) { return __uint_as_float(u << 16); }
__device__ __forceinline__ float bfhi_f(uint32_t u) { return __uint_as_float(u & 0xffff0000u); }
__device__ __forceinline__ uint32_t f16pack(float lo, float hi) {
    uint32_t r;
    asm("cvt.rn.f16x2.f32 %0, %1, %2;" : "=r"(r) : "f"(hi), "f"(lo));
    return r;
}

// mma.sync m16n8k16 row.col f32 accum (baseline sm_80 PTX)
__device__ __forceinline__ void mma_bf16(float* d,
                                         uint32_t a0, uint32_t a1, uint32_t a2, uint32_t a3,
                                         uint32_t b0, uint32_t b1) {
    asm volatile(
        "mma.sync.aligned.m16n8k16.row.col.f32.bf16.bf16.f32 "
        "{%0,%1,%2,%3}, {%4,%5,%6,%7}, {%8,%9}, {%0,%1,%2,%3};"
        : "+f"(d[0]), "+f"(d[1]), "+f"(d[2]), "+f"(d[3])
        : "r"(a0), "r"(a1), "r"(a2), "r"(a3), "r"(b0), "r"(b1));
}
__device__ __forceinline__ void mma_f16(float* d,
                                        uint32_t a0, uint32_t a1, uint32_t a2, uint32_t a3,
                                        uint32_t b0, uint32_t b1) {
    asm volatile(
        "mma.sync.aligned.m16n8k16.row.col.f32.f16.f16.f32 "
        "{%0,%1,%2,%3}, {%4,%5,%6,%7}, {%8,%9}, {%0,%1,%2,%3};"
        : "+f"(d[0]), "+f"(d[1]), "+f"(d[2]), "+f"(d[3])
        : "r"(a0), "r"(a1), "r"(a2), "r"(a3), "r"(b0), "r"(b1));
}

// ---------------- scratch (device globals; no allocation APIs) ----------------
__device__ int    g_idx[NPTS * KNB];
__device__ float  g_theta[NPTS * CCH];
__device__ float  g_phi[NPTS * CCH];
__device__ float  g_gv[NPTS * CCH];
__device__ float  g_y[NPTS * CCH];
__device__ uint32_t g_w2f[32768];
__device__ uint32_t g_wf_hi[4 * 32768];
__device__ uint32_t g_wf_lo[4 * 32768];
// grid-KNN scratch
__device__ float4 g_spts[NPTS];     // cell-sorted points (x,y,z,|p|^2)
__device__ int    g_sid[NPTS];      // original indices
__device__ int    g_cellcnt[512];   // histogram / scatter cursor
__device__ int    g_cellstart[513]; // exclusive prefix

#define GRID_DIM 8
#define CELL_H   12.5f
#define INV_H    0.08f

__device__ __forceinline__ int cell_coord(float v) {
    int c = (int)(v * INV_H);
    return min(GRID_DIM - 1, max(0, c));
}

// ---------------- grid build ----------------
__global__ void hist_kernel(const float* __restrict__ coords) {
    int i = blockIdx.x * blockDim.x + threadIdx.x;
    if (i < NPTS) {
        int cx = cell_coord(coords[3 * i + 0]);
        int cy = cell_coord(coords[3 * i + 1]);
        int cz = cell_coord(coords[3 * i + 2]);
        atomicAdd(&g_cellcnt[(cz * GRID_DIM + cy) * GRID_DIM + cx], 1);
    }
}

__global__ void scan_kernel() {   // 1 block, 512 threads
    __shared__ int tmp[512];
    int t = threadIdx.x;
    tmp[t] = g_cellcnt[t];
    __syncthreads();
    for (int off = 1; off < 512; off <<= 1) {
        int a = (t >= off) ? tmp[t - off] : 0;
        __syncthreads();
        tmp[t] += a;
        __syncthreads();
    }
    g_cellstart[t + 1] = tmp[t];
    if (t == 0) g_cellstart[0] = 0;
    g_cellcnt[t] = 0;             // reset cursor for scatter
}

__global__ void scatter_kernel(const float* __restrict__ coords) {
    int i = blockIdx.x * blockDim.x + threadIdx.x;
    if (i < NPTS) {
        float x = coords[3 * i + 0];
        float y = coords[3 * i + 1];
        float z = coords[3 * i + 2];
        int cell = (cell_coord(z) * GRID_DIM + cell_coord(y)) * GRID_DIM + cell_coord(x);
        int pos = g_cellstart[cell] + atomicAdd(&g_cellcnt[cell], 1);
        g_spts[pos] = make_float4(x, y, z, x * x + y * y + z * z);
        g_sid[pos] = i;
    }
}

// ---------------- grid KNN: warp per query, expanding shells, exact top-16 ----------------
__global__ __launch_bounds__(256) void knn_grid_kernel(const float* __restrict__ coords) {
    int warp = threadIdx.x >> 5;
    int lane = threadIdx.x & 31;
    int q = blockIdx.x * 8 + warp;

    float qx = coords[3 * q + 0];
    float qy = coords[3 * q + 1];
    float qz = coords[3 * q + 2];
    float qw = qx * qx + qy * qy + qz * qz;
    int cx = cell_coord(qx), cy = cell_coord(qy), cz = cell_coord(qz);

    ull slot = ~0ull;             // lane s (<16) holds s-th smallest (d2bits, origidx)
    ull thr  = ~0ull;
    float thrf = CUDART_INF_F;

    int px0 = 1, px1 = 0, py0 = 1, py1 = 0, pz0 = 1, pz1 = 0;  // empty prev box

    for (int s = 1; s <= GRID_DIM; ++s) {
        int x0 = max(cx - s, 0), x1 = min(cx + s, GRID_DIM - 1);
        int y0 = max(cy - s, 0), y1 = min(cy + s, GRID_DIM - 1);
        int z0 = max(cz - s, 0), z1 = min(cz + s, GRID_DIM - 1);

        for (int zz = z0; zz <= z1; ++zz)
        for (int yy = y0; yy <= y1; ++yy)
        for (int xx = x0; xx <= x1; ++xx) {
            if (zz >= pz0 && zz <= pz1 && yy >= py0 && yy <= py1 &&
                xx >= px0 && xx <= px1) continue;   // already scanned
            int cell = (zz * GRID_DIM + yy) * GRID_DIM + xx;
            int st = g_cellstart[cell];
            int en = g_cellstart[cell + 1];
            for (int jj = st; jj < en; jj += 32) {
                int id = jj + lane;
                ull key = ~0ull;
                if (id < en) {
                    float4 p = g_spts[id];
                    float dot = qx * p.x + qy * p.y + qz * p.z;
                    float d2 = (qw + p.w) - 2.0f * dot;   // same formula as reference
                    if (d2 <= thrf) {
                        unsigned u = __float_as_uint(d2);
                        u = ((int)u < 0) ? ~u : (u | 0x80000000u);
                        key = ((ull)u << 32) | (unsigned)g_sid[id];
                    }
                }
                unsigned mask = __ballot_sync(0xffffffffu, key < thr);
                while (mask) {
                    int src = __ffs(mask) - 1;
                    mask &= mask - 1;
                    ull cand = __shfl_sync(0xffffffffu, key, src);
                    if (cand < thr) {
                        unsigned lt = __ballot_sync(0xffffffffu, (lane < 16) && (slot < cand));
                        int pos = __popc(lt);
                        ull prev = __shfl_up_sync(0xffffffffu, slot, 1);
                        if (lane >= pos && lane < 16) slot = (lane == pos) ? cand : prev;
                        thr = __shfl_sync(0xffffffffu, slot, 15);
                    }
                }
            }
            // refresh float threshold (NaN-guard the ~0 sentinel -> +inf)
            unsigned hb = (unsigned)(thr >> 32);
            thrf = (hb == 0xffffffffu) ? CUDART_INF_F
                 : ((hb & 0x80000000u) ? __uint_as_float(hb & 0x7fffffffu)
                                       : __uint_as_float(~hb));
        }

        bool covered = (x0 == 0 && x1 == GRID_DIM - 1 &&
                        y0 == 0 && y1 == GRID_DIM - 1 &&
                        z0 == 0 && z1 == GRID_DIM - 1);
        float fxl = (x0 > 0) ? qx - x0 * CELL_H : CUDART_INF_F;
        float fxh = (x1 < GRID_DIM - 1) ? (x1 + 1) * CELL_H - qx : CUDART_INF_F;
        float fyl = (y0 > 0) ? qy - y0 * CELL_H : CUDART_INF_F;
        float fyh = (y1 < GRID_DIM - 1) ? (y1 + 1) * CELL_H - qy : CUDART_INF_F;
        float fzl = (z0 > 0) ? qz - z0 * CELL_H : CUDART_INF_F;
        float fzh = (z1 < GRID_DIM - 1) ? (z1 + 1) * CELL_H - qz : CUDART_INF_F;
        float md = fminf(fminf(fminf(fxl, fxh), fminf(fyl, fyh)), fminf(fzl, fzh));
        if (covered || md * md > thrf + 0.5f) break;

        px0 = x0; px1 = x1; py0 = y0; py1 = y1; pz0 = z0; pz1 = z1;
    }

    if (lane < 16) g_idx[q * KNB + lane] = (int)(unsigned)(slot & 0xffffffffu);
}

// ---------------- prep: w2 -> fp16 B fragments ----------------
__global__ void prep_w2_frag(const float* __restrict__ w2) {
    int tid = blockIdx.x * 256 + threadIdx.x;
    int reg = tid & 1;
    int ln  = (tid >> 1) & 31;
    int nt  = (tid >> 6) & 7;
    int kt  = (tid >> 9) & 15;
    int cc  = (tid >> 13) & 3;
    int n = cc * 64 + nt * 8 + (ln >> 2);
    int k = kt * 16 + 2 * (ln & 3) + reg * 8;
    float v0 = w2[k * CCH + n];
    float v1 = w2[(k + 1) * CCH + n];
    g_w2f[tid] = f16pack(v0, v1);
}

// ---------------- prep: 4 linear weights -> bf16 hi/lo B fragments ----------------
__global__ void prep_wf_frag(const float* __restrict__ w0, const float* __restrict__ w1,
                             const float* __restrict__ w2, const float* __restrict__ w3) {
    int tid = blockIdx.x * 256 + threadIdx.x;
    int m = tid >> 15;
    int r = tid & 32767;
    int reg = r & 1;
    int ln  = (r >> 1) & 31;
    int nt  = (r >> 6) & 31;
    int kt  = (r >> 11) & 15;
    int n = nt * 8 + (ln >> 2);
    int k = kt * 16 + 2 * (ln & 3) + reg * 8;
    const float* W = (m == 0) ? w0 : (m == 1) ? w1 : (m == 2) ? w2 : w3;
    float v0 = W[k * CCH + n];
    float v1 = W[(k + 1) * CCH + n];
    uint32_t hi = bf2pack(v0, v1);
    g_wf_hi[tid] = hi;
    g_wf_lo[tid] = bf2pack(v0 - bflo_f(hi), v1 - bfhi_f(hi));
}

// ---------------- tensor-core linear: out = A @ W + b (+ resid), bf16x3 ----------------
#define LIN_SMEM (2 * 64 * 132 * 4)

__global__ void __launch_bounds__(256, 2) linear_tc_kernel(
    const float* __restrict__ A, int m0,
    const float* __restrict__ b0_, const float* __restrict__ b1_, const float* __restrict__ b2_,
    float* __restrict__ o0, float* __restrict__ o1, float* __restrict__ o2,
    const float* __restrict__ resid)
{
    extern __shared__ uint32_t dsm[];
    uint32_t* sAhi = dsm;
    uint32_t* sAlo = dsm + 64 * 132;

    int mat = m0 + blockIdx.y;
    const float* bias = (blockIdx.y == 0) ? b0_ : (blockIdx.y == 1) ? b1_ : b2_;
    float*       out  = (blockIdx.y == 0) ? o0 : (blockIdx.y == 1) ? o1 : o2;

    int t = threadIdx.x;
    int lane = t & 31;
    int w = t >> 5;
    int wm = w & 3;
    int wn = w >> 2;
    int g = lane >> 2;
    int c4 = lane & 3;
    int row0 = blockIdx.x * 64;

    for (int idx = t; idx < 4096; idx += 256) {
        int row = idx >> 6;
        int qq = idx & 63;
        float4 v = *(const float4*)&A[(row0 + row) * CCH + qq * 4];
        uint32_t h0 = bf2pack(v.x, v.y);
        uint32_t h1 = bf2pack(v.z, v.w);
        uint32_t l0 = bf2pack(v.x - bflo_f(h0), v.y - bfhi_f(h0));
        uint32_t l1 = bf2pack(v.z - bflo_f(h1), v.w - bfhi_f(h1));
        *(uint2*)&sAhi[row * 132 + qq * 2] = make_uint2(h0, h1);
        *(uint2*)&sAlo[row * 132 + qq * 2] = make_uint2(l0, l1);
    }
    __syncthreads();

    float acc[16][4];
#pragma unroll
    for (int nt = 0; nt < 16; ++nt)
#pragma unroll
        for (int r = 0; r < 4; ++r) acc[nt][r] = 0.0f;

    int rA = wm * 16 + g;
    const uint32_t* bfrag_hi = g_wf_hi + mat * 32768;
    const uint32_t* bfrag_lo = g_wf_lo + mat * 32768;

#pragma unroll 2
    for (int kt = 0; kt < 16; ++kt) {
        uint32_t a0h = sAhi[rA * 132 + kt * 8 + c4];
        uint32_t a1h = sAhi[(rA + 8) * 132 + kt * 8 + c4];
        uint32_t a2h = sAhi[rA * 132 + kt * 8 + c4 + 4];
        uint32_t a3h = sAhi[(rA + 8) * 132 + kt * 8 + c4 + 4];
        uint32_t a0l = sAlo[rA * 132 + kt * 8 + c4];
        uint32_t a1l = sAlo[(rA + 8) * 132 + kt * 8 + c4];
        uint32_t a2l = sAlo[rA * 132 + kt * 8 + c4 + 4];
        uint32_t a3l = sAlo[(rA + 8) * 132 + kt * 8 + c4 + 4];
#pragma unroll
        for (int nt = 0; nt < 16; ++nt) {
            int ntg = wn * 16 + nt;
            uint2 bh = *(const uint2*)&bfrag_hi[kt * 2048 + ntg * 64 + lane * 2];
            uint2 bl = *(const uint2*)&bfrag_lo[kt * 2048 + ntg * 64 + lane * 2];
            mma_bf16(acc[nt], a0h, a1h, a2h, a3h, bh.x, bh.y);
            mma_bf16(acc[nt], a0h, a1h, a2h, a3h, bl.x, bl.y);
            mma_bf16(acc[nt], a0l, a1l, a2l, a3l, bh.x, bh.y);
        }
    }

#pragma unroll
    for (int nt = 0; nt < 16; ++nt) {
        int ntg = wn * 16 + nt;
        int n0 = ntg * 8 + 2 * c4;
        float2 bv = *(const float2*)&bias[n0];
        int r0 = row0 + rA;
        int r1 = r0 + 8;
        float2 v0 = make_float2(acc[nt][0] + bv.x, acc[nt][1] + bv.y);
        float2 v1 = make_float2(acc[nt][2] + bv.x, acc[nt][3] + bv.y);
        if (resid != nullptr) {
            float2 f0 = *(const float2*)&resid[r0 * CCH + n0];
            float2 f1 = *(const float2*)&resid[r1 * CCH + n0];
            v0.x += f0.x; v0.y += f0.y;
            v1.x += f1.x; v1.y += f1.y;
        }
        *(float2*)&out[r0 * CCH + n0] = v0;
        *(float2*)&out[r1 * CCH + n0] = v1;
    }
}

// ---------------- h-pair: 2 hidden values -> packed fp16 fragment reg ----------------
__device__ __forceinline__ uint32_t hpair16(float4 pa, float4 pb,
                                            float dx, float dy, float dz) {
    float h0 = fmaxf(fmaf(dz, pb.x, fmaf(dy, pa.z, fmaf(dx, pa.x, pb.z))), 0.0f);
    float h1 = fmaxf(fmaf(dz, pb.y, fmaf(dy, pa.w, fmaf(dx, pa.y, pb.w))), 0.0f);
    return f16pack(h0, h1);
}

// ---------------- attention: mma.sync fp16 pe-GEMM + warp-local softmax ----------------
#define ATTN_SMEM_U32 9728
#define ATTN_SMEM_B   (ATTN_SMEM_U32 * 4)

__global__ void __launch_bounds__(256) attn_tc_kernel(
    const float* __restrict__ coords,
    const float* __restrict__ pe1_w1, const float* __restrict__ pe1_b1,
    const float* __restrict__ pe1_b2)
{
    extern __shared__ uint32_t dsm[];
    uint32_t* BH  = dsm;
    float*    W1P = (float*)(dsm + 8192);
    float*    DL  = (float*)(dsm + 9216);
    int*      ID  = (int*)(dsm + 9600);

    int t = threadIdx.x;
    int lane = t & 31;
    int w = t >> 5;
    int g = lane >> 2;
    int c4 = lane & 3;

    {
        int f = 4 * t;
#pragma unroll
        for (int u = 0; u < 4; ++u) {
            int ff = f + u, p = ff >> 3, comp = ff & 7;
            float v;
            if (comp < 6) v = pe1_w1[(comp >> 1) * CCH + 2 * p + (comp & 1)];
            else          v = pe1_b1[2 * p + (comp & 1)];
            W1P[ff] = v;
        }
    }
    if (t < 128) ID[t] = g_idx[blockIdx.x * 128 + t];
    __syncthreads();
    if (t < 128) {
        int nid = ID[t];
        int ip = blockIdx.x * 8 + (t >> 4);
#pragma unroll
        for (int d = 0; d < 3; ++d)
            DL[t * 3 + d] = coords[nid * 3 + d] - coords[ip * 3 + d];
    }
    __syncthreads();

    int rA = w * 16 + g, rB = rA + 8;
    float dxa = DL[rA * 3], dya = DL[rA * 3 + 1], dza = DL[rA * 3 + 2];
    float dxb = DL[rB * 3], dyb = DL[rB * 3 + 1], dzb = DL[rB * 3 + 2];
    int nid0 = ID[rA], nid1 = ID[rB];
    int ipt = blockIdx.x * 8 + w;

    const float4* w1p4 = (const float4*)W1P;

    for (int cc = 0; cc < 4; ++cc) {
        __syncthreads();
        {
            const uint4* sh = (const uint4*)(g_w2f + cc * 8192);
            uint4* dh = (uint4*)BH;
            for (int u = t; u < 2048; u += 256) dh[u] = sh[u];
        }
        __syncthreads();

        float acc[8][4];
#pragma unroll
        for (int nt = 0; nt < 8; ++nt)
#pragma unroll
            for (int r = 0; r < 4; ++r) acc[nt][r] = 0.0f;

#pragma unroll 4
        for (int kt = 0; kt < 16; ++kt) {
            int jp0 = kt * 8 + c4;
            float4 p0a = w1p4[jp0 * 2],     p0b = w1p4[jp0 * 2 + 1];
            float4 p1a = w1p4[jp0 * 2 + 8], p1b = w1p4[jp0 * 2 + 9];
            uint32_t a0 = hpair16(p0a, p0b, dxa, dya, dza);
            uint32_t a1 = hpair16(p0a, p0b, dxb, dyb, dzb);
            uint32_t a2 = hpair16(p1a, p1b, dxa, dya, dza);
            uint32_t a3 = hpair16(p1a, p1b, dxb, dyb, dzb);
            int bbase = kt * 512 + lane * 2;
#pragma unroll
            for (int nt = 0; nt < 8; ++nt) {
                uint2 bh = *(const uint2*)&BH[bbase + nt * 64];
                mma_f16(acc[nt], a0, a1, a2, a3, bh.x, bh.y);
            }
        }

#pragma unroll
        for (int nt = 0; nt < 8; ++nt) {
            int n0 = cc * 64 + nt * 8 + 2 * c4;
            float2 b2v = *(const float2*)&pe1_b2[n0];
            float2 th  = *(const float2*)&g_theta[ipt * CCH + n0];
            float2 ph0 = *(const float2*)&g_phi[nid0 * CCH + n0];
            float2 ph1 = *(const float2*)&g_phi[nid1 * CCH + n0];

            float pe00 = acc[nt][0] + b2v.x, pe01 = acc[nt][1] + b2v.y;
            float pe10 = acc[nt][2] + b2v.x, pe11 = acc[nt][3] + b2v.y;

            float v00 = (pe00 * (th.x - ph0.x) + pe00) * 0.0625f;
            float v01 = (pe01 * (th.y - ph0.y) + pe01) * 0.0625f;
            float v10 = (pe10 * (th.x - ph1.x) + pe10) * 0.0625f;
            float v11 = (pe11 * (th.y - ph1.y) + pe11) * 0.0625f;

            float m0 = fmaxf(v00, v10), m1 = fmaxf(v01, v11);
#pragma unroll
            for (int off = 4; off <= 16; off <<= 1) {
                m0 = fmaxf(m0, __shfl_xor_sync(0xffffffffu, m0, off));
                m1 = fmaxf(m1, __shfl_xor_sync(0xffffffffu, m1, off));
            }
            float e00 = expf(v00 - m0), e10 = expf(v10 - m0);
            float e01 = expf(v01 - m1), e11 = expf(v11 - m1);
            float s0 = e00 + e10, s1 = e01 + e11;
#pragma unroll
            for (int off = 4; off <= 16; off <<= 1) {
                s0 += __shfl_xor_sync(0xffffffffu, s0, off);
                s1 += __shfl_xor_sync(0xffffffffu, s1, off);
            }
            float2 gv0 = *(const float2*)&g_gv[nid0 * CCH + n0];
            float2 gv1 = *(const float2*)&g_gv[nid1 * CCH + n0];
            float y0 = e00 * gv0.x + e10 * gv1.x;
            float y1 = e01 * gv0.y + e11 * gv1.y;
#pragma unroll
            for (int off = 4; off <= 16; off <<= 1) {
                y0 += __shfl_xor_sync(0xffffffffu, y0, off);
                y1 += __shfl_xor_sync(0xffffffffu, y1, off);
            }
            if (g == 0)
                *(float2*)&g_y[ipt * CCH + n0] = make_float2(y0 / s0, y1 / s1);
        }
    }
}

// ---------------- launch ----------------
extern "C" void kernel_launch(void* const* d_in, const int* in_sizes, int n_in,
                              void* d_out, int out_size) {
    const float* coords  = (const float*)d_in[0];
    const float* feats   = (const float*)d_in[1];
    const float* theta_w = (const float*)d_in[2];
    const float* theta_b = (const float*)d_in[3];
    const float* phi_w   = (const float*)d_in[4];
    const float* phi_b   = (const float*)d_in[5];
    const float* g_w     = (const float*)d_in[6];
    const float* g_b     = (const float*)d_in[7];
    const float* pe1_w1  = (const float*)d_in[8];
    const float* pe1_b1  = (const float*)d_in[9];
    const float* pe1_w2  = (const float*)d_in[10];
    const float* pe1_b2  = (const float*)d_in[11];
    const float* W_w     = (const float*)d_in[12];
    const float* W_b     = (const float*)d_in[13];
    float* out = (float*)d_out;

    float *p_theta, *p_phi, *p_g, *p_y;
    void* p_cnt;
    cudaGetSymbolAddress((void**)&p_theta, g_theta);
    cudaGetSymbolAddress((void**)&p_phi,   g_phi);
    cudaGetSymbolAddress((void**)&p_g,     g_gv);
    cudaGetSymbolAddress((void**)&p_y,     g_y);
    cudaGetSymbolAddress(&p_cnt,           g_cellcnt);

    cudaFuncSetAttribute(attn_tc_kernel,
                         cudaFuncAttributeMaxDynamicSharedMemorySize, ATTN_SMEM_B);
    cudaFuncSetAttribute(linear_tc_kernel,
                         cudaFuncAttributeMaxDynamicSharedMemorySize, LIN_SMEM);

    // grid build + KNN
    cudaMemsetAsync(p_cnt, 0, 512 * sizeof(int));
    hist_kernel<<<NPTS / 256, 256>>>(coords);
    scan_kernel<<<1, 512>>>();
    scatter_kernel<<<NPTS / 256, 256>>>(coords);
    knn_grid_kernel<<<NPTS / 8, 256>>>(coords);

    // weight fragment prep
    prep_w2_frag<<<128, 256>>>(pe1_w2);
    prep_wf_frag<<<512, 256>>>(theta_w, phi_w, g_w, W_w);

    // theta / phi / g in one tensor-core launch
    linear_tc_kernel<<<dim3(NPTS / 64, 3), 256, LIN_SMEM>>>(
        feats, 0, theta_b, phi_b, g_b, p_theta, p_phi, p_g, nullptr);

    attn_tc_kernel<<<NPTS / 8, 256, ATTN_SMEM_B>>>(coords, pe1_w1, pe1_b1, pe1_b2);

    // final: out = y @ W_w + W_b + feats
    linear_tc_kernel<<<dim3(NPTS / 64, 1), 256, LIN_SMEM>>>(
        p_y, 3, W_b, W_b, W_b, out, out, out, feats);
}

// round 12
// speedup vs baseline: 7.9885x; 1.0797x over previous
#include <cuda_runtime.h>
#include <cuda_bf16.h>
#include <math_constants.h>
#include <cstdint>

#define NPTS 8192
#define CCH  256
#define KNB  16

typedef unsigned long long ull;

// ---------------- pack helpers ----------------
__device__ __forceinline__ uint32_t bf2pack(float lo, float hi) {
    uint32_t r;
    asm("cvt.rn.bf16x2.f32 %0, %1, %2;" : "=r"(r) : "f"(hi), "f"(lo));
    return r;
}
__device__ __forceinline__ float bflo_f(uint32_t u) { return __uint_as_float(u << 16); }
__device__ __forceinline__ float bfhi_f(uint32_t u) { return __uint_as_float(u & 0xffff0000u); }
__device__ __forceinline__ uint32_t f16pack(float lo, float hi) {
    uint32_t r;
    asm("cvt.rn.f16x2.f32 %0, %1, %2;" : "=r"(r) : "f"(hi), "f"(lo));
    return r;
}

// mma.sync m16n8k16 row.col f32 accum (baseline sm_80 PTX)
__device__ __forceinline__ void mma_bf16(float* d,
                                         uint32_t a0, uint32_t a1, uint32_t a2, uint32_t a3,
                                         uint32_t b0, uint32_t b1) {
    asm volatile(
        "mma.sync.aligned.m16n8k16.row.col.f32.bf16.bf16.f32 "
        "{%0,%1,%2,%3}, {%4,%5,%6,%7}, {%8,%9}, {%0,%1,%2,%3};"
        : "+f"(d[0]), "+f"(d[1]), "+f"(d[2]), "+f"(d[3])
        : "r"(a0), "r"(a1), "r"(a2), "r"(a3), "r"(b0), "r"(b1));
}
__device__ __forceinline__ void mma_f16(float* d,
                                        uint32_t a0, uint32_t a1, uint32_t a2, uint32_t a3,
                                        uint32_t b0, uint32_t b1) {
    asm volatile(
        "mma.sync.aligned.m16n8k16.row.col.f32.f16.f16.f32 "
        "{%0,%1,%2,%3}, {%4,%5,%6,%7}, {%8,%9}, {%0,%1,%2,%3};"
        : "+f"(d[0]), "+f"(d[1]), "+f"(d[2]), "+f"(d[3])
        : "r"(a0), "r"(a1), "r"(a2), "r"(a3), "r"(b0), "r"(b1));
}

// ---------------- scratch (device globals; no allocation APIs) ----------------
__device__ int    g_idx[NPTS * KNB];
__device__ float  g_theta[NPTS * CCH];
__device__ float  g_phi[NPTS * CCH];
__device__ float  g_gv[NPTS * CCH];
__device__ float  g_y[NPTS * CCH];
__device__ uint32_t g_w2f[32768];
// mats 0,1 (theta,phi): fp16 frags in _hi (lo unused). mats 2,3 (g,W): bf16 hi/lo.
__device__ uint32_t g_wf_hi[4 * 32768];
__device__ uint32_t g_wf_lo[4 * 32768];
// grid-KNN scratch
__device__ float4 g_spts[NPTS];
__device__ int    g_sid[NPTS];
__device__ int    g_cellcnt[512];
__device__ int    g_cellstart[513];

#define GRID_DIM 8
#define CELL_H   12.5f
#define INV_H    0.08f

__device__ __forceinline__ int cell_coord(float v) {
    int c = (int)(v * INV_H);
    return min(GRID_DIM - 1, max(0, c));
}

// ---------------- grid build ----------------
__global__ void hist_kernel(const float* __restrict__ coords) {
    int i = blockIdx.x * blockDim.x + threadIdx.x;
    if (i < NPTS) {
        int cx = cell_coord(coords[3 * i + 0]);
        int cy = cell_coord(coords[3 * i + 1]);
        int cz = cell_coord(coords[3 * i + 2]);
        atomicAdd(&g_cellcnt[(cz * GRID_DIM + cy) * GRID_DIM + cx], 1);
    }
}

__global__ void scan_kernel() {   // 1 block, 512 threads
    __shared__ int tmp[512];
    int t = threadIdx.x;
    tmp[t] = g_cellcnt[t];
    __syncthreads();
    for (int off = 1; off < 512; off <<= 1) {
        int a = (t >= off) ? tmp[t - off] : 0;
        __syncthreads();
        tmp[t] += a;
        __syncthreads();
    }
    g_cellstart[t + 1] = tmp[t];
    if (t == 0) g_cellstart[0] = 0;
    g_cellcnt[t] = 0;
}

__global__ void scatter_kernel(const float* __restrict__ coords) {
    int i = blockIdx.x * blockDim.x + threadIdx.x;
    if (i < NPTS) {
        float x = coords[3 * i + 0];
        float y = coords[3 * i + 1];
        float z = coords[3 * i + 2];
        int cell = (cell_coord(z) * GRID_DIM + cell_coord(y)) * GRID_DIM + cell_coord(x);
        int pos = g_cellstart[cell] + atomicAdd(&g_cellcnt[cell], 1);
        g_spts[pos] = make_float4(x, y, z, x * x + y * y + z * z);
        g_sid[pos] = i;
    }
}

// ---------------- grid KNN: warp/query, expanding shells, row-merged ranges ----------------
__global__ __launch_bounds__(256) void knn_grid_kernel(const float* __restrict__ coords) {
    int warp = threadIdx.x >> 5;
    int lane = threadIdx.x & 31;
    int q = blockIdx.x * 8 + warp;

    float qx = coords[3 * q + 0];
    float qy = coords[3 * q + 1];
    float qz = coords[3 * q + 2];
    float qw = qx * qx + qy * qy + qz * qz;
    int cx = cell_coord(qx), cy = cell_coord(qy), cz = cell_coord(qz);

    ull slot = ~0ull;
    ull thr  = ~0ull;
    float thrf = CUDART_INF_F;

    // scan a contiguous cell range [c0, c1] (x-adjacent cells share storage)
    auto scan_range = [&](int c0, int c1) {
        int st = g_cellstart[c0];
        int en = g_cellstart[c1 + 1];
        for (int jj = st; jj < en; jj += 32) {
            int id = jj + lane;
            ull key = ~0ull;
            if (id < en) {
                float4 p = g_spts[id];
                float dot = qx * p.x + qy * p.y + qz * p.z;
                float d2 = (qw + p.w) - 2.0f * dot;   // reference formula
                if (d2 <= thrf) {
                    unsigned u = __float_as_uint(d2);
                    u = ((int)u < 0) ? ~u : (u | 0x80000000u);
                    key = ((ull)u << 32) | (unsigned)g_sid[id];
                }
            }
            unsigned mask = __ballot_sync(0xffffffffu, key < thr);
            while (mask) {
                int src = __ffs(mask) - 1;
                mask &= mask - 1;
                ull cand = __shfl_sync(0xffffffffu, key, src);
                if (cand < thr) {
                    unsigned lt = __ballot_sync(0xffffffffu, (lane < 16) && (slot < cand));
                    int pos = __popc(lt);
                    ull prev = __shfl_up_sync(0xffffffffu, slot, 1);
                    if (lane >= pos && lane < 16) slot = (lane == pos) ? cand : prev;
                    thr = __shfl_sync(0xffffffffu, slot, 15);
                }
            }
        }
        unsigned hb = (unsigned)(thr >> 32);
        thrf = (hb == 0xffffffffu) ? CUDART_INF_F
             : ((hb & 0x80000000u) ? __uint_as_float(hb & 0x7fffffffu)
                                   : __uint_as_float(~hb));
    };

    int px0 = 1, px1 = 0, py0 = 1, py1 = 0, pz0 = 1, pz1 = 0;  // empty prev box

    for (int s = 1; s <= GRID_DIM; ++s) {
        int x0 = max(cx - s, 0), x1 = min(cx + s, GRID_DIM - 1);
        int y0 = max(cy - s, 0), y1 = min(cy + s, GRID_DIM - 1);
        int z0 = max(cz - s, 0), z1 = min(cz + s, GRID_DIM - 1);

        for (int zz = z0; zz <= z1; ++zz)
        for (int yy = y0; yy <= y1; ++yy) {
            int rbase = (zz * GRID_DIM + yy) * GRID_DIM;
            bool inPrevZY = (zz >= pz0 && zz <= pz1 && yy >= py0 && yy <= py1);
            if (!inPrevZY) {
                scan_range(rbase + x0, rbase + x1);          // whole row at once
            } else {
                if (x0 < px0) scan_range(rbase + x0, rbase + px0 - 1);
                if (px1 < x1) scan_range(rbase + px1 + 1, rbase + x1);
            }
        }

        bool covered = (x0 == 0 && x1 == GRID_DIM - 1 &&
                        y0 == 0 && y1 == GRID_DIM - 1 &&
                        z0 == 0 && z1 == GRID_DIM - 1);
        float fxl = (x0 > 0) ? qx - x0 * CELL_H : CUDART_INF_F;
        float fxh = (x1 < GRID_DIM - 1) ? (x1 + 1) * CELL_H - qx : CUDART_INF_F;
        float fyl = (y0 > 0) ? qy - y0 * CELL_H : CUDART_INF_F;
        float fyh = (y1 < GRID_DIM - 1) ? (y1 + 1) * CELL_H - qy : CUDART_INF_F;
        float fzl = (z0 > 0) ? qz - z0 * CELL_H : CUDART_INF_F;
        float fzh = (z1 < GRID_DIM - 1) ? (z1 + 1) * CELL_H - qz : CUDART_INF_F;
        float md = fminf(fminf(fminf(fxl, fxh), fminf(fyl, fyh)), fminf(fzl, fzh));
        if (covered || md * md > thrf + 0.5f) break;

        px0 = x0; px1 = x1; py0 = y0; py1 = y1; pz0 = z0; pz1 = z1;
    }

    if (lane < 16) g_idx[q * KNB + lane] = (int)(unsigned)(slot & 0xffffffffu);
}

// ---------------- prep: all weight fragments in one launch ----------------
// blocks 0..127:   w2 -> fp16 frags (attn)
// blocks 128..639: theta/phi (fp16 frags) + g/W (bf16 hi/lo frags)
__global__ void prep_frags_kernel(const float* __restrict__ w2attn,
                                  const float* __restrict__ w0, const float* __restrict__ w1,
                                  const float* __restrict__ w2, const float* __restrict__ w3) {
    if (blockIdx.x < 128) {
        int tid = blockIdx.x * 256 + threadIdx.x;       // 0..32767
        int reg = tid & 1;
        int ln  = (tid >> 1) & 31;
        int nt  = (tid >> 6) & 7;
        int kt  = (tid >> 9) & 15;
        int cc  = (tid >> 13) & 3;
        int n = cc * 64 + nt * 8 + (ln >> 2);
        int k = kt * 16 + 2 * (ln & 3) + reg * 8;
        float v0 = w2attn[k * CCH + n];
        float v1 = w2attn[(k + 1) * CCH + n];
        g_w2f[tid] = f16pack(v0, v1);
    } else {
        int tid = (blockIdx.x - 128) * 256 + threadIdx.x;  // 0..131071
        int m = tid >> 15;
        int r = tid & 32767;
        int reg = r & 1;
        int ln  = (r >> 1) & 31;
        int nt  = (r >> 6) & 31;
        int kt  = (r >> 11) & 15;
        int n = nt * 8 + (ln >> 2);
        int k = kt * 16 + 2 * (ln & 3) + reg * 8;
        const float* W = (m == 0) ? w0 : (m == 1) ? w1 : (m == 2) ? w2 : w3;
        float v0 = W[k * CCH + n];
        float v1 = W[(k + 1) * CCH + n];
        if (m < 2) {
            g_wf_hi[tid] = f16pack(v0, v1);                // theta/phi: fp16 1-pass
        } else {
            uint32_t hi = bf2pack(v0, v1);
            g_wf_hi[tid] = hi;
            g_wf_lo[tid] = bf2pack(v0 - bflo_f(hi), v1 - bfhi_f(hi));
        }
    }
}

// ---------------- tensor-core linear ----------------
// mats 0,1: fp16 single-pass. mats 2,3: bf16 3-pass.
#define LIN_SMEM (2 * 64 * 132 * 4)

__global__ void __launch_bounds__(256, 2) linear_tc_kernel(
    const float* __restrict__ A, int m0,
    const float* __restrict__ b0_, const float* __restrict__ b1_, const float* __restrict__ b2_,
    float* __restrict__ o0, float* __restrict__ o1, float* __restrict__ o2,
    const float* __restrict__ resid)
{
    extern __shared__ uint32_t dsm[];
    uint32_t* sAhi = dsm;
    uint32_t* sAlo = dsm + 64 * 132;

    int mat = m0 + blockIdx.y;
    bool f16m = (mat < 2);
    const float* bias = (blockIdx.y == 0) ? b0_ : (blockIdx.y == 1) ? b1_ : b2_;
    float*       out  = (blockIdx.y == 0) ? o0 : (blockIdx.y == 1) ? o1 : o2;

    int t = threadIdx.x;
    int lane = t & 31;
    int w = t >> 5;
    int wm = w & 3;
    int wn = w >> 2;
    int g = lane >> 2;
    int c4 = lane & 3;
    int row0 = blockIdx.x * 64;

    for (int idx = t; idx < 4096; idx += 256) {
        int row = idx >> 6;
        int qq = idx & 63;
        float4 v = *(const float4*)&A[(row0 + row) * CCH + qq * 4];
        if (f16m) {
            *(uint2*)&sAhi[row * 132 + qq * 2] =
                make_uint2(f16pack(v.x, v.y), f16pack(v.z, v.w));
        } else {
            uint32_t h0 = bf2pack(v.x, v.y);
            uint32_t h1 = bf2pack(v.z, v.w);
            uint32_t l0 = bf2pack(v.x - bflo_f(h0), v.y - bfhi_f(h0));
            uint32_t l1 = bf2pack(v.z - bflo_f(h1), v.w - bfhi_f(h1));
            *(uint2*)&sAhi[row * 132 + qq * 2] = make_uint2(h0, h1);
            *(uint2*)&sAlo[row * 132 + qq * 2] = make_uint2(l0, l1);
        }
    }
    __syncthreads();

    float acc[16][4];
#pragma unroll
    for (int nt = 0; nt < 16; ++nt)
#pragma unroll
        for (int r = 0; r < 4; ++r) acc[nt][r] = 0.0f;

    int rA = wm * 16 + g;
    const uint32_t* bfrag_hi = g_wf_hi + mat * 32768;
    const uint32_t* bfrag_lo = g_wf_lo + mat * 32768;

    if (f16m) {
#pragma unroll 2
        for (int kt = 0; kt < 16; ++kt) {
            uint32_t a0 = sAhi[rA * 132 + kt * 8 + c4];
            uint32_t a1 = sAhi[(rA + 8) * 132 + kt * 8 + c4];
            uint32_t a2 = sAhi[rA * 132 + kt * 8 + c4 + 4];
            uint32_t a3 = sAhi[(rA + 8) * 132 + kt * 8 + c4 + 4];
#pragma unroll
            for (int nt = 0; nt < 16; ++nt) {
                int ntg = wn * 16 + nt;
                uint2 bh = *(const uint2*)&bfrag_hi[kt * 2048 + ntg * 64 + lane * 2];
                mma_f16(acc[nt], a0, a1, a2, a3, bh.x, bh.y);
            }
        }
    } else {
#pragma unroll 2
        for (int kt = 0; kt < 16; ++kt) {
            uint32_t a0h = sAhi[rA * 132 + kt * 8 + c4];
            uint32_t a1h = sAhi[(rA + 8) * 132 + kt * 8 + c4];
            uint32_t a2h = sAhi[rA * 132 + kt * 8 + c4 + 4];
            uint32_t a3h = sAhi[(rA + 8) * 132 + kt * 8 + c4 + 4];
            uint32_t a0l = sAlo[rA * 132 + kt * 8 + c4];
            uint32_t a1l = sAlo[(rA + 8) * 132 + kt * 8 + c4];
            uint32_t a2l = sAlo[rA * 132 + kt * 8 + c4 + 4];
            uint32_t a3l = sAlo[(rA + 8) * 132 + kt * 8 + c4 + 4];
#pragma unroll
            for (int nt = 0; nt < 16; ++nt) {
                int ntg = wn * 16 + nt;
                uint2 bh = *(const uint2*)&bfrag_hi[kt * 2048 + ntg * 64 + lane * 2];
                uint2 bl = *(const uint2*)&bfrag_lo[kt * 2048 + ntg * 64 + lane * 2];
                mma_bf16(acc[nt], a0h, a1h, a2h, a3h, bh.x, bh.y);
                mma_bf16(acc[nt], a0h, a1h, a2h, a3h, bl.x, bl.y);
                mma_bf16(acc[nt], a0l, a1l, a2l, a3l, bh.x, bh.y);
            }
        }
    }

#pragma unroll
    for (int nt = 0; nt < 16; ++nt) {
        int ntg = wn * 16 + nt;
        int n0 = ntg * 8 + 2 * c4;
        float2 bv = *(const float2*)&bias[n0];
        int r0 = row0 + rA;
        int r1 = r0 + 8;
        float2 v0 = make_float2(acc[nt][0] + bv.x, acc[nt][1] + bv.y);
        float2 v1 = make_float2(acc[nt][2] + bv.x, acc[nt][3] + bv.y);
        if (resid != nullptr) {
            float2 f0 = *(const float2*)&resid[r0 * CCH + n0];
            float2 f1 = *(const float2*)&resid[r1 * CCH + n0];
            v0.x += f0.x; v0.y += f0.y;
            v1.x += f1.x; v1.y += f1.y;
        }
        *(float2*)&out[r0 * CCH + n0] = v0;
        *(float2*)&out[r1 * CCH + n0] = v1;
    }
}

// ---------------- h-pair: 2 hidden values -> packed fp16 fragment reg ----------------
__device__ __forceinline__ uint32_t hpair16(float4 pa, float4 pb,
                                            float dx, float dy, float dz) {
    float h0 = fmaxf(fmaf(dz, pb.x, fmaf(dy, pa.z, fmaf(dx, pa.x, pb.z))), 0.0f);
    float h1 = fmaxf(fmaf(dz, pb.y, fmaf(dy, pa.w, fmaf(dx, pa.y, pb.w))), 0.0f);
    return f16pack(h0, h1);
}

// ---------------- attention: mma.sync fp16 pe-GEMM + warp-local softmax ----------------
#define ATTN_SMEM_U32 9728
#define ATTN_SMEM_B   (ATTN_SMEM_U32 * 4)

__global__ void __launch_bounds__(256) attn_tc_kernel(
    const float* __restrict__ coords,
    const float* __restrict__ pe1_w1, const float* __restrict__ pe1_b1,
    const float* __restrict__ pe1_b2)
{
    extern __shared__ uint32_t dsm[];
    uint32_t* BH  = dsm;
    float*    W1P = (float*)(dsm + 8192);
    float*    DL  = (float*)(dsm + 9216);
    int*      ID  = (int*)(dsm + 9600);

    int t = threadIdx.x;
    int lane = t & 31;
    int w = t >> 5;
    int g = lane >> 2;
    int c4 = lane & 3;

    {
        int f = 4 * t;
#pragma unroll
        for (int u = 0; u < 4; ++u) {
            int ff = f + u, p = ff >> 3, comp = ff & 7;
            float v;
            if (comp < 6) v = pe1_w1[(comp >> 1) * CCH + 2 * p + (comp & 1)];
            else          v = pe1_b1[2 * p + (comp & 1)];
            W1P[ff] = v;
        }
    }
    if (t < 128) ID[t] = g_idx[blockIdx.x * 128 + t];
    __syncthreads();
    if (t < 128) {
        int nid = ID[t];
        int ip = blockIdx.x * 8 + (t >> 4);
#pragma unroll
        for (int d = 0; d < 3; ++d)
            DL[t * 3 + d] = coords[nid * 3 + d] - coords[ip * 3 + d];
    }
    __syncthreads();

    int rA = w * 16 + g, rB = rA + 8;
    float dxa = DL[rA * 3], dya = DL[rA * 3 + 1], dza = DL[rA * 3 + 2];
    float dxb = DL[rB * 3], dyb = DL[rB * 3 + 1], dzb = DL[rB * 3 + 2];
    int nid0 = ID[rA], nid1 = ID[rB];
    int ipt = blockIdx.x * 8 + w;

    const float4* w1p4 = (const float4*)W1P;

    for (int cc = 0; cc < 4; ++cc) {
        __syncthreads();
        {
            const uint4* sh = (const uint4*)(g_w2f + cc * 8192);
            uint4* dh = (uint4*)BH;
            for (int u = t; u < 2048; u += 256) dh[u] = sh[u];
        }
        __syncthreads();

        float acc[8][4];
#pragma unroll
        for (int nt = 0; nt < 8; ++nt)
#pragma unroll
            for (int r = 0; r < 4; ++r) acc[nt][r] = 0.0f;

#pragma unroll 4
        for (int kt = 0; kt < 16; ++kt) {
            int jp0 = kt * 8 + c4;
            float4 p0a = w1p4[jp0 * 2],     p0b = w1p4[jp0 * 2 + 1];
            float4 p1a = w1p4[jp0 * 2 + 8], p1b = w1p4[jp0 * 2 + 9];
            uint32_t a0 = hpair16(p0a, p0b, dxa, dya, dza);
            uint32_t a1 = hpair16(p0a, p0b, dxb, dyb, dzb);
            uint32_t a2 = hpair16(p1a, p1b, dxa, dya, dza);
            uint32_t a3 = hpair16(p1a, p1b, dxb, dyb, dzb);
            int bbase = kt * 512 + lane * 2;
#pragma unroll
            for (int nt = 0; nt < 8; ++nt) {
                uint2 bh = *(const uint2*)&BH[bbase + nt * 64];
                mma_f16(acc[nt], a0, a1, a2, a3, bh.x, bh.y);
            }
        }

#pragma unroll
        for (int nt = 0; nt < 8; ++nt) {
            int n0 = cc * 64 + nt * 8 + 2 * c4;
            float2 b2v = *(const float2*)&pe1_b2[n0];
            float2 th  = *(const float2*)&g_theta[ipt * CCH + n0];
            float2 ph0 = *(const float2*)&g_phi[nid0 * CCH + n0];
            float2 ph1 = *(const float2*)&g_phi[nid1 * CCH + n0];

            float pe00 = acc[nt][0] + b2v.x, pe01 = acc[nt][1] + b2v.y;
            float pe10 = acc[nt][2] + b2v.x, pe11 = acc[nt][3] + b2v.y;

            float v00 = (pe00 * (th.x - ph0.x) + pe00) * 0.0625f;
            float v01 = (pe01 * (th.y - ph0.y) + pe01) * 0.0625f;
            float v10 = (pe10 * (th.x - ph1.x) + pe10) * 0.0625f;
            float v11 = (pe11 * (th.y - ph1.y) + pe11) * 0.0625f;

            float m0 = fmaxf(v00, v10), m1 = fmaxf(v01, v11);
#pragma unroll
            for (int off = 4; off <= 16; off <<= 1) {
                m0 = fmaxf(m0, __shfl_xor_sync(0xffffffffu, m0, off));
                m1 = fmaxf(m1, __shfl_xor_sync(0xffffffffu, m1, off));
            }
            float e00 = expf(v00 - m0), e10 = expf(v10 - m0);
            float e01 = expf(v01 - m1), e11 = expf(v11 - m1);
            float s0 = e00 + e10, s1 = e01 + e11;
#pragma unroll
            for (int off = 4; off <= 16; off <<= 1) {
                s0 += __shfl_xor_sync(0xffffffffu, s0, off);
                s1 += __shfl_xor_sync(0xffffffffu, s1, off);
            }
            float2 gv0 = *(const float2*)&g_gv[nid0 * CCH + n0];
            float2 gv1 = *(const float2*)&g_gv[nid1 * CCH + n0];
            float y0 = e00 * gv0.x + e10 * gv1.x;
            float y1 = e01 * gv0.y + e11 * gv1.y;
#pragma unroll
            for (int off = 4; off <= 16; off <<= 1) {
                y0 += __shfl_xor_sync(0xffffffffu, y0, off);
                y1 += __shfl_xor_sync(0xffffffffu, y1, off);
            }
            if (g == 0)
                *(float2*)&g_y[ipt * CCH + n0] = make_float2(y0 / s0, y1 / s1);
        }
    }
}

// ---------------- launch ----------------
extern "C" void kernel_launch(void* const* d_in, const int* in_sizes, int n_in,
                              void* d_out, int out_size) {
    const float* coords  = (const float*)d_in[0];
    const float* feats   = (const float*)d_in[1];
    const float* theta_w = (const float*)d_in[2];
    const float* theta_b = (const float*)d_in[3];
    const float* phi_w   = (const float*)d_in[4];
    const float* phi_b   = (const float*)d_in[5];
    const float* g_w     = (const float*)d_in[6];
    const float* g_b     = (const float*)d_in[7];
    const float* pe1_w1  = (const float*)d_in[8];
    const float* pe1_b1  = (const float*)d_in[9];
    const float* pe1_w2  = (const float*)d_in[10];
    const float* pe1_b2  = (const float*)d_in[11];
    const float* W_w     = (const float*)d_in[12];
    const float* W_b     = (const float*)d_in[13];
    float* out = (float*)d_out;

    float *p_theta, *p_phi, *p_g, *p_y;
    void* p_cnt;
    cudaGetSymbolAddress((void**)&p_theta, g_theta);
    cudaGetSymbolAddress((void**)&p_phi,   g_phi);
    cudaGetSymbolAddress((void**)&p_g,     g_gv);
    cudaGetSymbolAddress((void**)&p_y,     g_y);
    cudaGetSymbolAddress(&p_cnt,           g_cellcnt);

    cudaFuncSetAttribute(attn_tc_kernel,
                         cudaFuncAttributeMaxDynamicSharedMemorySize, ATTN_SMEM_B);
    cudaFuncSetAttribute(linear_tc_kernel,
                         cudaFuncAttributeMaxDynamicSharedMemorySize, LIN_SMEM);

    // grid build + KNN
    cudaMemsetAsync(p_cnt, 0, 512 * sizeof(int));
    hist_kernel<<<NPTS / 256, 256>>>(coords);
    scan_kernel<<<1, 512>>>();
    scatter_kernel<<<NPTS / 256, 256>>>(coords);
    knn_grid_kernel<<<NPTS / 8, 256>>>(coords);

    // all weight fragments in one launch
    prep_frags_kernel<<<640, 256>>>(pe1_w2, theta_w, phi_w, g_w, W_w);

    // theta(f16) / phi(f16) / g(bf16x3) in one tensor-core launch
    linear_tc_kernel<<<dim3(NPTS / 64, 3), 256, LIN_SMEM>>>(
        feats, 0, theta_b, phi_b, g_b, p_theta, p_phi, p_g, nullptr);

    attn_tc_kernel<<<NPTS / 8, 256, ATTN_SMEM_B>>>(coords, pe1_w1, pe1_b1, pe1_b2);

    // final: out = y @ W_w + W_b + feats (bf16x3)
    linear_tc_kernel<<<dim3(NPTS / 64, 1), 256, LIN_SMEM>>>(
        p_y, 3, W_b, W_b, W_b, out, out, out, feats);
}

// round 13
// speedup vs baseline: 8.9754x; 1.1235x over previous
#include <cuda_runtime.h>
#include <cuda_bf16.h>
#include <math_constants.h>
#include <cstdint>

#define NPTS 8192
#define CCH  256
#define KNB  16

typedef unsigned long long ull;

// ---------------- pack helpers ----------------
// f16x2: bits[15:0] = lo arg, bits[31:16] = hi arg
__device__ __forceinline__ uint32_t f16pack(float lo, float hi) {
    uint32_t r;
    asm("cvt.rn.f16x2.f32 %0, %1, %2;" : "=r"(r) : "f"(hi), "f"(lo));
    return r;
}

// mma.sync m16n8k16 row.col f32 accum (baseline sm_80 PTX)
__device__ __forceinline__ void mma_f16(float* d,
                                        uint32_t a0, uint32_t a1, uint32_t a2, uint32_t a3,
                                        uint32_t b0, uint32_t b1) {
    asm volatile(
        "mma.sync.aligned.m16n8k16.row.col.f32.f16.f16.f32 "
        "{%0,%1,%2,%3}, {%4,%5,%6,%7}, {%8,%9}, {%0,%1,%2,%3};"
        : "+f"(d[0]), "+f"(d[1]), "+f"(d[2]), "+f"(d[3])
        : "r"(a0), "r"(a1), "r"(a2), "r"(a3), "r"(b0), "r"(b1));
}

// ---------------- scratch (device globals; no allocation APIs) ----------------
__device__ int    g_idx[NPTS * KNB];
__device__ float  g_theta[NPTS * CCH];
__device__ float  g_phi[NPTS * CCH];
__device__ float  g_gv[NPTS * CCH];
__device__ float  g_y[NPTS * CCH];
__device__ uint32_t g_w2f[32768];
// linear weights (theta, phi, g, W) -> fp16 B fragments
__device__ uint32_t g_wf[4 * 32768];
// grid-KNN scratch
__device__ float4 g_spts[NPTS];
__device__ int    g_sid[NPTS];
__device__ int    g_cellcnt[512];
__device__ int    g_cellstart[513];

#define GRID_DIM 8
#define CELL_H   12.5f
#define INV_H    0.08f

__device__ __forceinline__ int cell_coord(float v) {
    int c = (int)(v * INV_H);
    return min(GRID_DIM - 1, max(0, c));
}

// ---------------- grid build ----------------
__global__ void hist_kernel(const float* __restrict__ coords) {
    int i = blockIdx.x * blockDim.x + threadIdx.x;
    if (i < NPTS) {
        int cx = cell_coord(coords[3 * i + 0]);
        int cy = cell_coord(coords[3 * i + 1]);
        int cz = cell_coord(coords[3 * i + 2]);
        atomicAdd(&g_cellcnt[(cz * GRID_DIM + cy) * GRID_DIM + cx], 1);
    }
}

__global__ void scan_kernel() {   // 1 block, 512 threads
    __shared__ int tmp[512];
    int t = threadIdx.x;
    tmp[t] = g_cellcnt[t];
    __syncthreads();
    for (int off = 1; off < 512; off <<= 1) {
        int a = (t >= off) ? tmp[t - off] : 0;
        __syncthreads();
        tmp[t] += a;
        __syncthreads();
    }
    g_cellstart[t + 1] = tmp[t];
    if (t == 0) g_cellstart[0] = 0;
    g_cellcnt[t] = 0;
}

__global__ void scatter_kernel(const float* __restrict__ coords) {
    int i = blockIdx.x * blockDim.x + threadIdx.x;
    if (i < NPTS) {
        float x = coords[3 * i + 0];
        float y = coords[3 * i + 1];
        float z = coords[3 * i + 2];
        int cell = (cell_coord(z) * GRID_DIM + cell_coord(y)) * GRID_DIM + cell_coord(x);
        int pos = g_cellstart[cell] + atomicAdd(&g_cellcnt[cell], 1);
        g_spts[pos] = make_float4(x, y, z, x * x + y * y + z * z);
        g_sid[pos] = i;
    }
}

// ---------------- grid KNN: warp/query, bitonic seed + lean exact inserts ----------------
__global__ __launch_bounds__(256) void knn_grid_kernel(const float* __restrict__ coords) {
    int warp = threadIdx.x >> 5;
    int lane = threadIdx.x & 31;
    int q = blockIdx.x * 8 + warp;

    float qx = coords[3 * q + 0];
    float qy = coords[3 * q + 1];
    float qz = coords[3 * q + 2];
    float qw = qx * qx + qy * qy + qz * qz;
    int cx = cell_coord(qx), cy = cell_coord(qy), cz = cell_coord(qz);

    ull slot = ~0ull;
    ull thr  = ~0ull;
    float thrf = CUDART_INF_F;
    bool seeded = false;

    auto scan_range = [&](int c0, int c1) {
        int st = g_cellstart[c0];
        int en = g_cellstart[c1 + 1];
        for (int jj = st; jj < en; jj += 32) {
            int id = jj + lane;
            ull key = ~0ull;
            if (id < en) {
                float4 p = g_spts[id];
                float dot = qx * p.x + qy * p.y + qz * p.z;
                float d2 = (qw + p.w) - 2.0f * dot;   // reference formula
                if (d2 <= thrf) {
                    unsigned u = __float_as_uint(d2);
                    u = ((int)u < 0) ? ~u : (u | 0x80000000u);
                    key = ((ull)u << 32) | (unsigned)g_sid[id];
                }
            }
            if (!seeded) {
                // warp bitonic sort (ascending by lane) replaces the warm-up insert burst
#pragma unroll
                for (int k = 2; k <= 32; k <<= 1) {
#pragma unroll
                    for (int j = k >> 1; j > 0; j >>= 1) {
                        ull other = __shfl_xor_sync(0xffffffffu, key, j);
                        bool keepSmall = (((lane & k) == 0) == ((lane & j) == 0));
                        bool less = key < other;
                        key = (keepSmall == less) ? key : other;
                    }
                }
                slot = key;                            // lanes 0..15 = top-16 sorted
                thr  = __shfl_sync(0xffffffffu, slot, 15);
                seeded = true;
            } else {
                unsigned mask = __ballot_sync(0xffffffffu, key < thr);
                if (mask) {
                    while (mask) {
                        int src = __ffs(mask) - 1;
                        mask &= mask - 1;
                        ull cand = __shfl_sync(0xffffffffu, key, src);
                        unsigned lt = __ballot_sync(0xffffffffu, (lane < 16) && (slot < cand));
                        int pos = __popc(lt);                       // pos==16 -> no-op (stale cand)
                        ull prev = __shfl_up_sync(0xffffffffu, slot, 1);
                        if (lane >= pos && lane < 16) slot = (lane == pos) ? cand : prev;
                    }
                    thr = __shfl_sync(0xffffffffu, slot, 15);
                }
            }
        }
        unsigned hb = (unsigned)(thr >> 32);
        thrf = (hb == 0xffffffffu) ? CUDART_INF_F
             : ((hb & 0x80000000u) ? __uint_as_float(hb & 0x7fffffffu)
                                   : __uint_as_float(~hb));
    };

    int px0 = 1, px1 = 0, py0 = 1, py1 = 0, pz0 = 1, pz1 = 0;  // empty prev box

    for (int s = 1; s <= GRID_DIM; ++s) {
        int x0 = max(cx - s, 0), x1 = min(cx + s, GRID_DIM - 1);
        int y0 = max(cy - s, 0), y1 = min(cy + s, GRID_DIM - 1);
        int z0 = max(cz - s, 0), z1 = min(cz + s, GRID_DIM - 1);

        for (int zz = z0; zz <= z1; ++zz)
        for (int yy = y0; yy <= y1; ++yy) {
            int rbase = (zz * GRID_DIM + yy) * GRID_DIM;
            bool inPrevZY = (zz >= pz0 && zz <= pz1 && yy >= py0 && yy <= py1);
            if (!inPrevZY) {
                scan_range(rbase + x0, rbase + x1);          // whole row at once
            } else {
                if (x0 < px0) scan_range(rbase + x0, rbase + px0 - 1);
                if (px1 < x1) scan_range(rbase + px1 + 1, rbase + x1);
            }
        }

        bool covered = (x0 == 0 && x1 == GRID_DIM - 1 &&
                        y0 == 0 && y1 == GRID_DIM - 1 &&
                        z0 == 0 && z1 == GRID_DIM - 1);
        float fxl = (x0 > 0) ? qx - x0 * CELL_H : CUDART_INF_F;
        float fxh = (x1 < GRID_DIM - 1) ? (x1 + 1) * CELL_H - qx : CUDART_INF_F;
        float fyl = (y0 > 0) ? qy - y0 * CELL_H : CUDART_INF_F;
        float fyh = (y1 < GRID_DIM - 1) ? (y1 + 1) * CELL_H - qy : CUDART_INF_F;
        float fzl = (z0 > 0) ? qz - z0 * CELL_H : CUDART_INF_F;
        float fzh = (z1 < GRID_DIM - 1) ? (z1 + 1) * CELL_H - qz : CUDART_INF_F;
        float md = fminf(fminf(fminf(fxl, fxh), fminf(fyl, fyh)), fminf(fzl, fzh));
        if (covered || md * md > thrf + 0.5f) break;

        px0 = x0; px1 = x1; py0 = y0; py1 = y1; pz0 = z0; pz1 = z1;
    }

    if (lane < 16) g_idx[q * KNB + lane] = (int)(unsigned)(slot & 0xffffffffu);
}

// ---------------- prep: all weight fragments (fp16) in one launch ----------------
__global__ void prep_frags_kernel(const float* __restrict__ w2attn,
                                  const float* __restrict__ w0, const float* __restrict__ w1,
                                  const float* __restrict__ w2, const float* __restrict__ w3) {
    if (blockIdx.x < 128) {
        int tid = blockIdx.x * 256 + threadIdx.x;       // 0..32767
        int reg = tid & 1;
        int ln  = (tid >> 1) & 31;
        int nt  = (tid >> 6) & 7;
        int kt  = (tid >> 9) & 15;
        int cc  = (tid >> 13) & 3;
        int n = cc * 64 + nt * 8 + (ln >> 2);
        int k = kt * 16 + 2 * (ln & 3) + reg * 8;
        g_w2f[tid] = f16pack(w2attn[k * CCH + n], w2attn[(k + 1) * CCH + n]);
    } else {
        int tid = (blockIdx.x - 128) * 256 + threadIdx.x;  // 0..131071
        int m = tid >> 15;
        int r = tid & 32767;
        int reg = r & 1;
        int ln  = (r >> 1) & 31;
        int nt  = (r >> 6) & 31;
        int kt  = (r >> 11) & 15;
        int n = nt * 8 + (ln >> 2);
        int k = kt * 16 + 2 * (ln & 3) + reg * 8;
        const float* W = (m == 0) ? w0 : (m == 1) ? w1 : (m == 2) ? w2 : w3;
        g_wf[tid] = f16pack(W[k * CCH + n], W[(k + 1) * CCH + n]);
    }
}

// ---------------- tensor-core linear: fp16 single-pass ----------------
#define LIN_SMEM (64 * 132 * 4)

__global__ void __launch_bounds__(256, 2) linear_tc_kernel(
    const float* __restrict__ A, int m0,
    const float* __restrict__ b0_, const float* __restrict__ b1_, const float* __restrict__ b2_,
    float* __restrict__ o0, float* __restrict__ o1, float* __restrict__ o2,
    const float* __restrict__ resid)
{
    extern __shared__ uint32_t dsm[];
    uint32_t* sA = dsm;

    int mat = m0 + blockIdx.y;
    const float* bias = (blockIdx.y == 0) ? b0_ : (blockIdx.y == 1) ? b1_ : b2_;
    float*       out  = (blockIdx.y == 0) ? o0 : (blockIdx.y == 1) ? o1 : o2;

    int t = threadIdx.x;
    int lane = t & 31;
    int w = t >> 5;
    int wm = w & 3;
    int wn = w >> 2;
    int g = lane >> 2;
    int c4 = lane & 3;
    int row0 = blockIdx.x * 64;

    for (int idx = t; idx < 4096; idx += 256) {
        int row = idx >> 6;
        int qq = idx & 63;
        float4 v = *(const float4*)&A[(row0 + row) * CCH + qq * 4];
        *(uint2*)&sA[row * 132 + qq * 2] = make_uint2(f16pack(v.x, v.y), f16pack(v.z, v.w));
    }
    __syncthreads();

    float acc[16][4];
#pragma unroll
    for (int nt = 0; nt < 16; ++nt)
#pragma unroll
        for (int r = 0; r < 4; ++r) acc[nt][r] = 0.0f;

    int rA = wm * 16 + g;
    const uint32_t* bfrag = g_wf + mat * 32768;

#pragma unroll 2
    for (int kt = 0; kt < 16; ++kt) {
        uint32_t a0 = sA[rA * 132 + kt * 8 + c4];
        uint32_t a1 = sA[(rA + 8) * 132 + kt * 8 + c4];
        uint32_t a2 = sA[rA * 132 + kt * 8 + c4 + 4];
        uint32_t a3 = sA[(rA + 8) * 132 + kt * 8 + c4 + 4];
#pragma unroll
        for (int nt = 0; nt < 16; ++nt) {
            int ntg = wn * 16 + nt;
            uint2 bh = *(const uint2*)&bfrag[kt * 2048 + ntg * 64 + lane * 2];
            mma_f16(acc[nt], a0, a1, a2, a3, bh.x, bh.y);
        }
    }

#pragma unroll
    for (int nt = 0; nt < 16; ++nt) {
        int ntg = wn * 16 + nt;
        int n0 = ntg * 8 + 2 * c4;
        float2 bv = *(const float2*)&bias[n0];
        int r0 = row0 + rA;
        int r1 = r0 + 8;
        float2 v0 = make_float2(acc[nt][0] + bv.x, acc[nt][1] + bv.y);
        float2 v1 = make_float2(acc[nt][2] + bv.x, acc[nt][3] + bv.y);
        if (resid != nullptr) {
            float2 f0 = *(const float2*)&resid[r0 * CCH + n0];
            float2 f1 = *(const float2*)&resid[r1 * CCH + n0];
            v0.x += f0.x; v0.y += f0.y;
            v1.x += f1.x; v1.y += f1.y;
        }
        *(float2*)&out[r0 * CCH + n0] = v0;
        *(float2*)&out[r1 * CCH + n0] = v1;
    }
}

// ---------------- h-pair: 2 hidden values -> packed fp16 fragment reg ----------------
__device__ __forceinline__ uint32_t hpair16(float4 pa, float4 pb,
                                            float dx, float dy, float dz) {
    float h0 = fmaxf(fmaf(dz, pb.x, fmaf(dy, pa.z, fmaf(dx, pa.x, pb.z))), 0.0f);
    float h1 = fmaxf(fmaf(dz, pb.y, fmaf(dy, pa.w, fmaf(dx, pa.y, pb.w))), 0.0f);
    return f16pack(h0, h1);
}

// ---------------- attention: mma.sync fp16 pe-GEMM + warp-local softmax ----------------
#define ATTN_SMEM_U32 9728
#define ATTN_SMEM_B   (ATTN_SMEM_U32 * 4)

__global__ void __launch_bounds__(256) attn_tc_kernel(
    const float* __restrict__ coords,
    const float* __restrict__ pe1_w1, const float* __restrict__ pe1_b1,
    const float* __restrict__ pe1_b2)
{
    extern __shared__ uint32_t dsm[];
    uint32_t* BH  = dsm;
    float*    W1P = (float*)(dsm + 8192);
    float*    DL  = (float*)(dsm + 9216);
    int*      ID  = (int*)(dsm + 9600);

    int t = threadIdx.x;
    int lane = t & 31;
    int w = t >> 5;
    int g = lane >> 2;
    int c4 = lane & 3;

    {
        int f = 4 * t;
#pragma unroll
        for (int u = 0; u < 4; ++u) {
            int ff = f + u, p = ff >> 3, comp = ff & 7;
            float v;
            if (comp < 6) v = pe1_w1[(comp >> 1) * CCH + 2 * p + (comp & 1)];
            else          v = pe1_b1[2 * p + (comp & 1)];
            W1P[ff] = v;
        }
    }
    if (t < 128) ID[t] = g_idx[blockIdx.x * 128 + t];
    __syncthreads();
    if (t < 128) {
        int nid = ID[t];
        int ip = blockIdx.x * 8 + (t >> 4);
#pragma unroll
        for (int d = 0; d < 3; ++d)
            DL[t * 3 + d] = coords[nid * 3 + d] - coords[ip * 3 + d];
    }
    __syncthreads();

    int rA = w * 16 + g, rB = rA + 8;
    float dxa = DL[rA * 3], dya = DL[rA * 3 + 1], dza = DL[rA * 3 + 2];
    float dxb = DL[rB * 3], dyb = DL[rB * 3 + 1], dzb = DL[rB * 3 + 2];
    int nid0 = ID[rA], nid1 = ID[rB];
    int ipt = blockIdx.x * 8 + w;

    const float4* w1p4 = (const float4*)W1P;

    for (int cc = 0; cc < 4; ++cc) {
        __syncthreads();
        {
            const uint4* sh = (const uint4*)(g_w2f + cc * 8192);
            uint4* dh = (uint4*)BH;
            for (int u = t; u < 2048; u += 256) dh[u] = sh[u];
        }
        __syncthreads();

        float acc[8][4];
#pragma unroll
        for (int nt = 0; nt < 8; ++nt)
#pragma unroll
            for (int r = 0; r < 4; ++r) acc[nt][r] = 0.0f;

#pragma unroll 4
        for (int kt = 0; kt < 16; ++kt) {
            int jp0 = kt * 8 + c4;
            float4 p0a = w1p4[jp0 * 2],     p0b = w1p4[jp0 * 2 + 1];
            float4 p1a = w1p4[jp0 * 2 + 8], p1b = w1p4[jp0 * 2 + 9];
            uint32_t a0 = hpair16(p0a, p0b, dxa, dya, dza);
            uint32_t a1 = hpair16(p0a, p0b, dxb, dyb, dzb);
            uint32_t a2 = hpair16(p1a, p1b, dxa, dya, dza);
            uint32_t a3 = hpair16(p1a, p1b, dxb, dyb, dzb);
            int bbase = kt * 512 + lane * 2;
#pragma unroll
            for (int nt = 0; nt < 8; ++nt) {
                uint2 bh = *(const uint2*)&BH[bbase + nt * 64];
                mma_f16(acc[nt], a0, a1, a2, a3, bh.x, bh.y);
            }
        }

#pragma unroll
        for (int nt = 0; nt < 8; ++nt) {
            int n0 = cc * 64 + nt * 8 + 2 * c4;
            float2 b2v = *(const float2*)&pe1_b2[n0];
            float2 th  = *(const float2*)&g_theta[ipt * CCH + n0];
            float2 ph0 = *(const float2*)&g_phi[nid0 * CCH + n0];
            float2 ph1 = *(const float2*)&g_phi[nid1 * CCH + n0];

            float pe00 = acc[nt][0] + b2v.x, pe01 = acc[nt][1] + b2v.y;
            float pe10 = acc[nt][2] + b2v.x, pe11 = acc[nt][3] + b2v.y;

            float v00 = (pe00 * (th.x - ph0.x) + pe00) * 0.0625f;
            float v01 = (pe01 * (th.y - ph0.y) + pe01) * 0.0625f;
            float v10 = (pe10 * (th.x - ph1.x) + pe10) * 0.0625f;
            float v11 = (pe11 * (th.y - ph1.y) + pe11) * 0.0625f;

            float m0 = fmaxf(v00, v10), m1 = fmaxf(v01, v11);
#pragma unroll
            for (int off = 4; off <= 16; off <<= 1) {
                m0 = fmaxf(m0, __shfl_xor_sync(0xffffffffu, m0, off));
                m1 = fmaxf(m1, __shfl_xor_sync(0xffffffffu, m1, off));
            }
            float e00 = expf(v00 - m0), e10 = expf(v10 - m0);
            float e01 = expf(v01 - m1), e11 = expf(v11 - m1);
            float s0 = e00 + e10, s1 = e01 + e11;
#pragma unroll
            for (int off = 4; off <= 16; off <<= 1) {
                s0 += __shfl_xor_sync(0xffffffffu, s0, off);
                s1 += __shfl_xor_sync(0xffffffffu, s1, off);
            }
            float2 gv0 = *(const float2*)&g_gv[nid0 * CCH + n0];
            float2 gv1 = *(const float2*)&g_gv[nid1 * CCH + n0];
            float y0 = e00 * gv0.x + e10 * gv1.x;
            float y1 = e01 * gv0.y + e11 * gv1.y;
#pragma unroll
            for (int off = 4; off <= 16; off <<= 1) {
                y0 += __shfl_xor_sync(0xffffffffu, y0, off);
                y1 += __shfl_xor_sync(0xffffffffu, y1, off);
            }
            if (g == 0)
                *(float2*)&g_y[ipt * CCH + n0] = make_float2(y0 / s0, y1 / s1);
        }
    }
}

// ---------------- launch ----------------
extern "C" void kernel_launch(void* const* d_in, const int* in_sizes, int n_in,
                              void* d_out, int out_size) {
    const float* coords  = (const float*)d_in[0];
    const float* feats   = (const float*)d_in[1];
    const float* theta_w = (const float*)d_in[2];
    const float* theta_b = (const float*)d_in[3];
    const float* phi_w   = (const float*)d_in[4];
    const float* phi_b   = (const float*)d_in[5];
    const float* g_w     = (const float*)d_in[6];
    const float* g_b     = (const float*)d_in[7];
    const float* pe1_w1  = (const float*)d_in[8];
    const float* pe1_b1  = (const float*)d_in[9];
    const float* pe1_w2  = (const float*)d_in[10];
    const float* pe1_b2  = (const float*)d_in[11];
    const float* W_w     = (const float*)d_in[12];
    const float* W_b     = (const float*)d_in[13];
    float* out = (float*)d_out;

    float *p_theta, *p_phi, *p_g, *p_y;
    void* p_cnt;
    cudaGetSymbolAddress((void**)&p_theta, g_theta);
    cudaGetSymbolAddress((void**)&p_phi,   g_phi);
    cudaGetSymbolAddress((void**)&p_g,     g_gv);
    cudaGetSymbolAddress((void**)&p_y,     g_y);
    cudaGetSymbolAddress(&p_cnt,           g_cellcnt);

    cudaFuncSetAttribute(attn_tc_kernel,
                         cudaFuncAttributeMaxDynamicSharedMemorySize, ATTN_SMEM_B);
    cudaFuncSetAttribute(linear_tc_kernel,
                         cudaFuncAttributeMaxDynamicSharedMemorySize, LIN_SMEM);

    // grid build + KNN
    cudaMemsetAsync(p_cnt, 0, 512 * sizeof(int));
    hist_kernel<<<NPTS / 256, 256>>>(coords);
    scan_kernel<<<1, 512>>>();
    scatter_kernel<<<NPTS / 256, 256>>>(coords);
    knn_grid_kernel<<<NPTS / 8, 256>>>(coords);

    // all weight fragments (fp16) in one launch
    prep_frags_kernel<<<640, 256>>>(pe1_w2, theta_w, phi_w, g_w, W_w);

    // theta / phi / g — fp16 single-pass tensor-core launch
    linear_tc_kernel<<<dim3(NPTS / 64, 3), 256, LIN_SMEM>>>(
        feats, 0, theta_b, phi_b, g_b, p_theta, p_phi, p_g, nullptr);

    attn_tc_kernel<<<NPTS / 8, 256, ATTN_SMEM_B>>>(coords, pe1_w1, pe1_b1, pe1_b2);

    // final: out = y @ W_w + W_b + feats (fp16 single-pass)
    linear_tc_kernel<<<dim3(NPTS / 64, 1), 256, LIN_SMEM>>>(
        p_y, 3, W_b, W_b, W_b, out, out, out, feats);
}

// round 15
// speedup vs baseline: 9.4290x; 1.0505x over previous
#include <cuda_runtime.h>
#include <cuda_bf16.h>
#include <math_constants.h>
#include <cstdint>

#define NPTS 8192
#define CCH  256
#define KNB  16

typedef unsigned long long ull;

// ---------------- pack helpers ----------------
// f16x2: bits[15:0] = lo arg, bits[31:16] = hi arg
__device__ __forceinline__ uint32_t f16pack(float lo, float hi) {
    uint32_t r;
    asm("cvt.rn.f16x2.f32 %0, %1, %2;" : "=r"(r) : "f"(hi), "f"(lo));
    return r;
}

// mma.sync m16n8k16 row.col f32 accum (baseline sm_80 PTX)
__device__ __forceinline__ void mma_f16(float* d,
                                        uint32_t a0, uint32_t a1, uint32_t a2, uint32_t a3,
                                        uint32_t b0, uint32_t b1) {
    asm volatile(
        "mma.sync.aligned.m16n8k16.row.col.f32.f16.f16.f32 "
        "{%0,%1,%2,%3}, {%4,%5,%6,%7}, {%8,%9}, {%0,%1,%2,%3};"
        : "+f"(d[0]), "+f"(d[1]), "+f"(d[2]), "+f"(d[3])
        : "r"(a0), "r"(a1), "r"(a2), "r"(a3), "r"(b0), "r"(b1));
}

// ---------------- scratch (device globals; no allocation APIs) ----------------
__device__ int    g_idx[NPTS * KNB];
__device__ float  g_theta[NPTS * CCH];
__device__ float  g_phi[NPTS * CCH];
__device__ float  g_gv[NPTS * CCH];
__device__ float  g_y[NPTS * CCH];
__device__ uint32_t g_w2f[32768];
// linear weights (theta, phi, g, W) -> fp16 B fragments
__device__ uint32_t g_wf[4 * 32768];
// grid-KNN scratch
__device__ float4 g_spts[NPTS];
__device__ int    g_sid[NPTS];
__device__ int    g_cellcnt[512];
__device__ int    g_cellstart[513];

#define GRID_DIM 8
#define CELL_H   12.5f
#define INV_H    0.08f

__device__ __forceinline__ int cell_coord(float v) {
    int c = (int)(v * INV_H);
    return min(GRID_DIM - 1, max(0, c));
}

// ---------------- grid build ----------------
__global__ void hist_kernel(const float* __restrict__ coords) {
    int i = blockIdx.x * blockDim.x + threadIdx.x;
    if (i < NPTS) {
        int cx = cell_coord(coords[3 * i + 0]);
        int cy = cell_coord(coords[3 * i + 1]);
        int cz = cell_coord(coords[3 * i + 2]);
        atomicAdd(&g_cellcnt[(cz * GRID_DIM + cy) * GRID_DIM + cx], 1);
    }
}

__global__ void scan_kernel() {   // 1 block, 512 threads
    __shared__ int tmp[512];
    int t = threadIdx.x;
    tmp[t] = g_cellcnt[t];
    __syncthreads();
    for (int off = 1; off < 512; off <<= 1) {
        int a = (t >= off) ? tmp[t - off] : 0;
        __syncthreads();
        tmp[t] += a;
        __syncthreads();
    }
    g_cellstart[t + 1] = tmp[t];
    if (t == 0) g_cellstart[0] = 0;
    g_cellcnt[t] = 0;
}

__global__ void scatter_kernel(const float* __restrict__ coords) {
    int i = blockIdx.x * blockDim.x + threadIdx.x;
    if (i < NPTS) {
        float x = coords[3 * i + 0];
        float y = coords[3 * i + 1];
        float z = coords[3 * i + 2];
        int cell = (cell_coord(z) * GRID_DIM + cell_coord(y)) * GRID_DIM + cell_coord(x);
        int pos = g_cellstart[cell] + atomicAdd(&g_cellcnt[cell], 1);
        g_spts[pos] = make_float4(x, y, z, x * x + y * y + z * z);
        g_sid[pos] = i;
    }
}

// ---------------- grid KNN: warp/query, bitonic seed + lean exact inserts ----------------
__global__ __launch_bounds__(256) void knn_grid_kernel(const float* __restrict__ coords) {
    int warp = threadIdx.x >> 5;
    int lane = threadIdx.x & 31;
    int q = blockIdx.x * 8 + warp;

    float qx = coords[3 * q + 0];
    float qy = coords[3 * q + 1];
    float qz = coords[3 * q + 2];
    float qw = qx * qx + qy * qy + qz * qz;
    int cx = cell_coord(qx), cy = cell_coord(qy), cz = cell_coord(qz);

    ull slot = ~0ull;
    ull thr  = ~0ull;
    float thrf = CUDART_INF_F;
    bool seeded = false;

    auto scan_range = [&](int c0, int c1) {
        int st = g_cellstart[c0];
        int en = g_cellstart[c1 + 1];
        for (int jj = st; jj < en; jj += 32) {
            int id = jj + lane;
            ull key = ~0ull;
            if (id < en) {
                float4 p = g_spts[id];
                float dot = qx * p.x + qy * p.y + qz * p.z;
                float d2 = (qw + p.w) - 2.0f * dot;   // reference formula
                if (d2 <= thrf) {
                    unsigned u = __float_as_uint(d2);
                    u = ((int)u < 0) ? ~u : (u | 0x80000000u);
                    key = ((ull)u << 32) | (unsigned)g_sid[id];
                }
            }
            if (!seeded) {
                // warp bitonic sort (ascending by lane) replaces the warm-up insert burst
#pragma unroll
                for (int k = 2; k <= 32; k <<= 1) {
#pragma unroll
                    for (int j = k >> 1; j > 0; j >>= 1) {
                        ull other = __shfl_xor_sync(0xffffffffu, key, j);
                        bool keepSmall = (((lane & k) == 0) == ((lane & j) == 0));
                        bool less = key < other;
                        key = (keepSmall == less) ? key : other;
                    }
                }
                slot = key;                            // lanes 0..15 = top-16 sorted
                thr  = __shfl_sync(0xffffffffu, slot, 15);
                seeded = true;
            } else {
                unsigned mask = __ballot_sync(0xffffffffu, key < thr);
                if (mask) {
                    while (mask) {
                        int src = __ffs(mask) - 1;
                        mask &= mask - 1;
                        ull cand = __shfl_sync(0xffffffffu, key, src);
                        unsigned lt = __ballot_sync(0xffffffffu, (lane < 16) && (slot < cand));
                        int pos = __popc(lt);                       // pos==16 -> no-op (stale cand)
                        ull prev = __shfl_up_sync(0xffffffffu, slot, 1);
                        if (lane >= pos && lane < 16) slot = (lane == pos) ? cand : prev;
                    }
                    thr = __shfl_sync(0xffffffffu, slot, 15);
                }
            }
        }
        unsigned hb = (unsigned)(thr >> 32);
        thrf = (hb == 0xffffffffu) ? CUDART_INF_F
             : ((hb & 0x80000000u) ? __uint_as_float(hb & 0x7fffffffu)
                                   : __uint_as_float(~hb));
    };

    int px0 = 1, px1 = 0, py0 = 1, py1 = 0, pz0 = 1, pz1 = 0;  // empty prev box

    for (int s = 1; s <= GRID_DIM; ++s) {
        int x0 = max(cx - s, 0), x1 = min(cx + s, GRID_DIM - 1);
        int y0 = max(cy - s, 0), y1 = min(cy + s, GRID_DIM - 1);
        int z0 = max(cz - s, 0), z1 = min(cz + s, GRID_DIM - 1);

        for (int zz = z0; zz <= z1; ++zz)
        for (int yy = y0; yy <= y1; ++yy) {
            int rbase = (zz * GRID_DIM + yy) * GRID_DIM;
            bool inPrevZY = (zz >= pz0 && zz <= pz1 && yy >= py0 && yy <= py1);
            if (!inPrevZY) {
                scan_range(rbase + x0, rbase + x1);          // whole row at once
            } else {
                if (x0 < px0) scan_range(rbase + x0, rbase + px0 - 1);
                if (px1 < x1) scan_range(rbase + px1 + 1, rbase + x1);
            }
        }

        bool covered = (x0 == 0 && x1 == GRID_DIM - 1 &&
                        y0 == 0 && y1 == GRID_DIM - 1 &&
                        z0 == 0 && z1 == GRID_DIM - 1);
        float fxl = (x0 > 0) ? qx - x0 * CELL_H : CUDART_INF_F;
        float fxh = (x1 < GRID_DIM - 1) ? (x1 + 1) * CELL_H - qx : CUDART_INF_F;
        float fyl = (y0 > 0) ? qy - y0 * CELL_H : CUDART_INF_F;
        float fyh = (y1 < GRID_DIM - 1) ? (y1 + 1) * CELL_H - qy : CUDART_INF_F;
        float fzl = (z0 > 0) ? qz - z0 * CELL_H : CUDART_INF_F;
        float fzh = (z1 < GRID_DIM - 1) ? (z1 + 1) * CELL_H - qz : CUDART_INF_F;
        float md = fminf(fminf(fminf(fxl, fxh), fminf(fyl, fyh)), fminf(fzl, fzh));
        if (covered || md * md > thrf + 0.5f) break;

        px0 = x0; px1 = x1; py0 = y0; py1 = y1; pz0 = z0; pz1 = z1;
    }

    if (lane < 16) g_idx[q * KNB + lane] = (int)(unsigned)(slot & 0xffffffffu);
}

// ---------------- prep: all weight fragments (fp16) in one launch ----------------
__global__ void prep_frags_kernel(const float* __restrict__ w2attn,
                                  const float* __restrict__ w0, const float* __restrict__ w1,
                                  const float* __restrict__ w2, const float* __restrict__ w3) {
    if (blockIdx.x < 128) {
        int tid = blockIdx.x * 256 + threadIdx.x;       // 0..32767
        int reg = tid & 1;
        int ln  = (tid >> 1) & 31;
        int nt  = (tid >> 6) & 7;
        int kt  = (tid >> 9) & 15;
        int cc  = (tid >> 13) & 3;
        int n = cc * 64 + nt * 8 + (ln >> 2);
        int k = kt * 16 + 2 * (ln & 3) + reg * 8;
        g_w2f[tid] = f16pack(w2attn[k * CCH + n], w2attn[(k + 1) * CCH + n]);
    } else {
        int tid = (blockIdx.x - 128) * 256 + threadIdx.x;  // 0..131071
        int m = tid >> 15;
        int r = tid & 32767;
        int reg = r & 1;
        int ln  = (r >> 1) & 31;
        int nt  = (r >> 6) & 31;
        int kt  = (r >> 11) & 15;
        int n = nt * 8 + (ln >> 2);
        int k = kt * 16 + 2 * (ln & 3) + reg * 8;
        const float* W = (m == 0) ? w0 : (m == 1) ? w1 : (m == 2) ? w2 : w3;
        g_wf[tid] = f16pack(W[k * CCH + n], W[(k + 1) * CCH + n]);
    }
}

// ---------------- tensor-core linear: fp16 single-pass ----------------
#define LIN_SMEM (64 * 132 * 4)

__global__ void __launch_bounds__(256, 2) linear_tc_kernel(
    const float* __restrict__ A, int m0,
    const float* __restrict__ b0_, const float* __restrict__ b1_, const float* __restrict__ b2_,
    float* __restrict__ o0, float* __restrict__ o1, float* __restrict__ o2,
    const float* __restrict__ resid)
{
    extern __shared__ uint32_t dsm[];
    uint32_t* sA = dsm;

    int mat = m0 + blockIdx.y;
    const float* bias = (blockIdx.y == 0) ? b0_ : (blockIdx.y == 1) ? b1_ : b2_;
    float*       out  = (blockIdx.y == 0) ? o0 : (blockIdx.y == 1) ? o1 : o2;

    int t = threadIdx.x;
    int lane = t & 31;
    int w = t >> 5;
    int wm = w & 3;
    int wn = w >> 2;
    int g = lane >> 2;
    int c4 = lane & 3;
    int row0 = blockIdx.x * 64;

    for (int idx = t; idx < 4096; idx += 256) {
        int row = idx >> 6;
        int qq = idx & 63;
        float4 v = *(const float4*)&A[(row0 + row) * CCH + qq * 4];
        *(uint2*)&sA[row * 132 + qq * 2] = make_uint2(f16pack(v.x, v.y), f16pack(v.z, v.w));
    }
    __syncthreads();

    float acc[16][4];
#pragma unroll
    for (int nt = 0; nt < 16; ++nt)
#pragma unroll
        for (int r = 0; r < 4; ++r) acc[nt][r] = 0.0f;

    int rA = wm * 16 + g;
    const uint32_t* bfrag = g_wf + mat * 32768;

#pragma unroll 2
    for (int kt = 0; kt < 16; ++kt) {
        uint32_t a0 = sA[rA * 132 + kt * 8 + c4];
        uint32_t a1 = sA[(rA + 8) * 132 + kt * 8 + c4];
        uint32_t a2 = sA[rA * 132 + kt * 8 + c4 + 4];
        uint32_t a3 = sA[(rA + 8) * 132 + kt * 8 + c4 + 4];
#pragma unroll
        for (int nt = 0; nt < 16; ++nt) {
            int ntg = wn * 16 + nt;
            uint2 bh = *(const uint2*)&bfrag[kt * 2048 + ntg * 64 + lane * 2];
            mma_f16(acc[nt], a0, a1, a2, a3, bh.x, bh.y);
        }
    }

#pragma unroll
    for (int nt = 0; nt < 16; ++nt) {
        int ntg = wn * 16 + nt;
        int n0 = ntg * 8 + 2 * c4;
        float2 bv = *(const float2*)&bias[n0];
        int r0 = row0 + rA;
        int r1 = r0 + 8;
        float2 v0 = make_float2(acc[nt][0] + bv.x, acc[nt][1] + bv.y);
        float2 v1 = make_float2(acc[nt][2] + bv.x, acc[nt][3] + bv.y);
        if (resid != nullptr) {
            float2 f0 = *(const float2*)&resid[r0 * CCH + n0];
            float2 f1 = *(const float2*)&resid[r1 * CCH + n0];
            v0.x += f0.x; v0.y += f0.y;
            v1.x += f1.x; v1.y += f1.y;
        }
        *(float2*)&out[r0 * CCH + n0] = v0;
        *(float2*)&out[r1 * CCH + n0] = v1;
    }
}

// ---------------- h-pair: 2 hidden values -> packed fp16 fragment reg ----------------
__device__ __forceinline__ uint32_t hpair16(float4 pa, float4 pb,
                                            float dx, float dy, float dz) {
    float h0 = fmaxf(fmaf(dz, pb.x, fmaf(dy, pa.z, fmaf(dx, pa.x, pb.z))), 0.0f);
    float h1 = fmaxf(fmaf(dz, pb.y, fmaf(dy, pa.w, fmaf(dx, pa.y, pb.w))), 0.0f);
    return f16pack(h0, h1);
}

// ---------------- attention: mma.sync fp16 pe-GEMM + warp-local softmax ----------------
#define ATTN_SMEM_U32 9728
#define ATTN_SMEM_B   (ATTN_SMEM_U32 * 4)

__global__ void __launch_bounds__(256) attn_tc_kernel(
    const float* __restrict__ coords,
    const float* __restrict__ pe1_w1, const float* __restrict__ pe1_b1,
    const float* __restrict__ pe1_b2)
{
    extern __shared__ uint32_t dsm[];
    uint32_t* BH  = dsm;
    float*    W1P = (float*)(dsm + 8192);
    float*    DL  = (float*)(dsm + 9216);
    int*      ID  = (int*)(dsm + 9600);

    int t = threadIdx.x;
    int lane = t & 31;
    int w = t >> 5;
    int g = lane >> 2;
    int c4 = lane & 3;

    {
        int f = 4 * t;
#pragma unroll
        for (int u = 0; u < 4; ++u) {
            int ff = f + u, p = ff >> 3, comp = ff & 7;
            float v;
            if (comp < 6) v = pe1_w1[(comp >> 1) * CCH + 2 * p + (comp & 1)];
            else          v = pe1_b1[2 * p + (comp & 1)];
            W1P[ff] = v;
        }
    }
    if (t < 128) ID[t] = g_idx[blockIdx.x * 128 + t];
    __syncthreads();
    if (t < 128) {
        int nid = ID[t];
        int ip = blockIdx.x * 8 + (t >> 4);
#pragma unroll
        for (int d = 0; d < 3; ++d)
            DL[t * 3 + d] = coords[nid * 3 + d] - coords[ip * 3 + d];
    }
    __syncthreads();

    int rA = w * 16 + g, rB = rA + 8;
    float dxa = DL[rA * 3], dya = DL[rA * 3 + 1], dza = DL[rA * 3 + 2];
    float dxb = DL[rB * 3], dyb = DL[rB * 3 + 1], dzb = DL[rB * 3 + 2];
    int nid0 = ID[rA], nid1 = ID[rB];
    int ipt = blockIdx.x * 8 + w;

    const float4* w1p4 = (const float4*)W1P;

    for (int cc = 0; cc < 4; ++cc) {
        __syncthreads();
        {
            const uint4* sh = (const uint4*)(g_w2f + cc * 8192);
            uint4* dh = (uint4*)BH;
            for (int u = t; u < 2048; u += 256) dh[u] = sh[u];
        }
        __syncthreads();

        float acc[8][4];
#pragma unroll
        for (int nt = 0; nt < 8; ++nt)
#pragma unroll
            for (int r = 0; r < 4; ++r) acc[nt][r] = 0.0f;

#pragma unroll 4
        for (int kt = 0; kt < 16; ++kt) {
            int jp0 = kt * 8 + c4;
            float4 p0a = w1p4[jp0 * 2],     p0b = w1p4[jp0 * 2 + 1];
            float4 p1a = w1p4[jp0 * 2 + 8], p1b = w1p4[jp0 * 2 + 9];
            uint32_t a0 = hpair16(p0a, p0b, dxa, dya, dza);
            uint32_t a1 = hpair16(p0a, p0b, dxb, dyb, dzb);
            uint32_t a2 = hpair16(p1a, p1b, dxa, dya, dza);
            uint32_t a3 = hpair16(p1a, p1b, dxb, dyb, dzb);
            int bbase = kt * 512 + lane * 2;
#pragma unroll
            for (int nt = 0; nt < 8; ++nt) {
                uint2 bh = *(const uint2*)&BH[bbase + nt * 64];
                mma_f16(acc[nt], a0, a1, a2, a3, bh.x, bh.y);
            }
        }

#pragma unroll
        for (int nt = 0; nt < 8; ++nt) {
            int n0 = cc * 64 + nt * 8 + 2 * c4;
            float2 b2v = *(const float2*)&pe1_b2[n0];
            float2 th  = *(const float2*)&g_theta[ipt * CCH + n0];
            float2 ph0 = *(const float2*)&g_phi[nid0 * CCH + n0];
            float2 ph1 = *(const float2*)&g_phi[nid1 * CCH + n0];

            float pe00 = acc[nt][0] + b2v.x, pe01 = acc[nt][1] + b2v.y;
            float pe10 = acc[nt][2] + b2v.x, pe11 = acc[nt][3] + b2v.y;

            float v00 = (pe00 * (th.x - ph0.x) + pe00) * 0.0625f;
            float v01 = (pe01 * (th.y - ph0.y) + pe01) * 0.0625f;
            float v10 = (pe10 * (th.x - ph1.x) + pe10) * 0.0625f;
            float v11 = (pe11 * (th.y - ph1.y) + pe11) * 0.0625f;

            float m0 = fmaxf(v00, v10), m1 = fmaxf(v01, v11);
#pragma unroll
            for (int off = 4; off <= 16; off <<= 1) {
                m0 = fmaxf(m0, __shfl_xor_sync(0xffffffffu, m0, off));
                m1 = fmaxf(m1, __shfl_xor_sync(0xffffffffu, m1, off));
            }
            float e00 = expf(v00 - m0), e10 = expf(v10 - m0);
            float e01 = expf(v01 - m1), e11 = expf(v11 - m1);
            float s0 = e00 + e10, s1 = e01 + e11;
#pragma unroll
            for (int off = 4; off <= 16; off <<= 1) {
                s0 += __shfl_xor_sync(0xffffffffu, s0, off);
                s1 += __shfl_xor_sync(0xffffffffu, s1, off);
            }
            float2 gv0 = *(const float2*)&g_gv[nid0 * CCH + n0];
            float2 gv1 = *(const float2*)&g_gv[nid1 * CCH + n0];
            float y0 = e00 * gv0.x + e10 * gv1.x;
            float y1 = e01 * gv0.y + e11 * gv1.y;
#pragma unroll
            for (int off = 4; off <= 16; off <<= 1) {
                y0 += __shfl_xor_sync(0xffffffffu, y0, off);
                y1 += __shfl_xor_sync(0xffffffffu, y1, off);
            }
            if (g == 0)
                *(float2*)&g_y[ipt * CCH + n0] = make_float2(y0 / s0, y1 / s1);
        }
    }
}

// ---------------- launch: fork KNN chain and GEMM-prep chain onto parallel streams ----------------
extern "C" void kernel_launch(void* const* d_in, const int* in_sizes, int n_in,
                              void* d_out, int out_size) {
    const float* coords  = (const float*)d_in[0];
    const float* feats   = (const float*)d_in[1];
    const float* theta_w = (const float*)d_in[2];
    const float* theta_b = (const float*)d_in[3];
    const float* phi_w   = (const float*)d_in[4];
    const float* phi_b   = (const float*)d_in[5];
    const float* g_w     = (const float*)d_in[6];
    const float* g_b     = (const float*)d_in[7];
    const float* pe1_w1  = (const float*)d_in[8];
    const float* pe1_b1  = (const float*)d_in[9];
    const float* pe1_w2  = (const float*)d_in[10];
    const float* pe1_b2  = (const float*)d_in[11];
    const float* W_w     = (const float*)d_in[12];
    const float* W_b     = (const float*)d_in[13];
    float* out = (float*)d_out;

    float *p_theta, *p_phi, *p_g, *p_y;
    void* p_cnt;
    cudaGetSymbolAddress((void**)&p_theta, g_theta);
    cudaGetSymbolAddress((void**)&p_phi,   g_phi);
    cudaGetSymbolAddress((void**)&p_g,     g_gv);
    cudaGetSymbolAddress((void**)&p_y,     g_y);
    cudaGetSymbolAddress(&p_cnt,           g_cellcnt);

    cudaFuncSetAttribute(attn_tc_kernel,
                         cudaFuncAttributeMaxDynamicSharedMemorySize, ATTN_SMEM_B);
    cudaFuncSetAttribute(linear_tc_kernel,
                         cudaFuncAttributeMaxDynamicSharedMemorySize, LIN_SMEM);

    // fork: side stream runs the weight-prep + theta/phi/g GEMMs while the
    // main stream runs the grid build + KNN chain. Event-based fork/join is
    // the supported cross-stream pattern under graph capture.
    cudaStream_t s2;
    cudaStreamCreateWithFlags(&s2, cudaStreamNonBlocking);
    cudaEvent_t eFork, eJoin;
    cudaEventCreateWithFlags(&eFork, cudaEventDisableTiming);
    cudaEventCreateWithFlags(&eJoin, cudaEventDisableTiming);

    cudaEventRecord(eFork, 0);
    cudaStreamWaitEvent(s2, eFork, 0);

    // branch B (s2): weight fragments + theta/phi/g linears
    prep_frags_kernel<<<640, 256, 0, s2>>>(pe1_w2, theta_w, phi_w, g_w, W_w);
    linear_tc_kernel<<<dim3(NPTS / 64, 3), 256, LIN_SMEM, s2>>>(
        feats, 0, theta_b, phi_b, g_b, p_theta, p_phi, p_g, nullptr);

    // branch A (main stream): grid build + KNN
    cudaMemsetAsync(p_cnt, 0, 512 * sizeof(int), 0);
    hist_kernel<<<NPTS / 256, 256>>>(coords);
    scan_kernel<<<1, 512>>>();
    scatter_kernel<<<NPTS / 256, 256>>>(coords);
    knn_grid_kernel<<<NPTS / 8, 256>>>(coords);

    // join
    cudaEventRecord(eJoin, s2);
    cudaStreamWaitEvent(0, eJoin, 0);

    attn_tc_kernel<<<NPTS / 8, 256, ATTN_SMEM_B>>>(coords, pe1_w1, pe1_b1, pe1_b2);

    // final: out = y @ W_w + W_b + feats (fp16 single-pass)
    linear_tc_kernel<<<dim3(NPTS / 64, 1), 256, LIN_SMEM>>>(
        p_y, 3, W_b, W_b, W_b, out, out, out, feats);

    cudaEventDestroy(eFork);
    cudaEventDestroy(eJoin);
    cudaStreamDestroy(s2);
}